// round 1
// baseline (speedup 1.0000x reference)
#include <cuda_runtime.h>
#include <math.h>
#include <float.h>

// ---------------- problem constants ----------------
#define Nn    50000
#define Ee    1600000
#define EF    1650000          // E + N self loops
#define HID   32
#define HEADS 4
#define INF_  3.402823466e38f

// output layout (float32, flattened in return order)
#define W_OFF  0               // weights [25001]
#define V_OFF  25001           // value   [1]
#define EI_OFF 25002           // edge_index_full [2, EF]
#define A1_OFF (25002 + 2*EF)  // alpha1 [EF, 4]   (== 3325002, 8B-aligned only!)

// ---------------- device scratch ----------------
__device__ __align__(16) float g_h1   [Nn*128];   // layer1 projected features
__device__ __align__(16) float g_ss1  [Nn*4];     // s_src1
__device__ __align__(16) float g_sd1  [Nn*4];     // s_dst1
__device__ __align__(16) float g_m1   [Nn*4];     // segment max
__device__ __align__(16) float g_d1   [Nn*4];     // segment denom
__device__ __align__(16) float g_o1   [Nn*128];   // layer1 aggregate
__device__ __align__(16) float g_h2   [Nn*32];    // layer2 projected features
__device__ float g_ss2[Nn], g_sd2[Nn], g_m2[Nn], g_d2[Nn];
__device__ __align__(16) float g_o2   [Nn*32];    // layer2 aggregate
__device__ float g_num2[EF];
__device__ float g_scores[Nn];
__device__ float g_gsum[32];
__device__ float g_easum;
__device__ float g_eamean;
__device__ float g_c1[4];
__device__ float g_c2;

// ---------------- helpers ----------------
__device__ __forceinline__ float wredsum(float v) {
#pragma unroll
    for (int o = 16; o; o >>= 1) v += __shfl_xor_sync(0xffffffffu, v, o);
    return v;
}
__device__ __forceinline__ float wredmax(float v) {
#pragma unroll
    for (int o = 16; o; o >>= 1) v = fmaxf(v, __shfl_xor_sync(0xffffffffu, v, o));
    return v;
}
__device__ __forceinline__ float lrelu(float x) { return x >= 0.f ? x : 0.2f * x; }
__device__ __forceinline__ float elu(float x)   { return x > 0.f ? x : expm1f(x); }

__device__ __forceinline__ void atomicMaxF(float* addr, float v) {
    v += 0.0f;  // normalize -0 -> +0
    if (v >= 0.f) atomicMax((int*)addr, __float_as_int(v));
    else          atomicMin((unsigned int*)addr, __float_as_uint(v));
}
__device__ __forceinline__ void redAdd4(float* dst, float a, float b, float c, float d) {
    asm volatile("red.relaxed.gpu.global.add.v4.f32 [%0], {%1,%2,%3,%4};"
                 :: "l"(dst), "f"(a), "f"(b), "f"(c), "f"(d) : "memory");
}

// ---------------- kernels ----------------
__global__ void k_init() {
    int stride = gridDim.x * blockDim.x;
    int t = blockIdx.x * blockDim.x + threadIdx.x;
    for (int i = t; i < Nn*128; i += stride) g_o1[i] = 0.f;
    for (int i = t; i < Nn*32;  i += stride) g_o2[i] = 0.f;
    for (int i = t; i < Nn*4;   i += stride) { g_m1[i] = -INF_; g_d1[i] = 0.f; }
    for (int i = t; i < Nn;     i += stride) { g_m2[i] = -INF_; g_d2[i] = 0.f; }
    if (t < 32) g_gsum[t] = 0.f;
    if (t == 0) g_easum = 0.f;
}

__global__ void k_easum(const float* __restrict__ ea) {
    float s = 0.f;
    for (int i = blockIdx.x * blockDim.x + threadIdx.x; i < Ee; i += gridDim.x * blockDim.x)
        s += ea[i];
    s = wredsum(s);
    __shared__ float sm[8];
    int lane = threadIdx.x & 31, w = threadIdx.x >> 5;
    if (lane == 0) sm[w] = s;
    __syncthreads();
    if (threadIdx.x == 0) {
        float b = 0.f;
        for (int i = 0; i < (int)(blockDim.x >> 5); i++) b += sm[i];
        atomicAdd(&g_easum, b);
    }
}

__global__ void k_consts(const float* __restrict__ We1, const float* __restrict__ ae1,
                         const float* __restrict__ We2, const float* __restrict__ ae2) {
    int t = threadIdx.x;            // 128 threads
    float p = We1[t] * ae1[t];
    p = wredsum(p);
    if ((t & 31) == 0) g_c1[t >> 5] = p;
    if (t < 32) {
        float q = We2[t] * ae2[t];
        q = wredsum(q);
        if (t == 0) { g_c2 = q; g_eamean = g_easum * (1.0f / Ee); }
    }
}

// layer-1 projection + attention scores: warp per node
__global__ void k_node1(const float* __restrict__ x, const float* __restrict__ W1,
                        const float* __restrict__ as1, const float* __restrict__ ad1) {
    __shared__ float W1s[5*128];
    __shared__ float s_as[128], s_ad[128];
    int t = threadIdx.x;
    for (int i = t; i < 640; i += 128) W1s[i] = W1[i];
    s_as[t] = as1[t]; s_ad[t] = ad1[t];
    __syncthreads();
    int warp = t >> 5, lane = t & 31;
    int n = blockIdx.x * 4 + warp;
    if (n >= Nn) return;
    float x0 = x[n*5+0], x1 = x[n*5+1], x2 = x[n*5+2], x3 = x[n*5+3], x4 = x[n*5+4];
#pragma unroll
    for (int k = 0; k < 4; k++) {
        int ch = lane + 32 * k;
        float acc = x0*W1s[ch] + x1*W1s[128+ch] + x2*W1s[256+ch] + x3*W1s[384+ch] + x4*W1s[512+ch];
        g_h1[n*128 + ch] = acc;
        float ps = wredsum(acc * s_as[ch]);
        float pd = wredsum(acc * s_ad[ch]);
        if (lane == 0) { g_ss1[n*4+k] = ps; g_sd1[n*4+k] = pd; }
    }
}

__device__ __forceinline__ void edge_sd(int e, const int* __restrict__ ei, int& s, int& d) {
    if (e < Ee) { s = ei[e]; d = ei[Ee + e]; }
    else        { s = e - Ee; d = s; }
}

// pass A1: logits -> segment max; also emit edge_index_full
__global__ void k_edgeA1(const int* __restrict__ ei, const float* __restrict__ ea,
                         float* __restrict__ out) {
    int e = blockIdx.x * blockDim.x + threadIdx.x;
    if (e >= EF) return;
    int s, d; edge_sd(e, ei, s, d);
    float a = (e < Ee) ? ea[e] : g_eamean;
    out[EI_OFF + e]      = (float)s;
    out[EI_OFF + EF + e] = (float)d;
    float4 ss = ((const float4*)g_ss1)[s];
    float4 sd = ((const float4*)g_sd1)[d];
    atomicMaxF(&g_m1[d*4+0], lrelu(ss.x + sd.x + a * g_c1[0]));
    atomicMaxF(&g_m1[d*4+1], lrelu(ss.y + sd.y + a * g_c1[1]));
    atomicMaxF(&g_m1[d*4+2], lrelu(ss.z + sd.z + a * g_c1[2]));
    atomicMaxF(&g_m1[d*4+3], lrelu(ss.w + sd.w + a * g_c1[3]));
}

// pass B1: numerators -> alpha slot in d_out, denom atomics
__global__ void k_edgeB1(const int* __restrict__ ei, const float* __restrict__ ea,
                         float* __restrict__ out) {
    int e = blockIdx.x * blockDim.x + threadIdx.x;
    if (e >= EF) return;
    int s, d; edge_sd(e, ei, s, d);
    float a = (e < Ee) ? ea[e] : g_eamean;
    float4 ss = ((const float4*)g_ss1)[s];
    float4 sd = ((const float4*)g_sd1)[d];
    float4 mm = ((const float4*)g_m1)[d];
    float n0 = __expf(lrelu(ss.x + sd.x + a * g_c1[0]) - mm.x);
    float n1 = __expf(lrelu(ss.y + sd.y + a * g_c1[1]) - mm.y);
    float n2 = __expf(lrelu(ss.z + sd.z + a * g_c1[2]) - mm.z);
    float n3 = __expf(lrelu(ss.w + sd.w + a * g_c1[3]) - mm.w);
    float2* ao = (float2*)(out + A1_OFF + 4*e);      // 8B-aligned region
    ao[0] = make_float2(n0, n1);
    ao[1] = make_float2(n2, n3);
    atomicAdd(&g_d1[d*4+0], n0);
    atomicAdd(&g_d1[d*4+1], n1);
    atomicAdd(&g_d1[d*4+2], n2);
    atomicAdd(&g_d1[d*4+3], n3);
}

// pass C1: normalize alpha in place + aggregate 128-ch features. One warp per edge.
__global__ void k_edgeC1(const int* __restrict__ ei, float* __restrict__ out) {
    int gt = blockIdx.x * blockDim.x + threadIdx.x;
    int e = gt >> 5;
    int lane = threadIdx.x & 31;
    if (e >= EF) return;
    int s, d; edge_sd(e, ei, s, d);
    const float2* ao = (const float2*)(out + A1_OFF + 4*e);
    float2 n01 = ao[0], n23 = ao[1];
    float4 dd = ((const float4*)g_d1)[d];
    float a0 = n01.x / (dd.x + 1e-16f);
    float a1 = n01.y / (dd.y + 1e-16f);
    float a2 = n23.x / (dd.z + 1e-16f);
    float a3 = n23.y / (dd.w + 1e-16f);
    if (lane == 0) {
        float2* w = (float2*)(out + A1_OFF + 4*e);
        w[0] = make_float2(a0, a1);
        w[1] = make_float2(a2, a3);
    }
    float aa = lane < 8 ? a0 : lane < 16 ? a1 : lane < 24 ? a2 : a3;
    float4 v = ((const float4*)g_h1)[s*32 + lane];   // 128 floats per row
    redAdd4(g_o1 + d*128 + lane*4, aa*v.x, aa*v.y, aa*v.z, aa*v.w);
}

// layer-2 projection + scores: warp per node, W2 staged in smem
__global__ void k_node2(const float* __restrict__ W2, const float* __restrict__ b1,
                        const float* __restrict__ as2, const float* __restrict__ ad2) {
    __shared__ float W2s[128*32];
    __shared__ float hs[4][128];
    int t = threadIdx.x;
    for (int i = t; i < 4096; i += 128) W2s[i] = W2[i];
    __syncthreads();
    int warp = t >> 5, lane = t & 31;
    int n = blockIdx.x * 4 + warp;
    if (n >= Nn) return;
    float4 v  = ((const float4*)g_o1)[n*32 + lane];
    float4 bb = ((const float4*)b1)[lane];
    hs[warp][lane*4+0] = elu(v.x + bb.x);
    hs[warp][lane*4+1] = elu(v.y + bb.y);
    hs[warp][lane*4+2] = elu(v.z + bb.z);
    hs[warp][lane*4+3] = elu(v.w + bb.w);
    __syncwarp();
    float acc = 0.f;
#pragma unroll 16
    for (int i = 0; i < 128; i++)
        acc += hs[warp][i] * W2s[i*32 + lane];
    g_h2[n*32 + lane] = acc;
    float ps = wredsum(acc * as2[lane]);
    float pd = wredsum(acc * ad2[lane]);
    if (lane == 0) { g_ss2[n] = ps; g_sd2[n] = pd; }
}

__global__ void k_edgeA2(const int* __restrict__ ei, const float* __restrict__ ea) {
    int e = blockIdx.x * blockDim.x + threadIdx.x;
    if (e >= EF) return;
    int s, d; edge_sd(e, ei, s, d);
    float a = (e < Ee) ? ea[e] : g_eamean;
    atomicMaxF(&g_m2[d], lrelu(g_ss2[s] + g_sd2[d] + a * g_c2));
}

__global__ void k_edgeB2(const int* __restrict__ ei, const float* __restrict__ ea) {
    int e = blockIdx.x * blockDim.x + threadIdx.x;
    if (e >= EF) return;
    int s, d; edge_sd(e, ei, s, d);
    float a = (e < Ee) ? ea[e] : g_eamean;
    float num = __expf(lrelu(g_ss2[s] + g_sd2[d] + a * g_c2) - g_m2[d]);
    g_num2[e] = num;
    atomicAdd(&g_d2[d], num);
}

// pass C2: 8 lanes per edge (32 channels), 4 edges per warp
__global__ void k_edgeC2(const int* __restrict__ ei) {
    int gt = blockIdx.x * blockDim.x + threadIdx.x;
    int lane = threadIdx.x & 31;
    int e = (gt >> 5) * 4 + (lane >> 3);
    if (e >= EF) return;
    int sub = lane & 7;
    int s, d; edge_sd(e, ei, s, d);
    float a = g_num2[e] / (g_d2[d] + 1e-16f);
    float4 v = ((const float4*)g_h2)[s*8 + sub];
    redAdd4(g_o2 + d*32 + sub*4, a*v.x, a*v.y, a*v.z, a*v.w);
}

// final node activations, actor scores, graph embed partial sums
__global__ void k_node3(const float* __restrict__ b2, const float* __restrict__ Wa,
                        const float* __restrict__ ba) {
    __shared__ float sacc[32];
    int t = threadIdx.x;
    if (t < 32) sacc[t] = 0.f;
    __syncthreads();
    int lane = t & 31, warp = t >> 5;
    int nwarps = gridDim.x * (blockDim.x >> 5);
    float bl = b2[lane], wl = Wa[lane], bb = ba[0];
    for (int n = blockIdx.x * (blockDim.x >> 5) + warp; n < Nn; n += nwarps) {
        float v = g_o2[n*32 + lane] + bl;
        v = elu(v);
        atomicAdd(&sacc[lane], v);
        float p = wredsum(v * wl);
        if (lane == 0) g_scores[n] = p + bb;
    }
    __syncthreads();
    if (t < 32) atomicAdd(&g_gsum[t], sacc[t]);
}

// softmax over [cash, scores[stock_idx]] + critic value
__global__ void k_head(const float* __restrict__ cash, const int* __restrict__ stock_idx,
                       const float* __restrict__ Wc, const float* __restrict__ bc,
                       int ns, float* __restrict__ out) {
    if (threadIdx.x < 32) {
        float p = wredsum(g_gsum[threadIdx.x] * (1.0f / Nn) * Wc[threadIdx.x]);
        if (threadIdx.x == 0) out[V_OFF] = p + bc[0];
    }
    __shared__ float sm[32];
    __shared__ float bM, bS;
    int t = threadIdx.x, lane = t & 31, w = t >> 5, nw = blockDim.x >> 5;
    int total = ns + 1;
    // max
    float m = -INF_;
    for (int i = t; i < total; i += blockDim.x) {
        float v = (i == 0) ? cash[0] : g_scores[stock_idx[i-1]];
        m = fmaxf(m, v);
    }
    m = wredmax(m);
    if (lane == 0) sm[w] = m;
    __syncthreads();
    if (w == 0) {
        float v = (lane < nw) ? sm[lane] : -INF_;
        v = wredmax(v);
        if (lane == 0) bM = v;
    }
    __syncthreads();
    float M = bM;
    // sum
    float s = 0.f;
    for (int i = t; i < total; i += blockDim.x) {
        float v = (i == 0) ? cash[0] : g_scores[stock_idx[i-1]];
        s += __expf(v - M);
    }
    s = wredsum(s);
    __syncthreads();
    if (lane == 0) sm[w] = s;
    __syncthreads();
    if (w == 0) {
        float v = (lane < nw) ? sm[lane] : 0.f;
        v = wredsum(v);
        if (lane == 0) bS = v;
    }
    __syncthreads();
    float inv = 1.0f / bS;
    for (int i = t; i < total; i += blockDim.x) {
        float v = (i == 0) ? cash[0] : g_scores[stock_idx[i-1]];
        out[W_OFF + i] = __expf(v - M) * inv;
    }
}

// ---------------- launch ----------------
extern "C" void kernel_launch(void* const* d_in, const int* in_sizes, int n_in,
                              void* d_out, int out_size) {
    const float* x    = (const float*)d_in[0];
    const float* ea   = (const float*)d_in[1];
    const float* W1   = (const float*)d_in[2];
    const float* as1  = (const float*)d_in[3];
    const float* ad1  = (const float*)d_in[4];
    const float* We1  = (const float*)d_in[5];
    const float* ae1  = (const float*)d_in[6];
    const float* b1   = (const float*)d_in[7];
    const float* W2   = (const float*)d_in[8];
    const float* as2  = (const float*)d_in[9];
    const float* ad2  = (const float*)d_in[10];
    const float* We2  = (const float*)d_in[11];
    const float* ae2  = (const float*)d_in[12];
    const float* b2   = (const float*)d_in[13];
    const float* Wa   = (const float*)d_in[14];
    const float* ba   = (const float*)d_in[15];
    const float* cash = (const float*)d_in[16];
    const float* Wc   = (const float*)d_in[17];
    const float* bc   = (const float*)d_in[18];
    const int*   ei   = (const int*)  d_in[19];
    const int*   sidx = (const int*)  d_in[20];
    float* out = (float*)d_out;
    int ns = in_sizes[20];

    k_init  <<<4096, 256>>>();
    k_easum <<<2048, 256>>>(ea);
    k_consts<<<1, 128>>>(We1, ae1, We2, ae2);
    k_node1 <<<(Nn + 3) / 4, 128>>>(x, W1, as1, ad1);
    k_edgeA1<<<(EF + 255) / 256, 256>>>(ei, ea, out);
    k_edgeB1<<<(EF + 255) / 256, 256>>>(ei, ea, out);
    k_edgeC1<<<(EF + 7) / 8, 256>>>(ei, out);
    k_node2 <<<(Nn + 3) / 4, 128>>>(W2, b1, as2, ad2);
    k_edgeA2<<<(EF + 255) / 256, 256>>>(ei, ea);
    k_edgeB2<<<(EF + 255) / 256, 256>>>(ei, ea);
    k_edgeC2<<<(EF + 31) / 32, 256>>>(ei);
    k_node3 <<<512, 256>>>(b2, Wa, ba);
    k_head  <<<1, 1024>>>(cash, sidx, Wc, bc, ns, out);
}

// round 2
// speedup vs baseline: 1.1507x; 1.1507x over previous
#include <cuda_runtime.h>
#include <math.h>
#include <float.h>

// ---------------- problem constants ----------------
#define Nn    50000
#define Ee    1600000
#define EF    1650000          // E + N self loops
#define INF_  3.402823466e38f

// output layout (float32, flattened in return order)
#define W_OFF  0               // weights [25001]
#define V_OFF  25001           // value   [1]
#define EI_OFF 25002           // edge_index_full [2, EF]
#define A1_OFF (25002 + 2*EF)  // alpha1 [EF, 4]   (8B-aligned only!)

// ---------------- device scratch ----------------
__device__ __align__(16) float g_h1   [Nn*128];   // layer1 projected features
__device__ __align__(16) float g_ss1  [Nn*4];     // s_src1
__device__ __align__(16) float g_sd1  [Nn*4];     // s_dst1
__device__ __align__(16) float g_d1   [Nn*4];     // segment denom (layer1)
__device__ __align__(16) float g_o1   [Nn*128];   // layer1 unnormalized aggregate
__device__ __align__(16) float g_h2   [Nn*32];    // layer2 projected features
__device__ float g_ss2[Nn], g_sd2[Nn], g_d2[Nn];
__device__ __align__(16) float g_o2   [Nn*32];    // layer2 unnormalized aggregate
__device__ float g_scores[Nn];
__device__ float g_gsum[32];
__device__ float g_easum;
__device__ float g_eamean;
__device__ float g_c1[4];
__device__ float g_c2;

// ---------------- helpers ----------------
__device__ __forceinline__ float wredsum(float v) {
#pragma unroll
    for (int o = 16; o; o >>= 1) v += __shfl_xor_sync(0xffffffffu, v, o);
    return v;
}
__device__ __forceinline__ float wredmax(float v) {
#pragma unroll
    for (int o = 16; o; o >>= 1) v = fmaxf(v, __shfl_xor_sync(0xffffffffu, v, o));
    return v;
}
__device__ __forceinline__ float lrelu(float x) { return x >= 0.f ? x : 0.2f * x; }
__device__ __forceinline__ float elu(float x)   { return x > 0.f ? x : expm1f(x); }

__device__ __forceinline__ void redAdd4(float* dst, float a, float b, float c, float d) {
    asm volatile("red.relaxed.gpu.global.add.v4.f32 [%0], {%1,%2,%3,%4};"
                 :: "l"(dst), "f"(a), "f"(b), "f"(c), "f"(d) : "memory");
}
__device__ __forceinline__ void redAdd1(float* dst, float a) {
    asm volatile("red.relaxed.gpu.global.add.f32 [%0], %1;"
                 :: "l"(dst), "f"(a) : "memory");
}

__device__ __forceinline__ void edge_sd(int e, const int* __restrict__ ei, int& s, int& d) {
    if (e < Ee) { s = ei[e]; d = ei[Ee + e]; }
    else        { s = e - Ee; d = s; }
}

// ---------------- kernels ----------------
__global__ void k_init() {
    int stride = gridDim.x * blockDim.x;
    int t = blockIdx.x * blockDim.x + threadIdx.x;
    for (int i = t; i < Nn*128; i += stride) g_o1[i] = 0.f;
    for (int i = t; i < Nn*32;  i += stride) g_o2[i] = 0.f;
    for (int i = t; i < Nn*4;   i += stride) g_d1[i] = 0.f;
    for (int i = t; i < Nn;     i += stride) g_d2[i] = 0.f;
    if (t < 32) g_gsum[t] = 0.f;
    if (t == 0) g_easum = 0.f;
}

__global__ void k_easum(const float* __restrict__ ea) {
    float s = 0.f;
    for (int i = blockIdx.x * blockDim.x + threadIdx.x; i < Ee; i += gridDim.x * blockDim.x)
        s += ea[i];
    s = wredsum(s);
    __shared__ float sm[8];
    int lane = threadIdx.x & 31, w = threadIdx.x >> 5;
    if (lane == 0) sm[w] = s;
    __syncthreads();
    if (threadIdx.x == 0) {
        float b = 0.f;
        for (int i = 0; i < (int)(blockDim.x >> 5); i++) b += sm[i];
        atomicAdd(&g_easum, b);
    }
}

__global__ void k_consts(const float* __restrict__ We1, const float* __restrict__ ae1,
                         const float* __restrict__ We2, const float* __restrict__ ae2) {
    int t = threadIdx.x;            // 128 threads
    float p = We1[t] * ae1[t];
    p = wredsum(p);
    if ((t & 31) == 0) g_c1[t >> 5] = p;
    if (t < 32) {
        float q = We2[t] * ae2[t];
        q = wredsum(q);
        if (t == 0) { g_c2 = q; g_eamean = g_easum * (1.0f / Ee); }
    }
}

// layer-1 projection + attention scores: warp per node
__global__ void k_node1(const float* __restrict__ x, const float* __restrict__ W1,
                        const float* __restrict__ as1, const float* __restrict__ ad1) {
    __shared__ float W1s[5*128];
    __shared__ float s_as[128], s_ad[128];
    int t = threadIdx.x;
    for (int i = t; i < 640; i += 128) W1s[i] = W1[i];
    s_as[t] = as1[t]; s_ad[t] = ad1[t];
    __syncthreads();
    int warp = t >> 5, lane = t & 31;
    int n = blockIdx.x * 4 + warp;
    if (n >= Nn) return;
    float x0 = x[n*5+0], x1 = x[n*5+1], x2 = x[n*5+2], x3 = x[n*5+3], x4 = x[n*5+4];
#pragma unroll
    for (int k = 0; k < 4; k++) {
        int ch = lane + 32 * k;
        float acc = x0*W1s[ch] + x1*W1s[128+ch] + x2*W1s[256+ch] + x3*W1s[384+ch] + x4*W1s[512+ch];
        g_h1[n*128 + ch] = acc;
        float ps = wredsum(acc * s_as[ch]);
        float pd = wredsum(acc * s_ad[ch]);
        if (lane == 0) { g_ss1[n*4+k] = ps; g_sd1[n*4+k] = pd; }
    }
}

// fused layer-1 edge pass: num -> out (unnormalized), den RED, aggregate num*h.
// one warp per edge. No segment max (logits are O(0.3); exp is safe and softmax
// is shift-invariant, so alpha is identical to the reference).
__global__ void k_edge1(const int* __restrict__ ei, const float* __restrict__ ea,
                        float* __restrict__ out) {
    int gt = blockIdx.x * blockDim.x + threadIdx.x;
    int e = gt >> 5;
    int lane = threadIdx.x & 31;
    if (e >= EF) return;
    int s, d; edge_sd(e, ei, s, d);
    float n0 = 0.f, n1 = 0.f, n2 = 0.f, n3 = 0.f;
    if (lane == 0) {
        float a = (e < Ee) ? ea[e] : g_eamean;
        float4 ss = ((const float4*)g_ss1)[s];
        float4 sd = ((const float4*)g_sd1)[d];
        n0 = __expf(lrelu(ss.x + sd.x + a * g_c1[0]));
        n1 = __expf(lrelu(ss.y + sd.y + a * g_c1[1]));
        n2 = __expf(lrelu(ss.z + sd.z + a * g_c1[2]));
        n3 = __expf(lrelu(ss.w + sd.w + a * g_c1[3]));
        out[EI_OFF + e]      = (float)s;
        out[EI_OFF + EF + e] = (float)d;
        float2* ao = (float2*)(out + A1_OFF + 4*e);   // 8B-aligned region
        ao[0] = make_float2(n0, n1);
        ao[1] = make_float2(n2, n3);
        redAdd4(&g_d1[d*4], n0, n1, n2, n3);
    }
    n0 = __shfl_sync(0xffffffffu, n0, 0);
    n1 = __shfl_sync(0xffffffffu, n1, 0);
    n2 = __shfl_sync(0xffffffffu, n2, 0);
    n3 = __shfl_sync(0xffffffffu, n3, 0);
    float aa = lane < 8 ? n0 : lane < 16 ? n1 : lane < 24 ? n2 : n3;
    float4 v = ((const float4*)g_h1)[s*32 + lane];    // 128 floats per node row
    redAdd4(g_o1 + d*128 + lane*4, aa*v.x, aa*v.y, aa*v.z, aa*v.w);
}

// normalize alpha1 output in place: alpha = num / (den[dst] + 1e-16)
__global__ void k_norm1(const int* __restrict__ ei, float* __restrict__ out) {
    int e = blockIdx.x * blockDim.x + threadIdx.x;
    if (e >= EF) return;
    int d = (e < Ee) ? ei[Ee + e] : (e - Ee);
    float4 dd = ((const float4*)g_d1)[d];
    float2* ao = (float2*)(out + A1_OFF + 4*e);
    float2 a01 = ao[0], a23 = ao[1];
    ao[0] = make_float2(a01.x / (dd.x + 1e-16f), a01.y / (dd.y + 1e-16f));
    ao[1] = make_float2(a23.x / (dd.z + 1e-16f), a23.y / (dd.w + 1e-16f));
}

// layer-2 projection + scores: warp per node; divides layer-1 aggregate by den here.
__global__ void k_node2(const float* __restrict__ W2, const float* __restrict__ b1,
                        const float* __restrict__ as2, const float* __restrict__ ad2) {
    __shared__ float W2s[128*32];
    __shared__ float hs[4][128];
    int t = threadIdx.x;
    for (int i = t; i < 4096; i += 128) W2s[i] = W2[i];
    __syncthreads();
    int warp = t >> 5, lane = t & 31;
    int n = blockIdx.x * 4 + warp;
    if (n >= Nn) return;
    float4 v  = ((const float4*)g_o1)[n*32 + lane];
    float4 bb = ((const float4*)b1)[lane];
    float dn = g_d1[n*4 + (lane >> 3)] + 1e-16f;       // head = (lane*4)/32
    float inv = 1.0f / dn;
    hs[warp][lane*4+0] = elu(v.x * inv + bb.x);
    hs[warp][lane*4+1] = elu(v.y * inv + bb.y);
    hs[warp][lane*4+2] = elu(v.z * inv + bb.z);
    hs[warp][lane*4+3] = elu(v.w * inv + bb.w);
    __syncwarp();
    float acc = 0.f;
#pragma unroll 16
    for (int i = 0; i < 128; i++)
        acc += hs[warp][i] * W2s[i*32 + lane];
    g_h2[n*32 + lane] = acc;
    float ps = wredsum(acc * as2[lane]);
    float pd = wredsum(acc * ad2[lane]);
    if (lane == 0) { g_ss2[n] = ps; g_sd2[n] = pd; }
}

// fused layer-2 edge pass: 8 lanes per edge (32 channels), 4 edges per warp.
// den RED + unnormalized aggregate; normalization happens in k_node3.
__global__ void k_edge2(const int* __restrict__ ei, const float* __restrict__ ea) {
    int gt = blockIdx.x * blockDim.x + threadIdx.x;
    int lane = threadIdx.x & 31;
    int e = (gt >> 5) * 4 + (lane >> 3);
    if (e >= EF) return;
    int sub = lane & 7;
    int s, d; edge_sd(e, ei, s, d);
    float a = (e < Ee) ? ea[e] : g_eamean;
    float num = __expf(lrelu(g_ss2[s] + g_sd2[d] + a * g_c2));
    if (sub == 0) redAdd1(&g_d2[d], num);
    float4 v = ((const float4*)g_h2)[s*8 + sub];
    redAdd4(g_o2 + d*32 + sub*4, num*v.x, num*v.y, num*v.z, num*v.w);
}

// final node activations, actor scores, graph embed partial sums
__global__ void k_node3(const float* __restrict__ b2, const float* __restrict__ Wa,
                        const float* __restrict__ ba) {
    __shared__ float sacc[32];
    int t = threadIdx.x;
    if (t < 32) sacc[t] = 0.f;
    __syncthreads();
    int lane = t & 31, warp = t >> 5;
    int nwarps = gridDim.x * (blockDim.x >> 5);
    float bl = b2[lane], wl = Wa[lane], bb = ba[0];
    for (int n = blockIdx.x * (blockDim.x >> 5) + warp; n < Nn; n += nwarps) {
        float inv = 1.0f / (g_d2[n] + 1e-16f);
        float v = g_o2[n*32 + lane] * inv + bl;
        v = elu(v);
        atomicAdd(&sacc[lane], v);
        float p = wredsum(v * wl);
        if (lane == 0) g_scores[n] = p + bb;
    }
    __syncthreads();
    if (t < 32) atomicAdd(&g_gsum[t], sacc[t]);
}

// softmax over [cash, scores[stock_idx]] + critic value
__global__ void k_head(const float* __restrict__ cash, const int* __restrict__ stock_idx,
                       const float* __restrict__ Wc, const float* __restrict__ bc,
                       int ns, float* __restrict__ out) {
    if (threadIdx.x < 32) {
        float p = wredsum(g_gsum[threadIdx.x] * (1.0f / Nn) * Wc[threadIdx.x]);
        if (threadIdx.x == 0) out[V_OFF] = p + bc[0];
    }
    __shared__ float sm[32];
    __shared__ float bM, bS;
    int t = threadIdx.x, lane = t & 31, w = t >> 5, nw = blockDim.x >> 5;
    int total = ns + 1;
    // max
    float m = -INF_;
    for (int i = t; i < total; i += blockDim.x) {
        float v = (i == 0) ? cash[0] : g_scores[stock_idx[i-1]];
        m = fmaxf(m, v);
    }
    m = wredmax(m);
    if (lane == 0) sm[w] = m;
    __syncthreads();
    if (w == 0) {
        float v = (lane < nw) ? sm[lane] : -INF_;
        v = wredmax(v);
        if (lane == 0) bM = v;
    }
    __syncthreads();
    float M = bM;
    // sum
    float s = 0.f;
    for (int i = t; i < total; i += blockDim.x) {
        float v = (i == 0) ? cash[0] : g_scores[stock_idx[i-1]];
        s += __expf(v - M);
    }
    s = wredsum(s);
    __syncthreads();
    if (lane == 0) sm[w] = s;
    __syncthreads();
    if (w == 0) {
        float v = (lane < nw) ? sm[lane] : 0.f;
        v = wredsum(v);
        if (lane == 0) bS = v;
    }
    __syncthreads();
    float inv = 1.0f / bS;
    for (int i = t; i < total; i += blockDim.x) {
        float v = (i == 0) ? cash[0] : g_scores[stock_idx[i-1]];
        out[W_OFF + i] = __expf(v - M) * inv;
    }
}

// ---------------- launch ----------------
extern "C" void kernel_launch(void* const* d_in, const int* in_sizes, int n_in,
                              void* d_out, int out_size) {
    const float* x    = (const float*)d_in[0];
    const float* ea   = (const float*)d_in[1];
    const float* W1   = (const float*)d_in[2];
    const float* as1  = (const float*)d_in[3];
    const float* ad1  = (const float*)d_in[4];
    const float* We1  = (const float*)d_in[5];
    const float* ae1  = (const float*)d_in[6];
    const float* b1   = (const float*)d_in[7];
    const float* W2   = (const float*)d_in[8];
    const float* as2  = (const float*)d_in[9];
    const float* ad2  = (const float*)d_in[10];
    const float* We2  = (const float*)d_in[11];
    const float* ae2  = (const float*)d_in[12];
    const float* b2   = (const float*)d_in[13];
    const float* Wa   = (const float*)d_in[14];
    const float* ba   = (const float*)d_in[15];
    const float* cash = (const float*)d_in[16];
    const float* Wc   = (const float*)d_in[17];
    const float* bc   = (const float*)d_in[18];
    const int*   ei   = (const int*)  d_in[19];
    const int*   sidx = (const int*)  d_in[20];
    float* out = (float*)d_out;
    int ns = in_sizes[20];

    k_init  <<<4096, 256>>>();
    k_easum <<<2048, 256>>>(ea);
    k_consts<<<1, 128>>>(We1, ae1, We2, ae2);
    k_node1 <<<(Nn + 3) / 4, 128>>>(x, W1, as1, ad1);
    k_edge1 <<<(EF*32 + 255) / 256, 256>>>(ei, ea, out);
    k_norm1 <<<(EF + 255) / 256, 256>>>(ei, out);
    k_node2 <<<(Nn + 3) / 4, 128>>>(W2, b1, as2, ad2);
    k_edge2 <<<(EF*8 + 255) / 256, 256>>>(ei, ea);
    k_node3 <<<512, 256>>>(b2, Wa, ba);
    k_head  <<<1, 1024>>>(cash, sidx, Wc, bc, ns, out);
}

// round 3
// speedup vs baseline: 1.2004x; 1.0431x over previous
#include <cuda_runtime.h>
#include <math.h>

// ---------------- problem constants ----------------
#define Nn    50000
#define Ee    1600000
#define EF    1650000          // E + N self loops
#define INF_  3.402823466e38f

// output layout (float32, flattened in return order)
#define W_OFF  0               // weights [25001]
#define V_OFF  25001           // value   [1]
#define EI_OFF 25002           // edge_index_full [2, EF]
#define A1_OFF (25002 + 2*EF)  // alpha1 [EF, 4]  (8B-aligned only!)

// ---------------- device scratch ----------------
__device__ __align__(16) float g_h1  [Nn*128];   // layer1 projected features
__device__ __align__(16) float g_ss1 [Nn*4];     // s_src1
__device__ __align__(16) float g_sd1 [Nn*4];     // s_dst1
__device__ __align__(16) float g_o1  [Nn*128];   // layer1 NORMALIZED aggregate
__device__ __align__(16) float g_h2  [Nn*32];    // layer2 projected features
__device__ float g_ss2[Nn], g_sd2[Nn];
__device__ float g_scores[Nn];
__device__ float g_gsum[32];
__device__ float g_easum, g_eamean;
__device__ float g_c1[4], g_c2;
// CSR-by-dst structures
__device__ int g_cnt [Nn];
__device__ int g_off [Nn+1];
__device__ int g_pos [Nn];
__device__ int g_esrc[EF];
__device__ int g_eid [EF];

// ---------------- helpers ----------------
__device__ __forceinline__ float wredsum(float v) {
#pragma unroll
    for (int o = 16; o; o >>= 1) v += __shfl_xor_sync(0xffffffffu, v, o);
    return v;
}
__device__ __forceinline__ float wredmax(float v) {
#pragma unroll
    for (int o = 16; o; o >>= 1) v = fmaxf(v, __shfl_xor_sync(0xffffffffu, v, o));
    return v;
}
__device__ __forceinline__ float lrelu(float x) { return x >= 0.f ? x : 0.2f * x; }
__device__ __forceinline__ float elu(float x)   { return x > 0.f ? x : expm1f(x); }

__device__ __forceinline__ void edge_sd(int e, const int* __restrict__ ei, int& s, int& d) {
    if (e < Ee) { s = ei[e]; d = ei[Ee + e]; }
    else        { s = e - Ee; d = s; }
}

// ---------------- kernels ----------------
__global__ void k_init() {
    int stride = gridDim.x * blockDim.x;
    int t = blockIdx.x * blockDim.x + threadIdx.x;
    for (int i = t; i < Nn; i += stride) g_cnt[i] = 0;
    if (t < 32) g_gsum[t] = 0.f;
    if (t == 0) g_easum = 0.f;
}

__global__ void k_easum(const float* __restrict__ ea) {
    float s = 0.f;
    for (int i = blockIdx.x * blockDim.x + threadIdx.x; i < Ee; i += gridDim.x * blockDim.x)
        s += ea[i];
    s = wredsum(s);
    __shared__ float sm[8];
    int lane = threadIdx.x & 31, w = threadIdx.x >> 5;
    if (lane == 0) sm[w] = s;
    __syncthreads();
    if (threadIdx.x == 0) {
        float b = 0.f;
        for (int i = 0; i < (int)(blockDim.x >> 5); i++) b += sm[i];
        atomicAdd(&g_easum, b);
    }
}

__global__ void k_consts(const float* __restrict__ We1, const float* __restrict__ ae1,
                         const float* __restrict__ We2, const float* __restrict__ ae2) {
    int t = threadIdx.x;            // 128 threads
    float p = We1[t] * ae1[t];
    p = wredsum(p);
    if ((t & 31) == 0) g_c1[t >> 5] = p;
    if (t < 32) {
        float q = We2[t] * ae2[t];
        q = wredsum(q);
        if (t == 0) { g_c2 = q; g_eamean = g_easum * (1.0f / Ee); }
    }
}

// histogram of dst (incl. self loops)
__global__ void k_hist(const int* __restrict__ ei) {
    int e = blockIdx.x * blockDim.x + threadIdx.x;
    if (e >= EF) return;
    int d = (e < Ee) ? ei[Ee + e] : (e - Ee);
    atomicAdd(&g_cnt[d], 1);
}

// single-block exclusive scan of g_cnt -> g_off, g_pos
__global__ void k_scan() {
    __shared__ int wsum[32];
    int t = threadIdx.x, lane = t & 31, w = t >> 5;
    int carry = 0;
    for (int base = 0; base < Nn; base += 1024) {
        int idx = base + t;
        int v = (idx < Nn) ? g_cnt[idx] : 0;
        int val = v;
#pragma unroll
        for (int o = 1; o < 32; o <<= 1) { int x = __shfl_up_sync(0xffffffffu, val, o); if (lane >= o) val += x; }
        if (lane == 31) wsum[w] = val;
        __syncthreads();
        if (w == 0) {
            int b = wsum[lane];
#pragma unroll
            for (int o = 1; o < 32; o <<= 1) { int x = __shfl_up_sync(0xffffffffu, b, o); if (lane >= o) b += x; }
            wsum[lane] = b;
        }
        __syncthreads();
        int add = (w > 0) ? wsum[w - 1] : 0;
        int excl = carry + add + val - v;
        if (idx < Nn) { g_off[idx] = excl; g_pos[idx] = excl; }
        carry += wsum[31];
        __syncthreads();
    }
    if (t == 0) g_off[Nn] = carry;
}

// scatter edges into CSR order + emit edge_index_full output
__global__ void k_scatter(const int* __restrict__ ei, float* __restrict__ out) {
    int e = blockIdx.x * blockDim.x + threadIdx.x;
    if (e >= EF) return;
    int s, d; edge_sd(e, ei, s, d);
    out[EI_OFF + e]      = (float)s;
    out[EI_OFF + EF + e] = (float)d;
    int p = atomicAdd(&g_pos[d], 1);
    g_esrc[p] = s;
    g_eid[p]  = e;
}

// layer-1 projection + attention scores: grid-stride, warp per node
__global__ void k_node1(const float* __restrict__ x, const float* __restrict__ W1,
                        const float* __restrict__ as1, const float* __restrict__ ad1) {
    __shared__ float W1s[5*128];
    __shared__ float s_as[128], s_ad[128];
    int t = threadIdx.x;
    for (int i = t; i < 640; i += 256) W1s[i] = W1[i];
    if (t < 128) { s_as[t] = as1[t]; s_ad[t] = ad1[t]; }
    __syncthreads();
    int lane = t & 31;
    int warp = (blockIdx.x * blockDim.x + t) >> 5;
    int nwarps = (gridDim.x * blockDim.x) >> 5;
    for (int n = warp; n < Nn; n += nwarps) {
        float x0 = x[n*5+0], x1 = x[n*5+1], x2 = x[n*5+2], x3 = x[n*5+3], x4 = x[n*5+4];
#pragma unroll
        for (int k = 0; k < 4; k++) {
            int ch = lane + 32 * k;
            float acc = x0*W1s[ch] + x1*W1s[128+ch] + x2*W1s[256+ch] + x3*W1s[384+ch] + x4*W1s[512+ch];
            g_h1[n*128 + ch] = acc;
            float ps = wredsum(acc * s_as[ch]);
            float pd = wredsum(acc * s_ad[ch]);
            if (lane == 0) { g_ss1[n*4+k] = ps; g_sd1[n*4+k] = pd; }
        }
    }
}

// layer-1 aggregation over CSR segments: warp per node, unroll x2.
// Produces: normalized g_o1, normalized alpha in d_out. No atomics, no max-pass
// (logits are O(0.3); exp without shift is safe, softmax is shift-invariant).
__global__ void k_agg1(const float* __restrict__ ea, float* __restrict__ out) {
    int t = threadIdx.x, lane = t & 31;
    int warp = (blockIdx.x * blockDim.x + t) >> 5;
    int nwarps = (gridDim.x * blockDim.x) >> 5;
    float c0 = g_c1[0], c1 = g_c1[1], c2 = g_c1[2], c3 = g_c1[3];
    float eam = g_eamean;
    int h = lane >> 3;                       // this lane's head (4 channels each)
    for (int d = warp; d < Nn; d += nwarps) {
        int beg = g_off[d], end = g_off[d+1];
        float4 sd = ((const float4*)g_sd1)[d];
        float4 acc = make_float4(0.f, 0.f, 0.f, 0.f);
        float den0 = 0.f, den1 = 0.f, den2 = 0.f, den3 = 0.f;
        int i = beg;
        for (; i + 1 < end; i += 2) {
            int s0 = g_esrc[i],   e0 = g_eid[i];
            int s1 = g_esrc[i+1], e1 = g_eid[i+1];
            float a0 = (e0 < Ee) ? ea[e0] : eam;
            float a1 = (e1 < Ee) ? ea[e1] : eam;
            float4 sa = ((const float4*)g_ss1)[s0];
            float4 sb = ((const float4*)g_ss1)[s1];
            float4 v0 = ((const float4*)g_h1)[s0*32 + lane];
            float4 v1 = ((const float4*)g_h1)[s1*32 + lane];
            float n00 = __expf(lrelu(sa.x + sd.x + a0*c0));
            float n01 = __expf(lrelu(sa.y + sd.y + a0*c1));
            float n02 = __expf(lrelu(sa.z + sd.z + a0*c2));
            float n03 = __expf(lrelu(sa.w + sd.w + a0*c3));
            float n10 = __expf(lrelu(sb.x + sd.x + a1*c0));
            float n11 = __expf(lrelu(sb.y + sd.y + a1*c1));
            float n12 = __expf(lrelu(sb.z + sd.z + a1*c2));
            float n13 = __expf(lrelu(sb.w + sd.w + a1*c3));
            den0 += n00 + n10; den1 += n01 + n11;
            den2 += n02 + n12; den3 += n03 + n13;
            float w0 = (h == 0) ? n00 : (h == 1) ? n01 : (h == 2) ? n02 : n03;
            float w1 = (h == 0) ? n10 : (h == 1) ? n11 : (h == 2) ? n12 : n13;
            acc.x += w0*v0.x + w1*v1.x;
            acc.y += w0*v0.y + w1*v1.y;
            acc.z += w0*v0.z + w1*v1.z;
            acc.w += w0*v0.w + w1*v1.w;
            // stash unnormalized nums in the alpha output slots (same lane will
            // re-read & normalize below — same-thread RAW through global is safe)
            if (lane == ((i - beg) & 31)) {
                float2* ao = (float2*)(out + A1_OFF + 4*e0);
                ao[0] = make_float2(n00, n01); ao[1] = make_float2(n02, n03);
            }
            if (lane == ((i + 1 - beg) & 31)) {
                float2* ao = (float2*)(out + A1_OFF + 4*e1);
                ao[0] = make_float2(n10, n11); ao[1] = make_float2(n12, n13);
            }
        }
        if (i < end) {
            int s0 = g_esrc[i], e0 = g_eid[i];
            float a0 = (e0 < Ee) ? ea[e0] : eam;
            float4 sa = ((const float4*)g_ss1)[s0];
            float4 v0 = ((const float4*)g_h1)[s0*32 + lane];
            float n00 = __expf(lrelu(sa.x + sd.x + a0*c0));
            float n01 = __expf(lrelu(sa.y + sd.y + a0*c1));
            float n02 = __expf(lrelu(sa.z + sd.z + a0*c2));
            float n03 = __expf(lrelu(sa.w + sd.w + a0*c3));
            den0 += n00; den1 += n01; den2 += n02; den3 += n03;
            float w0 = (h == 0) ? n00 : (h == 1) ? n01 : (h == 2) ? n02 : n03;
            acc.x += w0*v0.x; acc.y += w0*v0.y; acc.z += w0*v0.z; acc.w += w0*v0.w;
            if (lane == ((i - beg) & 31)) {
                float2* ao = (float2*)(out + A1_OFF + 4*e0);
                ao[0] = make_float2(n00, n01); ao[1] = make_float2(n02, n03);
            }
        }
        float i0 = 1.f / (den0 + 1e-16f), i1 = 1.f / (den1 + 1e-16f);
        float i2 = 1.f / (den2 + 1e-16f), i3 = 1.f / (den3 + 1e-16f);
        float invh = (h == 0) ? i0 : (h == 1) ? i1 : (h == 2) ? i2 : i3;
        float4 r = make_float4(acc.x*invh, acc.y*invh, acc.z*invh, acc.w*invh);
        ((float4*)g_o1)[d*32 + lane] = r;
        // normalize alphas: lane j handles positions with (pos-beg)&31 == j,
        // exactly the positions whose nums this lane wrote above.
        for (int j = beg + lane; j < end; j += 32) {
            int e = g_eid[j];
            float2* ao = (float2*)(out + A1_OFF + 4*e);
            float2 p0 = ao[0], p1 = ao[1];
            ao[0] = make_float2(p0.x * i0, p0.y * i1);
            ao[1] = make_float2(p1.x * i2, p1.y * i3);
        }
    }
}

// layer-2 projection + scores: grid-stride, warp per node, W2 staged once/block
__global__ void k_node2(const float* __restrict__ W2, const float* __restrict__ b1,
                        const float* __restrict__ as2, const float* __restrict__ ad2) {
    __shared__ float W2s[128*32];
    __shared__ float hs[8][128];
    int t = threadIdx.x;
    for (int i = t; i < 4096; i += 256) W2s[i] = W2[i];
    __syncthreads();
    int lane = t & 31, w = t >> 5;
    int warp = (blockIdx.x * blockDim.x + t) >> 5;
    int nwarps = (gridDim.x * blockDim.x) >> 5;
    float4 bb = ((const float4*)b1)[lane];
    float asv = as2[lane], adv = ad2[lane];
    for (int n = warp; n < Nn; n += nwarps) {
        float4 v = ((const float4*)g_o1)[n*32 + lane];   // already normalized
        hs[w][lane*4+0] = elu(v.x + bb.x);
        hs[w][lane*4+1] = elu(v.y + bb.y);
        hs[w][lane*4+2] = elu(v.z + bb.z);
        hs[w][lane*4+3] = elu(v.w + bb.w);
        __syncwarp();
        float acc = 0.f;
#pragma unroll 16
        for (int i = 0; i < 128; i++)
            acc += hs[w][i] * W2s[i*32 + lane];
        g_h2[n*32 + lane] = acc;
        float ps = wredsum(acc * asv);
        float pd = wredsum(acc * adv);
        if (lane == 0) { g_ss2[n] = ps; g_sd2[n] = pd; }
        __syncwarp();
    }
}

// layer-2 aggregation + final node head, fused: warp per node
__global__ void k_agg2(const float* __restrict__ ea, const float* __restrict__ b2,
                       const float* __restrict__ Wa, const float* __restrict__ ba) {
    __shared__ float sacc[32];
    int t = threadIdx.x, lane = t & 31;
    if (t < 32) sacc[t] = 0.f;
    __syncthreads();
    int warp = (blockIdx.x * blockDim.x + t) >> 5;
    int nwarps = (gridDim.x * blockDim.x) >> 5;
    float c = g_c2, eam = g_eamean;
    float bl = b2[lane], wl = Wa[lane], bb = ba[0];
    float gacc = 0.f;
    for (int d = warp; d < Nn; d += nwarps) {
        int beg = g_off[d], end = g_off[d+1];
        float sdv = g_sd2[d];
        float acc = 0.f, den = 0.f;
        int i = beg;
        for (; i + 1 < end; i += 2) {
            int s0 = g_esrc[i],   e0 = g_eid[i];
            int s1 = g_esrc[i+1], e1 = g_eid[i+1];
            float a0 = (e0 < Ee) ? ea[e0] : eam;
            float a1 = (e1 < Ee) ? ea[e1] : eam;
            float ss0 = g_ss2[s0], ss1v = g_ss2[s1];
            float v0 = g_h2[s0*32 + lane];
            float v1 = g_h2[s1*32 + lane];
            float n0 = __expf(lrelu(ss0  + sdv + a0*c));
            float n1 = __expf(lrelu(ss1v + sdv + a1*c));
            den += n0 + n1;
            acc += n0*v0 + n1*v1;
        }
        if (i < end) {
            int s0 = g_esrc[i], e0 = g_eid[i];
            float a0 = (e0 < Ee) ? ea[e0] : eam;
            float n0 = __expf(lrelu(g_ss2[s0] + sdv + a0*c));
            den += n0;
            acc += n0 * g_h2[s0*32 + lane];
        }
        float v = elu(acc / (den + 1e-16f) + bl);
        gacc += v;
        float p = wredsum(v * wl);
        if (lane == 0) g_scores[d] = p + bb;
    }
    atomicAdd(&sacc[lane], gacc);
    __syncthreads();
    if (t < 32) atomicAdd(&g_gsum[t], sacc[t]);
}

// softmax over [cash, scores[stock_idx]] + critic value
__global__ void k_head(const float* __restrict__ cash, const int* __restrict__ stock_idx,
                       const float* __restrict__ Wc, const float* __restrict__ bc,
                       int ns, float* __restrict__ out) {
    if (threadIdx.x < 32) {
        float p = wredsum(g_gsum[threadIdx.x] * (1.0f / Nn) * Wc[threadIdx.x]);
        if (threadIdx.x == 0) out[V_OFF] = p + bc[0];
    }
    __shared__ float sm[32];
    __shared__ float bM, bS;
    int t = threadIdx.x, lane = t & 31, w = t >> 5, nw = blockDim.x >> 5;
    int total = ns + 1;
    float m = -INF_;
    for (int i = t; i < total; i += blockDim.x) {
        float v = (i == 0) ? cash[0] : g_scores[stock_idx[i-1]];
        m = fmaxf(m, v);
    }
    m = wredmax(m);
    if (lane == 0) sm[w] = m;
    __syncthreads();
    if (w == 0) {
        float v = (lane < nw) ? sm[lane] : -INF_;
        v = wredmax(v);
        if (lane == 0) bM = v;
    }
    __syncthreads();
    float M = bM;
    float s = 0.f;
    for (int i = t; i < total; i += blockDim.x) {
        float v = (i == 0) ? cash[0] : g_scores[stock_idx[i-1]];
        s += __expf(v - M);
    }
    s = wredsum(s);
    __syncthreads();
    if (lane == 0) sm[w] = s;
    __syncthreads();
    if (w == 0) {
        float v = (lane < nw) ? sm[lane] : 0.f;
        v = wredsum(v);
        if (lane == 0) bS = v;
    }
    __syncthreads();
    float inv = 1.0f / bS;
    for (int i = t; i < total; i += blockDim.x) {
        float v = (i == 0) ? cash[0] : g_scores[stock_idx[i-1]];
        out[W_OFF + i] = __expf(v - M) * inv;
    }
}

// ---------------- launch ----------------
extern "C" void kernel_launch(void* const* d_in, const int* in_sizes, int n_in,
                              void* d_out, int out_size) {
    const float* x    = (const float*)d_in[0];
    const float* ea   = (const float*)d_in[1];
    const float* W1   = (const float*)d_in[2];
    const float* as1  = (const float*)d_in[3];
    const float* ad1  = (const float*)d_in[4];
    const float* We1  = (const float*)d_in[5];
    const float* ae1  = (const float*)d_in[6];
    const float* b1   = (const float*)d_in[7];
    const float* W2   = (const float*)d_in[8];
    const float* as2  = (const float*)d_in[9];
    const float* ad2  = (const float*)d_in[10];
    const float* We2  = (const float*)d_in[11];
    const float* ae2  = (const float*)d_in[12];
    const float* b2   = (const float*)d_in[13];
    const float* Wa   = (const float*)d_in[14];
    const float* ba   = (const float*)d_in[15];
    const float* cash = (const float*)d_in[16];
    const float* Wc   = (const float*)d_in[17];
    const float* bc   = (const float*)d_in[18];
    const int*   ei   = (const int*)  d_in[19];
    const int*   sidx = (const int*)  d_in[20];
    float* out = (float*)d_out;
    int ns = in_sizes[20];

    k_init   <<<256, 256>>>();
    k_easum  <<<1024, 256>>>(ea);
    k_consts <<<1, 128>>>(We1, ae1, We2, ae2);
    k_node1  <<<296, 256>>>(x, W1, as1, ad1);
    k_hist   <<<(EF + 255) / 256, 256>>>(ei);
    k_scan   <<<1, 1024>>>();
    k_scatter<<<(EF + 255) / 256, 256>>>(ei, out);
    k_agg1   <<<1184, 256>>>(ea, out);
    k_node2  <<<296, 256>>>(W2, b1, as2, ad2);
    k_agg2   <<<1184, 256>>>(ea, b2, Wa, ba);
    k_head   <<<1, 1024>>>(cash, sidx, Wc, bc, ns, out);
}

// round 4
// speedup vs baseline: 1.3782x; 1.1481x over previous
#include <cuda_runtime.h>
#include <math.h>

// ---------------- problem constants ----------------
#define Nn    50000
#define Ee    1600000
#define EF    1650000          // E + N self loops
#define INF_  3.402823466e38f

// output layout (float32, flattened in return order)
#define W_OFF  0               // weights [25001]
#define V_OFF  25001           // value   [1]
#define EI_OFF 25002           // edge_index_full [2, EF]
#define A1_OFF (25002 + 2*EF)  // alpha1 [EF, 4]  (8B-aligned only!)

// ---------------- device scratch ----------------
__device__ __align__(16) float g_h1  [Nn*128];   // layer1 projected features
__device__ __align__(16) float g_ss1 [Nn*4];     // s_src1
__device__ __align__(16) float g_sdd1[Nn*8];     // [sd1(4) | den1(4)] per node
__device__ __align__(16) float g_o1  [Nn*128];   // layer1 NORMALIZED aggregate
__device__ __align__(16) float g_h2  [Nn*32];    // layer2 projected features
__device__ float g_ss2[Nn], g_sd2[Nn];
__device__ float g_scores[Nn];
__device__ float g_gsum[32];
__device__ float g_easum, g_eamean;
__device__ float g_c1[4], g_c2;
// CSR-by-dst structures
__device__ __align__(16) int  g_cnt[Nn];
__device__ __align__(16) int  g_off[Nn + 4];
__device__ __align__(16) int  g_pos[Nn];
__device__ __align__(16) int2 g_sa [EF];         // (src, bitcast(edge_attr)) in CSR order

// ---------------- helpers ----------------
__device__ __forceinline__ float wredsum(float v) {
#pragma unroll
    for (int o = 16; o; o >>= 1) v += __shfl_xor_sync(0xffffffffu, v, o);
    return v;
}
__device__ __forceinline__ float wredmax(float v) {
#pragma unroll
    for (int o = 16; o; o >>= 1) v = fmaxf(v, __shfl_xor_sync(0xffffffffu, v, o));
    return v;
}
__device__ __forceinline__ float lrelu(float x) { return x >= 0.f ? x : 0.2f * x; }
__device__ __forceinline__ float elu(float x)   { return x > 0.f ? x : expm1f(x); }

// ---------------- kernels ----------------
__global__ void k_init() {
    int stride = gridDim.x * blockDim.x;
    int t = blockIdx.x * blockDim.x + threadIdx.x;
    for (int i = t; i < Nn; i += stride) g_cnt[i] = 1;   // self loop pre-counted
    if (t < 32) g_gsum[t] = 0.f;
    if (t == 0) g_easum = 0.f;
}

__global__ void k_easum(const float* __restrict__ ea) {
    float s = 0.f;
    for (int i = blockIdx.x * blockDim.x + threadIdx.x; i < Ee; i += gridDim.x * blockDim.x)
        s += ea[i];
    s = wredsum(s);
    __shared__ float sm[8];
    int lane = threadIdx.x & 31, w = threadIdx.x >> 5;
    if (lane == 0) sm[w] = s;
    __syncthreads();
    if (threadIdx.x == 0) {
        float b = 0.f;
        for (int i = 0; i < (int)(blockDim.x >> 5); i++) b += sm[i];
        atomicAdd(&g_easum, b);
    }
}

__global__ void k_consts(const float* __restrict__ We1, const float* __restrict__ ae1,
                         const float* __restrict__ We2, const float* __restrict__ ae2) {
    int t = threadIdx.x;            // 128 threads
    float p = We1[t] * ae1[t];
    p = wredsum(p);
    if ((t & 31) == 0) g_c1[t >> 5] = p;
    if (t < 32) {
        float q = We2[t] * ae2[t];
        q = wredsum(q);
        if (t == 0) { g_c2 = q; g_eamean = g_easum * (1.0f / Ee); }
    }
}

// histogram of dst over real edges only (self loops pre-counted in init)
__global__ void k_hist(const int* __restrict__ ei) {
    int e = blockIdx.x * blockDim.x + threadIdx.x;
    if (e >= Ee) return;
    atomicAdd(&g_cnt[ei[Ee + e]], 1);
}

// single-block exclusive scan of g_cnt -> g_off, g_pos (int4 vectorized, 13 iters)
__global__ void k_scan() {
    __shared__ int wsum[32];
    int t = threadIdx.x, lane = t & 31, w = t >> 5;
    int carry = 0;
    const int4* cnt4 = (const int4*)g_cnt;
    int4* off4 = (int4*)g_off;
    int4* pos4 = (int4*)g_pos;
    const int M4 = Nn / 4;                 // 12500
    for (int base = 0; base < M4; base += 1024) {
        int idx = base + t;
        int4 v = (idx < M4) ? cnt4[idx] : make_int4(0, 0, 0, 0);
        int tsum = v.x + v.y + v.z + v.w;
        int val = tsum;
#pragma unroll
        for (int o = 1; o < 32; o <<= 1) { int x = __shfl_up_sync(0xffffffffu, val, o); if (lane >= o) val += x; }
        if (lane == 31) wsum[w] = val;
        __syncthreads();
        if (w == 0) {
            int b = wsum[lane];
#pragma unroll
            for (int o = 1; o < 32; o <<= 1) { int x = __shfl_up_sync(0xffffffffu, b, o); if (lane >= o) b += x; }
            wsum[lane] = b;
        }
        __syncthreads();
        int add = (w > 0) ? wsum[w - 1] : 0;
        int excl = carry + add + val - tsum;
        if (idx < M4) {
            int4 o;
            o.x = excl; o.y = excl + v.x; o.z = o.y + v.y; o.w = o.z + v.z;
            off4[idx] = o; pos4[idx] = o;
        }
        carry += wsum[31];
        __syncthreads();
    }
    if (t == 0) g_off[Nn] = carry;
}

// scatter edges into CSR order as (src, edge_attr) pairs + emit edge_index_full
__global__ void k_scatter(const int* __restrict__ ei, const float* __restrict__ ea,
                          float* __restrict__ out) {
    int e = blockIdx.x * blockDim.x + threadIdx.x;
    if (e >= EF) return;
    int s, d; float a;
    if (e < Ee) { s = ei[e]; d = ei[Ee + e]; a = ea[e]; }
    else        { s = e - Ee; d = s; a = g_eamean; }
    out[EI_OFF + e]      = (float)s;
    out[EI_OFF + EF + e] = (float)d;
    int p = atomicAdd(&g_pos[d], 1);
    g_sa[p] = make_int2(s, __float_as_int(a));
}

// layer-1 projection + attention scores: grid-stride, warp per node
__global__ void k_node1(const float* __restrict__ x, const float* __restrict__ W1,
                        const float* __restrict__ as1, const float* __restrict__ ad1) {
    __shared__ float W1s[5*128];
    __shared__ float s_as[128], s_ad[128];
    int t = threadIdx.x;
    for (int i = t; i < 640; i += 256) W1s[i] = W1[i];
    if (t < 128) { s_as[t] = as1[t]; s_ad[t] = ad1[t]; }
    __syncthreads();
    int lane = t & 31;
    int warp = (blockIdx.x * blockDim.x + t) >> 5;
    int nwarps = (gridDim.x * blockDim.x) >> 5;
    for (int n = warp; n < Nn; n += nwarps) {
        float x0 = x[n*5+0], x1 = x[n*5+1], x2 = x[n*5+2], x3 = x[n*5+3], x4 = x[n*5+4];
#pragma unroll
        for (int k = 0; k < 4; k++) {
            int ch = lane + 32 * k;
            float acc = x0*W1s[ch] + x1*W1s[128+ch] + x2*W1s[256+ch] + x3*W1s[384+ch] + x4*W1s[512+ch];
            g_h1[n*128 + ch] = acc;
            float ps = wredsum(acc * s_as[ch]);
            float pd = wredsum(acc * s_ad[ch]);
            if (lane == 0) { g_ss1[n*4+k] = ps; g_sdd1[n*8+k] = pd; }
        }
    }
}

// layer-1 aggregation over CSR segments: warp per node, unroll x2.
// Produces normalized g_o1 and per-node denominators (alpha written separately).
__global__ void k_agg1(float* __restrict__ dummy) {
    int t = threadIdx.x, lane = t & 31;
    int warp = (blockIdx.x * blockDim.x + t) >> 5;
    int nwarps = (gridDim.x * blockDim.x) >> 5;
    float c0 = g_c1[0], c1 = g_c1[1], c2 = g_c1[2], c3 = g_c1[3];
    int h = lane >> 3;                       // this lane's head (4 channels each)
    for (int d = warp; d < Nn; d += nwarps) {
        int beg = g_off[d], end = g_off[d+1];
        float4 sd = ((const float4*)g_sdd1)[d*2];
        float4 acc = make_float4(0.f, 0.f, 0.f, 0.f);
        float den0 = 0.f, den1 = 0.f, den2 = 0.f, den3 = 0.f;
        int i = beg;
        for (; i + 1 < end; i += 2) {
            int2 p0 = g_sa[i], p1 = g_sa[i+1];
            int s0 = p0.x, s1 = p1.x;
            float a0 = __int_as_float(p0.y), a1 = __int_as_float(p1.y);
            float4 sa = ((const float4*)g_ss1)[s0];
            float4 sb = ((const float4*)g_ss1)[s1];
            float4 v0 = ((const float4*)g_h1)[s0*32 + lane];
            float4 v1 = ((const float4*)g_h1)[s1*32 + lane];
            float n00 = __expf(lrelu(sa.x + sd.x + a0*c0));
            float n01 = __expf(lrelu(sa.y + sd.y + a0*c1));
            float n02 = __expf(lrelu(sa.z + sd.z + a0*c2));
            float n03 = __expf(lrelu(sa.w + sd.w + a0*c3));
            float n10 = __expf(lrelu(sb.x + sd.x + a1*c0));
            float n11 = __expf(lrelu(sb.y + sd.y + a1*c1));
            float n12 = __expf(lrelu(sb.z + sd.z + a1*c2));
            float n13 = __expf(lrelu(sb.w + sd.w + a1*c3));
            den0 += n00 + n10; den1 += n01 + n11;
            den2 += n02 + n12; den3 += n03 + n13;
            float w0 = (h == 0) ? n00 : (h == 1) ? n01 : (h == 2) ? n02 : n03;
            float w1 = (h == 0) ? n10 : (h == 1) ? n11 : (h == 2) ? n12 : n13;
            acc.x += w0*v0.x + w1*v1.x;
            acc.y += w0*v0.y + w1*v1.y;
            acc.z += w0*v0.z + w1*v1.z;
            acc.w += w0*v0.w + w1*v1.w;
        }
        if (i < end) {
            int2 p0 = g_sa[i];
            int s0 = p0.x; float a0 = __int_as_float(p0.y);
            float4 sa = ((const float4*)g_ss1)[s0];
            float4 v0 = ((const float4*)g_h1)[s0*32 + lane];
            float n00 = __expf(lrelu(sa.x + sd.x + a0*c0));
            float n01 = __expf(lrelu(sa.y + sd.y + a0*c1));
            float n02 = __expf(lrelu(sa.z + sd.z + a0*c2));
            float n03 = __expf(lrelu(sa.w + sd.w + a0*c3));
            den0 += n00; den1 += n01; den2 += n02; den3 += n03;
            float w0 = (h == 0) ? n00 : (h == 1) ? n01 : (h == 2) ? n02 : n03;
            acc.x += w0*v0.x; acc.y += w0*v0.y; acc.z += w0*v0.z; acc.w += w0*v0.w;
        }
        if (lane == 0)
            ((float4*)g_sdd1)[d*2 + 1] = make_float4(den0, den1, den2, den3);
        float i0 = 1.f / (den0 + 1e-16f), i1 = 1.f / (den1 + 1e-16f);
        float i2 = 1.f / (den2 + 1e-16f), i3 = 1.f / (den3 + 1e-16f);
        float invh = (h == 0) ? i0 : (h == 1) ? i1 : (h == 2) ? i2 : i3;
        ((float4*)g_o1)[d*32 + lane] =
            make_float4(acc.x*invh, acc.y*invh, acc.z*invh, acc.w*invh);
    }
}

// edge-parallel alpha1 writer: original edge order -> coalesced output stores
__global__ void k_alphaE(const int* __restrict__ ei, const float* __restrict__ ea,
                         float* __restrict__ out) {
    int e = blockIdx.x * blockDim.x + threadIdx.x;
    if (e >= EF) return;
    int s, d; float a;
    if (e < Ee) { s = ei[e]; d = ei[Ee + e]; a = ea[e]; }
    else        { s = e - Ee; d = s; a = g_eamean; }
    float4 ss = ((const float4*)g_ss1)[s];
    float4 sd = ((const float4*)g_sdd1)[d*2];
    float4 dd = ((const float4*)g_sdd1)[d*2 + 1];
    float n0 = __expf(lrelu(ss.x + sd.x + a*g_c1[0])) / (dd.x + 1e-16f);
    float n1 = __expf(lrelu(ss.y + sd.y + a*g_c1[1])) / (dd.y + 1e-16f);
    float n2 = __expf(lrelu(ss.z + sd.z + a*g_c1[2])) / (dd.z + 1e-16f);
    float n3 = __expf(lrelu(ss.w + sd.w + a*g_c1[3])) / (dd.w + 1e-16f);
    float2* ao = (float2*)(out + A1_OFF + 4*e);
    ao[0] = make_float2(n0, n1);
    ao[1] = make_float2(n2, n3);
}

// layer-2 projection + scores: grid-stride, warp per node, W2 staged once/block
__global__ void k_node2(const float* __restrict__ W2, const float* __restrict__ b1,
                        const float* __restrict__ as2, const float* __restrict__ ad2) {
    __shared__ float W2s[128*32];
    __shared__ float hs[8][128];
    int t = threadIdx.x;
    for (int i = t; i < 4096; i += 256) W2s[i] = W2[i];
    __syncthreads();
    int lane = t & 31, w = t >> 5;
    int warp = (blockIdx.x * blockDim.x + t) >> 5;
    int nwarps = (gridDim.x * blockDim.x) >> 5;
    float4 bb = ((const float4*)b1)[lane];
    float asv = as2[lane], adv = ad2[lane];
    for (int n = warp; n < Nn; n += nwarps) {
        float4 v = ((const float4*)g_o1)[n*32 + lane];   // already normalized
        hs[w][lane*4+0] = elu(v.x + bb.x);
        hs[w][lane*4+1] = elu(v.y + bb.y);
        hs[w][lane*4+2] = elu(v.z + bb.z);
        hs[w][lane*4+3] = elu(v.w + bb.w);
        __syncwarp();
        float acc = 0.f;
#pragma unroll 16
        for (int i = 0; i < 128; i++)
            acc += hs[w][i] * W2s[i*32 + lane];
        g_h2[n*32 + lane] = acc;
        float ps = wredsum(acc * asv);
        float pd = wredsum(acc * adv);
        if (lane == 0) { g_ss2[n] = ps; g_sd2[n] = pd; }
        __syncwarp();
    }
}

// layer-2 aggregation + final node head, fused: warp per node
__global__ void k_agg2(const float* __restrict__ b2, const float* __restrict__ Wa,
                       const float* __restrict__ ba) {
    __shared__ float sacc[32];
    int t = threadIdx.x, lane = t & 31;
    if (t < 32) sacc[t] = 0.f;
    __syncthreads();
    int warp = (blockIdx.x * blockDim.x + t) >> 5;
    int nwarps = (gridDim.x * blockDim.x) >> 5;
    float c = g_c2;
    float bl = b2[lane], wl = Wa[lane], bb = ba[0];
    float gacc = 0.f;
    for (int d = warp; d < Nn; d += nwarps) {
        int beg = g_off[d], end = g_off[d+1];
        float sdv = g_sd2[d];
        float acc = 0.f, den = 0.f;
        int i = beg;
        for (; i + 1 < end; i += 2) {
            int2 p0 = g_sa[i], p1 = g_sa[i+1];
            int s0 = p0.x, s1 = p1.x;
            float a0 = __int_as_float(p0.y), a1 = __int_as_float(p1.y);
            float ss0 = g_ss2[s0], ss1v = g_ss2[s1];
            float v0 = g_h2[s0*32 + lane];
            float v1 = g_h2[s1*32 + lane];
            float n0 = __expf(lrelu(ss0  + sdv + a0*c));
            float n1 = __expf(lrelu(ss1v + sdv + a1*c));
            den += n0 + n1;
            acc += n0*v0 + n1*v1;
        }
        if (i < end) {
            int2 p0 = g_sa[i];
            int s0 = p0.x; float a0 = __int_as_float(p0.y);
            float n0 = __expf(lrelu(g_ss2[s0] + sdv + a0*c));
            den += n0;
            acc += n0 * g_h2[s0*32 + lane];
        }
        float v = elu(acc / (den + 1e-16f) + bl);
        gacc += v;
        float p = wredsum(v * wl);
        if (lane == 0) g_scores[d] = p + bb;
    }
    atomicAdd(&sacc[lane], gacc);
    __syncthreads();
    if (t < 32) atomicAdd(&g_gsum[t], sacc[t]);
}

// softmax over [cash, scores[stock_idx]] + critic value
__global__ void k_head(const float* __restrict__ cash, const int* __restrict__ stock_idx,
                       const float* __restrict__ Wc, const float* __restrict__ bc,
                       int ns, float* __restrict__ out) {
    if (threadIdx.x < 32) {
        float p = wredsum(g_gsum[threadIdx.x] * (1.0f / Nn) * Wc[threadIdx.x]);
        if (threadIdx.x == 0) out[V_OFF] = p + bc[0];
    }
    __shared__ float sm[32];
    __shared__ float bM, bS;
    int t = threadIdx.x, lane = t & 31, w = t >> 5, nw = blockDim.x >> 5;
    int total = ns + 1;
    float m = -INF_;
    for (int i = t; i < total; i += blockDim.x) {
        float v = (i == 0) ? cash[0] : g_scores[stock_idx[i-1]];
        m = fmaxf(m, v);
    }
    m = wredmax(m);
    if (lane == 0) sm[w] = m;
    __syncthreads();
    if (w == 0) {
        float v = (lane < nw) ? sm[lane] : -INF_;
        v = wredmax(v);
        if (lane == 0) bM = v;
    }
    __syncthreads();
    float M = bM;
    float s = 0.f;
    for (int i = t; i < total; i += blockDim.x) {
        float v = (i == 0) ? cash[0] : g_scores[stock_idx[i-1]];
        s += __expf(v - M);
    }
    s = wredsum(s);
    __syncthreads();
    if (lane == 0) sm[w] = s;
    __syncthreads();
    if (w == 0) {
        float v = (lane < nw) ? sm[lane] : 0.f;
        v = wredsum(v);
        if (lane == 0) bS = v;
    }
    __syncthreads();
    float inv = 1.0f / bS;
    for (int i = t; i < total; i += blockDim.x) {
        float v = (i == 0) ? cash[0] : g_scores[stock_idx[i-1]];
        out[W_OFF + i] = __expf(v - M) * inv;
    }
}

// ---------------- launch ----------------
extern "C" void kernel_launch(void* const* d_in, const int* in_sizes, int n_in,
                              void* d_out, int out_size) {
    const float* x    = (const float*)d_in[0];
    const float* ea   = (const float*)d_in[1];
    const float* W1   = (const float*)d_in[2];
    const float* as1  = (const float*)d_in[3];
    const float* ad1  = (const float*)d_in[4];
    const float* We1  = (const float*)d_in[5];
    const float* ae1  = (const float*)d_in[6];
    const float* b1   = (const float*)d_in[7];
    const float* W2   = (const float*)d_in[8];
    const float* as2  = (const float*)d_in[9];
    const float* ad2  = (const float*)d_in[10];
    const float* We2  = (const float*)d_in[11];
    const float* ae2  = (const float*)d_in[12];
    const float* b2   = (const float*)d_in[13];
    const float* Wa   = (const float*)d_in[14];
    const float* ba   = (const float*)d_in[15];
    const float* cash = (const float*)d_in[16];
    const float* Wc   = (const float*)d_in[17];
    const float* bc   = (const float*)d_in[18];
    const int*   ei   = (const int*)  d_in[19];
    const int*   sidx = (const int*)  d_in[20];
    float* out = (float*)d_out;
    int ns = in_sizes[20];

    k_init   <<<256, 256>>>();
    k_easum  <<<1024, 256>>>(ea);
    k_consts <<<1, 128>>>(We1, ae1, We2, ae2);
    k_node1  <<<592, 256>>>(x, W1, as1, ad1);
    k_hist   <<<(Ee + 255) / 256, 256>>>(ei);
    k_scan   <<<1, 1024>>>();
    k_scatter<<<(EF + 255) / 256, 256>>>(ei, ea, out);
    k_agg1   <<<1184, 256>>>(out);
    k_alphaE <<<(EF + 255) / 256, 256>>>(ei, ea, out);
    k_node2  <<<592, 256>>>(W2, b1, as2, ad2);
    k_agg2   <<<1184, 256>>>(b2, Wa, ba);
    k_head   <<<1, 1024>>>(cash, sidx, Wc, bc, ns, out);
}

// round 5
// speedup vs baseline: 1.5150x; 1.0993x over previous
#include <cuda_runtime.h>
#include <math.h>

// ---------------- problem constants ----------------
#define Nn    50000
#define Ee    1600000
#define EF    1650000          // E + N self loops
#define INF_  3.402823466e38f

// output layout (float32, flattened in return order)
#define W_OFF  0               // weights [25001]
#define V_OFF  25001           // value   [1]
#define EI_OFF 25002           // edge_index_full [2, EF]
#define A1_OFF (25002 + 2*EF)  // alpha1 [EF, 4]  (8B-aligned only!)

// ---------------- device scratch ----------------
__device__ __align__(16) float g_h1  [Nn*128];   // layer1 projected features
__device__ __align__(16) float g_ss1 [Nn*4];     // s_src1
__device__ __align__(16) float g_sdd1[Nn*8];     // [sd1(4) | den1(4)] per node
__device__ __align__(16) float g_o1  [Nn*128];   // layer1 NORMALIZED aggregate
__device__ __align__(16) float g_h2  [Nn*32];    // layer2 projected features
__device__ float g_ss2[Nn], g_sd2[Nn];
__device__ float g_scores[Nn];
__device__ float g_gsum[32];
__device__ float g_easum, g_eamean;
__device__ float g_c1[4], g_c2;
// CSR-by-dst structures
__device__ __align__(16) int  g_cnt[Nn];
__device__ __align__(16) int  g_off[Nn + 4];
__device__ __align__(16) int  g_pos[Nn];
__device__ __align__(16) int2 g_sa [EF];         // (src, bitcast(edge_attr)) in CSR order

// ---------------- helpers ----------------
__device__ __forceinline__ float wredsum(float v) {
#pragma unroll
    for (int o = 16; o; o >>= 1) v += __shfl_xor_sync(0xffffffffu, v, o);
    return v;
}
__device__ __forceinline__ float wredmax(float v) {
#pragma unroll
    for (int o = 16; o; o >>= 1) v = fmaxf(v, __shfl_xor_sync(0xffffffffu, v, o));
    return v;
}
__device__ __forceinline__ float lrelu(float x) { return x >= 0.f ? x : 0.2f * x; }
__device__ __forceinline__ float elu(float x)   { return x > 0.f ? x : expm1f(x); }

// ---------------- kernels ----------------
__global__ void k_init() {
    int stride = gridDim.x * blockDim.x;
    int t = blockIdx.x * blockDim.x + threadIdx.x;
    for (int i = t; i < Nn; i += stride) g_cnt[i] = 1;   // self loop pre-counted
    if (t < 32) g_gsum[t] = 0.f;
    if (t == 0) g_easum = 0.f;
}

__global__ void k_easum(const float* __restrict__ ea) {
    float s = 0.f;
    for (int i = blockIdx.x * blockDim.x + threadIdx.x; i < Ee; i += gridDim.x * blockDim.x)
        s += ea[i];
    s = wredsum(s);
    __shared__ float sm[8];
    int lane = threadIdx.x & 31, w = threadIdx.x >> 5;
    if (lane == 0) sm[w] = s;
    __syncthreads();
    if (threadIdx.x == 0) {
        float b = 0.f;
        for (int i = 0; i < (int)(blockDim.x >> 5); i++) b += sm[i];
        atomicAdd(&g_easum, b);
    }
}

__global__ void k_consts(const float* __restrict__ We1, const float* __restrict__ ae1,
                         const float* __restrict__ We2, const float* __restrict__ ae2) {
    int t = threadIdx.x;            // 128 threads
    float p = We1[t] * ae1[t];
    p = wredsum(p);
    if ((t & 31) == 0) g_c1[t >> 5] = p;
    if (t < 32) {
        float q = We2[t] * ae2[t];
        q = wredsum(q);
        if (t == 0) { g_c2 = q; g_eamean = g_easum * (1.0f / Ee); }
    }
}

// histogram of dst over real edges only (self loops pre-counted in init)
__global__ void k_hist(const int* __restrict__ ei) {
    int e = blockIdx.x * blockDim.x + threadIdx.x;
    if (e >= Ee) return;
    atomicAdd(&g_cnt[ei[Ee + e]], 1);
}

// single-block exclusive scan of g_cnt -> g_off, g_pos (int4 vectorized, 13 iters)
__global__ void k_scan() {
    __shared__ int wsum[32];
    int t = threadIdx.x, lane = t & 31, w = t >> 5;
    int carry = 0;
    const int4* cnt4 = (const int4*)g_cnt;
    int4* off4 = (int4*)g_off;
    int4* pos4 = (int4*)g_pos;
    const int M4 = Nn / 4;                 // 12500
    for (int base = 0; base < M4; base += 1024) {
        int idx = base + t;
        int4 v = (idx < M4) ? cnt4[idx] : make_int4(0, 0, 0, 0);
        int tsum = v.x + v.y + v.z + v.w;
        int val = tsum;
#pragma unroll
        for (int o = 1; o < 32; o <<= 1) { int x = __shfl_up_sync(0xffffffffu, val, o); if (lane >= o) val += x; }
        if (lane == 31) wsum[w] = val;
        __syncthreads();
        if (w == 0) {
            int b = wsum[lane];
#pragma unroll
            for (int o = 1; o < 32; o <<= 1) { int x = __shfl_up_sync(0xffffffffu, b, o); if (lane >= o) b += x; }
            wsum[lane] = b;
        }
        __syncthreads();
        int add = (w > 0) ? wsum[w - 1] : 0;
        int excl = carry + add + val - tsum;
        if (idx < M4) {
            int4 o;
            o.x = excl; o.y = excl + v.x; o.z = o.y + v.y; o.w = o.z + v.z;
            off4[idx] = o; pos4[idx] = o;
        }
        carry += wsum[31];
        __syncthreads();
    }
    if (t == 0) g_off[Nn] = carry;
}

// scatter edges into CSR order as (src, edge_attr) pairs + emit edge_index_full
__global__ void k_scatter(const int* __restrict__ ei, const float* __restrict__ ea,
                          float* __restrict__ out) {
    int e = blockIdx.x * blockDim.x + threadIdx.x;
    if (e >= EF) return;
    int s, d; float a;
    if (e < Ee) { s = ei[e]; d = ei[Ee + e]; a = ea[e]; }
    else        { s = e - Ee; d = s; a = g_eamean; }
    out[EI_OFF + e]      = (float)s;
    out[EI_OFF + EF + e] = (float)d;
    int p = atomicAdd(&g_pos[d], 1);
    g_sa[p] = make_int2(s, __float_as_int(a));
}

// layer-1 projection + attention scores: grid-stride, warp per node
__global__ void k_node1(const float* __restrict__ x, const float* __restrict__ W1,
                        const float* __restrict__ as1, const float* __restrict__ ad1) {
    __shared__ float W1s[5*128];
    __shared__ float s_as[128], s_ad[128];
    int t = threadIdx.x;
    for (int i = t; i < 640; i += 256) W1s[i] = W1[i];
    if (t < 128) { s_as[t] = as1[t]; s_ad[t] = ad1[t]; }
    __syncthreads();
    int lane = t & 31;
    int warp = (blockIdx.x * blockDim.x + t) >> 5;
    int nwarps = (gridDim.x * blockDim.x) >> 5;
    for (int n = warp; n < Nn; n += nwarps) {
        float x0 = x[n*5+0], x1 = x[n*5+1], x2 = x[n*5+2], x3 = x[n*5+3], x4 = x[n*5+4];
#pragma unroll
        for (int k = 0; k < 4; k++) {
            int ch = lane + 32 * k;
            float acc = x0*W1s[ch] + x1*W1s[128+ch] + x2*W1s[256+ch] + x3*W1s[384+ch] + x4*W1s[512+ch];
            g_h1[n*128 + ch] = acc;
            float ps = wredsum(acc * s_as[ch]);
            float pd = wredsum(acc * s_ad[ch]);
            if (lane == 0) { g_ss1[n*4+k] = ps; g_sdd1[n*8+k] = pd; }
        }
    }
}

// layer-1 aggregation over CSR segments: warp per node, unroll x2.
// Produces normalized g_o1 and per-node denominators (alpha written separately).
__global__ void k_agg1() {
    int t = threadIdx.x, lane = t & 31;
    int warp = (blockIdx.x * blockDim.x + t) >> 5;
    int nwarps = (gridDim.x * blockDim.x) >> 5;
    float c0 = g_c1[0], c1 = g_c1[1], c2 = g_c1[2], c3 = g_c1[3];
    int h = lane >> 3;                       // this lane's head (4 channels each)
    for (int d = warp; d < Nn; d += nwarps) {
        int beg = g_off[d], end = g_off[d+1];
        float4 sd = ((const float4*)g_sdd1)[d*2];
        float4 acc = make_float4(0.f, 0.f, 0.f, 0.f);
        float den0 = 0.f, den1 = 0.f, den2 = 0.f, den3 = 0.f;
        int i = beg;
        for (; i + 1 < end; i += 2) {
            int2 p0 = g_sa[i], p1 = g_sa[i+1];
            int s0 = p0.x, s1 = p1.x;
            float a0 = __int_as_float(p0.y), a1 = __int_as_float(p1.y);
            float4 sa = ((const float4*)g_ss1)[s0];
            float4 sb = ((const float4*)g_ss1)[s1];
            float4 v0 = ((const float4*)g_h1)[s0*32 + lane];
            float4 v1 = ((const float4*)g_h1)[s1*32 + lane];
            float n00 = __expf(lrelu(sa.x + sd.x + a0*c0));
            float n01 = __expf(lrelu(sa.y + sd.y + a0*c1));
            float n02 = __expf(lrelu(sa.z + sd.z + a0*c2));
            float n03 = __expf(lrelu(sa.w + sd.w + a0*c3));
            float n10 = __expf(lrelu(sb.x + sd.x + a1*c0));
            float n11 = __expf(lrelu(sb.y + sd.y + a1*c1));
            float n12 = __expf(lrelu(sb.z + sd.z + a1*c2));
            float n13 = __expf(lrelu(sb.w + sd.w + a1*c3));
            den0 += n00 + n10; den1 += n01 + n11;
            den2 += n02 + n12; den3 += n03 + n13;
            float w0 = (h == 0) ? n00 : (h == 1) ? n01 : (h == 2) ? n02 : n03;
            float w1 = (h == 0) ? n10 : (h == 1) ? n11 : (h == 2) ? n12 : n13;
            acc.x += w0*v0.x + w1*v1.x;
            acc.y += w0*v0.y + w1*v1.y;
            acc.z += w0*v0.z + w1*v1.z;
            acc.w += w0*v0.w + w1*v1.w;
        }
        if (i < end) {
            int2 p0 = g_sa[i];
            int s0 = p0.x; float a0 = __int_as_float(p0.y);
            float4 sa = ((const float4*)g_ss1)[s0];
            float4 v0 = ((const float4*)g_h1)[s0*32 + lane];
            float n00 = __expf(lrelu(sa.x + sd.x + a0*c0));
            float n01 = __expf(lrelu(sa.y + sd.y + a0*c1));
            float n02 = __expf(lrelu(sa.z + sd.z + a0*c2));
            float n03 = __expf(lrelu(sa.w + sd.w + a0*c3));
            den0 += n00; den1 += n01; den2 += n02; den3 += n03;
            float w0 = (h == 0) ? n00 : (h == 1) ? n01 : (h == 2) ? n02 : n03;
            acc.x += w0*v0.x; acc.y += w0*v0.y; acc.z += w0*v0.z; acc.w += w0*v0.w;
        }
        if (lane == 0)
            ((float4*)g_sdd1)[d*2 + 1] = make_float4(den0, den1, den2, den3);
        float i0 = 1.f / (den0 + 1e-16f), i1 = 1.f / (den1 + 1e-16f);
        float i2 = 1.f / (den2 + 1e-16f), i3 = 1.f / (den3 + 1e-16f);
        float invh = (h == 0) ? i0 : (h == 1) ? i1 : (h == 2) ? i2 : i3;
        ((float4*)g_o1)[d*32 + lane] =
            make_float4(acc.x*invh, acc.y*invh, acc.z*invh, acc.w*invh);
    }
}

// edge-parallel alpha1 writer: original edge order -> coalesced output stores
__global__ void k_alphaE(const int* __restrict__ ei, const float* __restrict__ ea,
                         float* __restrict__ out) {
    int e = blockIdx.x * blockDim.x + threadIdx.x;
    if (e >= EF) return;
    int s, d; float a;
    if (e < Ee) { s = ei[e]; d = ei[Ee + e]; a = ea[e]; }
    else        { s = e - Ee; d = s; a = g_eamean; }
    float4 ss = ((const float4*)g_ss1)[s];
    float4 sd = ((const float4*)g_sdd1)[d*2];
    float4 dd = ((const float4*)g_sdd1)[d*2 + 1];
    float n0 = __expf(lrelu(ss.x + sd.x + a*g_c1[0])) / (dd.x + 1e-16f);
    float n1 = __expf(lrelu(ss.y + sd.y + a*g_c1[1])) / (dd.y + 1e-16f);
    float n2 = __expf(lrelu(ss.z + sd.z + a*g_c1[2])) / (dd.z + 1e-16f);
    float n3 = __expf(lrelu(ss.w + sd.w + a*g_c1[3])) / (dd.w + 1e-16f);
    float2* ao = (float2*)(out + A1_OFF + 4*e);
    ao[0] = make_float2(n0, n1);
    ao[1] = make_float2(n2, n3);
}

// layer-2 projection + scores: grid-stride, warp per node, W2 staged once/block
__global__ void k_node2(const float* __restrict__ W2, const float* __restrict__ b1,
                        const float* __restrict__ as2, const float* __restrict__ ad2) {
    __shared__ float W2s[128*32];
    __shared__ float hs[8][128];
    int t = threadIdx.x;
    for (int i = t; i < 4096; i += 256) W2s[i] = W2[i];
    __syncthreads();
    int lane = t & 31, w = t >> 5;
    int warp = (blockIdx.x * blockDim.x + t) >> 5;
    int nwarps = (gridDim.x * blockDim.x) >> 5;
    float4 bb = ((const float4*)b1)[lane];
    float asv = as2[lane], adv = ad2[lane];
    for (int n = warp; n < Nn; n += nwarps) {
        float4 v = ((const float4*)g_o1)[n*32 + lane];   // already normalized
        hs[w][lane*4+0] = elu(v.x + bb.x);
        hs[w][lane*4+1] = elu(v.y + bb.y);
        hs[w][lane*4+2] = elu(v.z + bb.z);
        hs[w][lane*4+3] = elu(v.w + bb.w);
        __syncwarp();
        float acc = 0.f;
#pragma unroll 16
        for (int i = 0; i < 128; i++)
            acc += hs[w][i] * W2s[i*32 + lane];
        g_h2[n*32 + lane] = acc;
        float ps = wredsum(acc * asv);
        float pd = wredsum(acc * adv);
        if (lane == 0) { g_ss2[n] = ps; g_sd2[n] = pd; }
        __syncwarp();
    }
}

// layer-2 aggregation + final node head, fused: warp per node
__global__ void k_agg2(const float* __restrict__ b2, const float* __restrict__ Wa,
                       const float* __restrict__ ba) {
    __shared__ float sacc[32];
    int t = threadIdx.x, lane = t & 31;
    if (t < 32) sacc[t] = 0.f;
    __syncthreads();
    int warp = (blockIdx.x * blockDim.x + t) >> 5;
    int nwarps = (gridDim.x * blockDim.x) >> 5;
    float c = g_c2;
    float bl = b2[lane], wl = Wa[lane], bb = ba[0];
    float gacc = 0.f;
    for (int d = warp; d < Nn; d += nwarps) {
        int beg = g_off[d], end = g_off[d+1];
        float sdv = g_sd2[d];
        float acc = 0.f, den = 0.f;
        int i = beg;
        for (; i + 1 < end; i += 2) {
            int2 p0 = g_sa[i], p1 = g_sa[i+1];
            int s0 = p0.x, s1 = p1.x;
            float a0 = __int_as_float(p0.y), a1 = __int_as_float(p1.y);
            float ss0 = g_ss2[s0], ss1v = g_ss2[s1];
            float v0 = g_h2[s0*32 + lane];
            float v1 = g_h2[s1*32 + lane];
            float n0 = __expf(lrelu(ss0  + sdv + a0*c));
            float n1 = __expf(lrelu(ss1v + sdv + a1*c));
            den += n0 + n1;
            acc += n0*v0 + n1*v1;
        }
        if (i < end) {
            int2 p0 = g_sa[i];
            int s0 = p0.x; float a0 = __int_as_float(p0.y);
            float n0 = __expf(lrelu(g_ss2[s0] + sdv + a0*c));
            den += n0;
            acc += n0 * g_h2[s0*32 + lane];
        }
        float v = elu(acc / (den + 1e-16f) + bl);
        gacc += v;
        float p = wredsum(v * wl);
        if (lane == 0) g_scores[d] = p + bb;
    }
    atomicAdd(&sacc[lane], gacc);
    __syncthreads();
    if (t < 32) atomicAdd(&g_gsum[t], sacc[t]);
}

// softmax over [cash, scores[stock_idx]] + critic value
__global__ void k_head(const float* __restrict__ cash, const int* __restrict__ stock_idx,
                       const float* __restrict__ Wc, const float* __restrict__ bc,
                       int ns, float* __restrict__ out) {
    if (threadIdx.x < 32) {
        float p = wredsum(g_gsum[threadIdx.x] * (1.0f / Nn) * Wc[threadIdx.x]);
        if (threadIdx.x == 0) out[V_OFF] = p + bc[0];
    }
    __shared__ float sm[32];
    __shared__ float bM, bS;
    int t = threadIdx.x, lane = t & 31, w = t >> 5, nw = blockDim.x >> 5;
    int total = ns + 1;
    float m = -INF_;
    for (int i = t; i < total; i += blockDim.x) {
        float v = (i == 0) ? cash[0] : g_scores[stock_idx[i-1]];
        m = fmaxf(m, v);
    }
    m = wredmax(m);
    if (lane == 0) sm[w] = m;
    __syncthreads();
    if (w == 0) {
        float v = (lane < nw) ? sm[lane] : -INF_;
        v = wredmax(v);
        if (lane == 0) bM = v;
    }
    __syncthreads();
    float M = bM;
    float s = 0.f;
    for (int i = t; i < total; i += blockDim.x) {
        float v = (i == 0) ? cash[0] : g_scores[stock_idx[i-1]];
        s += __expf(v - M);
    }
    s = wredsum(s);
    __syncthreads();
    if (lane == 0) sm[w] = s;
    __syncthreads();
    if (w == 0) {
        float v = (lane < nw) ? sm[lane] : 0.f;
        v = wredsum(v);
        if (lane == 0) bS = v;
    }
    __syncthreads();
    float inv = 1.0f / bS;
    for (int i = t; i < total; i += blockDim.x) {
        float v = (i == 0) ? cash[0] : g_scores[stock_idx[i-1]];
        out[W_OFF + i] = __expf(v - M) * inv;
    }
}

// ---------------- launch ----------------
extern "C" void kernel_launch(void* const* d_in, const int* in_sizes, int n_in,
                              void* d_out, int out_size) {
    const float* x    = (const float*)d_in[0];
    const float* ea   = (const float*)d_in[1];
    const float* W1   = (const float*)d_in[2];
    const float* as1  = (const float*)d_in[3];
    const float* ad1  = (const float*)d_in[4];
    const float* We1  = (const float*)d_in[5];
    const float* ae1  = (const float*)d_in[6];
    const float* b1   = (const float*)d_in[7];
    const float* W2   = (const float*)d_in[8];
    const float* as2  = (const float*)d_in[9];
    const float* ad2  = (const float*)d_in[10];
    const float* We2  = (const float*)d_in[11];
    const float* ae2  = (const float*)d_in[12];
    const float* b2   = (const float*)d_in[13];
    const float* Wa   = (const float*)d_in[14];
    const float* ba   = (const float*)d_in[15];
    const float* cash = (const float*)d_in[16];
    const float* Wc   = (const float*)d_in[17];
    const float* bc   = (const float*)d_in[18];
    const int*   ei   = (const int*)  d_in[19];
    const int*   sidx = (const int*)  d_in[20];
    float* out = (float*)d_out;
    int ns = in_sizes[20];

    // lazy one-time stream/event setup (host-side objects only; no device mem)
    static cudaStream_t sA = nullptr, sB = nullptr;
    static cudaEvent_t evFork, evConsts, evNode1, evAgg1, evAlpha, evEnd;
    if (!sA) {
        cudaStreamCreateWithFlags(&sA, cudaStreamNonBlocking);
        cudaStreamCreateWithFlags(&sB, cudaStreamNonBlocking);
        cudaEventCreateWithFlags(&evFork,   cudaEventDisableTiming);
        cudaEventCreateWithFlags(&evConsts, cudaEventDisableTiming);
        cudaEventCreateWithFlags(&evNode1,  cudaEventDisableTiming);
        cudaEventCreateWithFlags(&evAgg1,   cudaEventDisableTiming);
        cudaEventCreateWithFlags(&evAlpha,  cudaEventDisableTiming);
        cudaEventCreateWithFlags(&evEnd,    cudaEventDisableTiming);
    }

    // fork from the harness's (captured) stream
    cudaEventRecord(evFork, 0);
    cudaStreamWaitEvent(sA, evFork, 0);
    cudaStreamWaitEvent(sB, evFork, 0);

    // stream B: easum -> consts -> node1 (independent of CSR build)
    k_easum <<<1024, 256, 0, sB>>>(ea);
    k_consts<<<1, 128, 0, sB>>>(We1, ae1, We2, ae2);
    cudaEventRecord(evConsts, sB);
    k_node1 <<<592, 256, 0, sB>>>(x, W1, as1, ad1);
    cudaEventRecord(evNode1, sB);

    // stream A: CSR build -> aggregate -> layer2 -> head
    k_init  <<<256, 256, 0, sA>>>();
    k_hist  <<<(Ee + 255) / 256, 256, 0, sA>>>(ei);
    k_scan  <<<1, 1024, 0, sA>>>();
    cudaStreamWaitEvent(sA, evConsts, 0);               // eamean
    k_scatter<<<(EF + 255) / 256, 256, 0, sA>>>(ei, ea, out);
    cudaStreamWaitEvent(sA, evNode1, 0);                // h1, ss1, sd1
    k_agg1  <<<1184, 256, 0, sA>>>();
    cudaEventRecord(evAgg1, sA);

    // stream B: alpha writer overlaps node2 (disjoint data)
    cudaStreamWaitEvent(sB, evAgg1, 0);                 // denominators
    k_alphaE<<<(EF + 255) / 256, 256, 0, sB>>>(ei, ea, out);
    cudaEventRecord(evAlpha, sB);

    k_node2 <<<592, 256, 0, sA>>>(W2, b1, as2, ad2);
    k_agg2  <<<1184, 256, 0, sA>>>(b2, Wa, ba);
    k_head  <<<1, 1024, 0, sA>>>(cash, sidx, Wc, bc, ns, out);
    cudaEventRecord(evEnd, sA);

    // join both streams back into the harness stream
    cudaStreamWaitEvent(0, evEnd, 0);
    cudaStreamWaitEvent(0, evAlpha, 0);
}

// round 6
// speedup vs baseline: 1.7224x; 1.1369x over previous
#include <cuda_runtime.h>
#include <math.h>

// ---------------- problem constants ----------------
#define Nn    50000
#define Ee    1600000
#define EF    1650000          // E + N self loops
#define INF_  3.402823466e38f

// output layout (float32, flattened in return order)
#define W_OFF  0               // weights [25001]
#define V_OFF  25001           // value   [1]
#define EI_OFF 25002           // edge_index_full [2, EF]
#define A1_OFF (25002 + 2*EF)  // alpha1 [EF, 4]  (8B-aligned only!)

// ---------------- device scratch ----------------
__device__ __align__(16) float g_h1  [Nn*128];   // layer1 projected features
__device__ __align__(16) float g_ss1 [Nn*4];     // s_src1
__device__ __align__(16) float g_sdd1[Nn*8];     // [sd1(4) | den1(4)] per node
__device__ __align__(16) float g_o1  [Nn*128];   // layer1 NORMALIZED aggregate
__device__ __align__(16) float g_h2  [Nn*32];    // layer2 projected features
__device__ float g_ss2[Nn], g_sd2[Nn];
__device__ float g_scores[Nn];
__device__ float g_gsum[32];
__device__ float g_easum, g_eamean;
__device__ float g_c1[4], g_c2;
// CSR-by-dst structures
__device__ __align__(16) int  g_cnt[Nn];
__device__ __align__(16) int  g_off[Nn + 4];
__device__ __align__(16) int  g_pos[Nn];
__device__ __align__(16) int2 g_sa [EF];         // (src, bitcast(edge_attr)) in CSR order

// ---------------- helpers ----------------
__device__ __forceinline__ float wredsum(float v) {
#pragma unroll
    for (int o = 16; o; o >>= 1) v += __shfl_xor_sync(0xffffffffu, v, o);
    return v;
}
__device__ __forceinline__ float wredmax(float v) {
#pragma unroll
    for (int o = 16; o; o >>= 1) v = fmaxf(v, __shfl_xor_sync(0xffffffffu, v, o));
    return v;
}
__device__ __forceinline__ float lrelu(float x) { return x >= 0.f ? x : 0.2f * x; }
__device__ __forceinline__ float elu(float x)   { return x > 0.f ? x : expm1f(x); }

// ---------------- kernels ----------------
__global__ void k_init() {
    int stride = gridDim.x * blockDim.x;
    int t = blockIdx.x * blockDim.x + threadIdx.x;
    for (int i = t; i < Nn; i += stride) g_cnt[i] = 1;   // self loop pre-counted
    if (t < 32) g_gsum[t] = 0.f;
    if (t == 0) g_easum = 0.f;
}

__global__ void k_easum(const float* __restrict__ ea) {
    float s = 0.f;
    for (int i = blockIdx.x * blockDim.x + threadIdx.x; i < Ee; i += gridDim.x * blockDim.x)
        s += ea[i];
    s = wredsum(s);
    __shared__ float sm[8];
    int lane = threadIdx.x & 31, w = threadIdx.x >> 5;
    if (lane == 0) sm[w] = s;
    __syncthreads();
    if (threadIdx.x == 0) {
        float b = 0.f;
        for (int i = 0; i < (int)(blockDim.x >> 5); i++) b += sm[i];
        atomicAdd(&g_easum, b);
    }
}

__global__ void k_consts(const float* __restrict__ We1, const float* __restrict__ ae1,
                         const float* __restrict__ We2, const float* __restrict__ ae2) {
    int t = threadIdx.x;            // 128 threads
    float p = We1[t] * ae1[t];
    p = wredsum(p);
    if ((t & 31) == 0) g_c1[t >> 5] = p;
    if (t < 32) {
        float q = We2[t] * ae2[t];
        q = wredsum(q);
        if (t == 0) { g_c2 = q; g_eamean = g_easum * (1.0f / Ee); }
    }
}

// emit edge_index_full output (depends only on ei) — runs on side stream
__global__ void k_eif(const int* __restrict__ ei, float* __restrict__ out) {
    int e = blockIdx.x * blockDim.x + threadIdx.x;
    if (e >= EF) return;
    int s, d;
    if (e < Ee) { s = ei[e]; d = ei[Ee + e]; }
    else        { s = e - Ee; d = s; }
    out[EI_OFF + e]      = (float)s;
    out[EI_OFF + EF + e] = (float)d;
}

// histogram of dst over real edges only (self loops pre-counted in init)
__global__ void k_hist(const int* __restrict__ ei) {
    int e = blockIdx.x * blockDim.x + threadIdx.x;
    if (e >= Ee) return;
    atomicAdd(&g_cnt[ei[Ee + e]], 1);
}

// single-block exclusive scan of g_cnt -> g_off, g_pos (int4 vectorized, 13 iters)
__global__ void k_scan() {
    __shared__ int wsum[32];
    int t = threadIdx.x, lane = t & 31, w = t >> 5;
    int carry = 0;
    const int4* cnt4 = (const int4*)g_cnt;
    int4* off4 = (int4*)g_off;
    int4* pos4 = (int4*)g_pos;
    const int M4 = Nn / 4;                 // 12500
    for (int base = 0; base < M4; base += 1024) {
        int idx = base + t;
        int4 v = (idx < M4) ? cnt4[idx] : make_int4(0, 0, 0, 0);
        int tsum = v.x + v.y + v.z + v.w;
        int val = tsum;
#pragma unroll
        for (int o = 1; o < 32; o <<= 1) { int x = __shfl_up_sync(0xffffffffu, val, o); if (lane >= o) val += x; }
        if (lane == 31) wsum[w] = val;
        __syncthreads();
        if (w == 0) {
            int b = wsum[lane];
#pragma unroll
            for (int o = 1; o < 32; o <<= 1) { int x = __shfl_up_sync(0xffffffffu, b, o); if (lane >= o) b += x; }
            wsum[lane] = b;
        }
        __syncthreads();
        int add = (w > 0) ? wsum[w - 1] : 0;
        int excl = carry + add + val - tsum;
        if (idx < M4) {
            int4 o;
            o.x = excl; o.y = excl + v.x; o.z = o.y + v.y; o.w = o.z + v.z;
            off4[idx] = o; pos4[idx] = o;
        }
        carry += wsum[31];
        __syncthreads();
    }
    if (t == 0) g_off[Nn] = carry;
}

// scatter edges into CSR order as (src, edge_attr) pairs
__global__ void k_scatter(const int* __restrict__ ei, const float* __restrict__ ea) {
    int e = blockIdx.x * blockDim.x + threadIdx.x;
    if (e >= EF) return;
    int s, d; float a;
    if (e < Ee) { s = ei[e]; d = ei[Ee + e]; a = ea[e]; }
    else        { s = e - Ee; d = s; a = g_eamean; }
    int p = atomicAdd(&g_pos[d], 1);
    g_sa[p] = make_int2(s, __float_as_int(a));
}

// layer-1 projection + attention scores: grid-stride, warp per node
__global__ void k_node1(const float* __restrict__ x, const float* __restrict__ W1,
                        const float* __restrict__ as1, const float* __restrict__ ad1) {
    __shared__ float W1s[5*128];
    __shared__ float s_as[128], s_ad[128];
    int t = threadIdx.x;
    for (int i = t; i < 640; i += 256) W1s[i] = W1[i];
    if (t < 128) { s_as[t] = as1[t]; s_ad[t] = ad1[t]; }
    __syncthreads();
    int lane = t & 31;
    int warp = (blockIdx.x * blockDim.x + t) >> 5;
    int nwarps = (gridDim.x * blockDim.x) >> 5;
    for (int n = warp; n < Nn; n += nwarps) {
        float x0 = x[n*5+0], x1 = x[n*5+1], x2 = x[n*5+2], x3 = x[n*5+3], x4 = x[n*5+4];
#pragma unroll
        for (int k = 0; k < 4; k++) {
            int ch = lane + 32 * k;
            float acc = x0*W1s[ch] + x1*W1s[128+ch] + x2*W1s[256+ch] + x3*W1s[384+ch] + x4*W1s[512+ch];
            g_h1[n*128 + ch] = acc;
            float ps = wredsum(acc * s_as[ch]);
            float pd = wredsum(acc * s_ad[ch]);
            if (lane == 0) { g_ss1[n*4+k] = ps; g_sdd1[n*8+k] = pd; }
        }
    }
}

// layer-1 aggregation over CSR segments: warp per node, unroll x4.
// Each lane computes ONLY its own head's exp (h = lane>>3): 1 MUFU/edge/lane
// instead of 4. Dens recovered per head-group; lane 0 gathers them by shuffle.
__global__ void k_agg1() {
    int t = threadIdx.x, lane = t & 31;
    int warp = (blockIdx.x * blockDim.x + t) >> 5;
    int nwarps = (gridDim.x * blockDim.x) >> 5;
    int h = lane >> 3;                       // this lane's head (4 channels each)
    float ch = g_c1[h];
    for (int d = warp; d < Nn; d += nwarps) {
        int beg = g_off[d], end = g_off[d+1];
        float sdh = g_sdd1[d*8 + h];
        float4 acc = make_float4(0.f, 0.f, 0.f, 0.f);
        float den = 0.f;
        int i = beg;
        for (; i + 3 < end; i += 4) {
            int2 p0 = g_sa[i], p1 = g_sa[i+1], p2 = g_sa[i+2], p3 = g_sa[i+3];
            float sa0 = g_ss1[p0.x*4 + h];
            float sa1 = g_ss1[p1.x*4 + h];
            float sa2 = g_ss1[p2.x*4 + h];
            float sa3 = g_ss1[p3.x*4 + h];
            float4 v0 = ((const float4*)g_h1)[p0.x*32 + lane];
            float4 v1 = ((const float4*)g_h1)[p1.x*32 + lane];
            float4 v2 = ((const float4*)g_h1)[p2.x*32 + lane];
            float4 v3 = ((const float4*)g_h1)[p3.x*32 + lane];
            float n0 = __expf(lrelu(sa0 + sdh + __int_as_float(p0.y)*ch));
            float n1 = __expf(lrelu(sa1 + sdh + __int_as_float(p1.y)*ch));
            float n2 = __expf(lrelu(sa2 + sdh + __int_as_float(p2.y)*ch));
            float n3 = __expf(lrelu(sa3 + sdh + __int_as_float(p3.y)*ch));
            den += (n0 + n1) + (n2 + n3);
            acc.x += n0*v0.x + n1*v1.x + n2*v2.x + n3*v3.x;
            acc.y += n0*v0.y + n1*v1.y + n2*v2.y + n3*v3.y;
            acc.z += n0*v0.z + n1*v1.z + n2*v2.z + n3*v3.z;
            acc.w += n0*v0.w + n1*v1.w + n2*v2.w + n3*v3.w;
        }
        for (; i < end; i++) {
            int2 p0 = g_sa[i];
            float sa0 = g_ss1[p0.x*4 + h];
            float4 v0 = ((const float4*)g_h1)[p0.x*32 + lane];
            float n0 = __expf(lrelu(sa0 + sdh + __int_as_float(p0.y)*ch));
            den += n0;
            acc.x += n0*v0.x; acc.y += n0*v0.y; acc.z += n0*v0.z; acc.w += n0*v0.w;
        }
        float d0 = __shfl_sync(0xffffffffu, den, 0);
        float d1 = __shfl_sync(0xffffffffu, den, 8);
        float d2 = __shfl_sync(0xffffffffu, den, 16);
        float d3 = __shfl_sync(0xffffffffu, den, 24);
        if (lane == 0)
            ((float4*)g_sdd1)[d*2 + 1] = make_float4(d0, d1, d2, d3);
        float invh = 1.0f / (den + 1e-16f);
        ((float4*)g_o1)[d*32 + lane] =
            make_float4(acc.x*invh, acc.y*invh, acc.z*invh, acc.w*invh);
    }
}

// edge-parallel alpha1 writer: original edge order -> coalesced output stores
__global__ void k_alphaE(const int* __restrict__ ei, const float* __restrict__ ea,
                         float* __restrict__ out) {
    int e = blockIdx.x * blockDim.x + threadIdx.x;
    if (e >= EF) return;
    int s, d; float a;
    if (e < Ee) { s = ei[e]; d = ei[Ee + e]; a = ea[e]; }
    else        { s = e - Ee; d = s; a = g_eamean; }
    float4 ss = ((const float4*)g_ss1)[s];
    float4 sd = ((const float4*)g_sdd1)[d*2];
    float4 dd = ((const float4*)g_sdd1)[d*2 + 1];
    float n0 = __expf(lrelu(ss.x + sd.x + a*g_c1[0])) / (dd.x + 1e-16f);
    float n1 = __expf(lrelu(ss.y + sd.y + a*g_c1[1])) / (dd.y + 1e-16f);
    float n2 = __expf(lrelu(ss.z + sd.z + a*g_c1[2])) / (dd.z + 1e-16f);
    float n3 = __expf(lrelu(ss.w + sd.w + a*g_c1[3])) / (dd.w + 1e-16f);
    float2* ao = (float2*)(out + A1_OFF + 4*e);
    ao[0] = make_float2(n0, n1);
    ao[1] = make_float2(n2, n3);
}

// layer-2 projection + scores: grid-stride, warp per node, W2 staged once/block
__global__ void k_node2(const float* __restrict__ W2, const float* __restrict__ b1,
                        const float* __restrict__ as2, const float* __restrict__ ad2) {
    __shared__ float W2s[128*32];
    __shared__ float hs[8][128];
    int t = threadIdx.x;
    for (int i = t; i < 4096; i += 256) W2s[i] = W2[i];
    __syncthreads();
    int lane = t & 31, w = t >> 5;
    int warp = (blockIdx.x * blockDim.x + t) >> 5;
    int nwarps = (gridDim.x * blockDim.x) >> 5;
    float4 bb = ((const float4*)b1)[lane];
    float asv = as2[lane], adv = ad2[lane];
    for (int n = warp; n < Nn; n += nwarps) {
        float4 v = ((const float4*)g_o1)[n*32 + lane];   // already normalized
        hs[w][lane*4+0] = elu(v.x + bb.x);
        hs[w][lane*4+1] = elu(v.y + bb.y);
        hs[w][lane*4+2] = elu(v.z + bb.z);
        hs[w][lane*4+3] = elu(v.w + bb.w);
        __syncwarp();
        float acc = 0.f;
#pragma unroll 16
        for (int i = 0; i < 128; i++)
            acc += hs[w][i] * W2s[i*32 + lane];
        g_h2[n*32 + lane] = acc;
        float ps = wredsum(acc * asv);
        float pd = wredsum(acc * adv);
        if (lane == 0) { g_ss2[n] = ps; g_sd2[n] = pd; }
        __syncwarp();
    }
}

// layer-2 aggregation + final node head, fused: warp per node, unroll x4
__global__ void k_agg2(const float* __restrict__ b2, const float* __restrict__ Wa,
                       const float* __restrict__ ba) {
    __shared__ float sacc[32];
    int t = threadIdx.x, lane = t & 31;
    if (t < 32) sacc[t] = 0.f;
    __syncthreads();
    int warp = (blockIdx.x * blockDim.x + t) >> 5;
    int nwarps = (gridDim.x * blockDim.x) >> 5;
    float c = g_c2;
    float bl = b2[lane], wl = Wa[lane], bb = ba[0];
    float gacc = 0.f;
    for (int d = warp; d < Nn; d += nwarps) {
        int beg = g_off[d], end = g_off[d+1];
        float sdv = g_sd2[d];
        float acc = 0.f, den = 0.f;
        int i = beg;
        for (; i + 3 < end; i += 4) {
            int2 p0 = g_sa[i], p1 = g_sa[i+1], p2 = g_sa[i+2], p3 = g_sa[i+3];
            float ss0 = g_ss2[p0.x], ss1v = g_ss2[p1.x];
            float ss2v = g_ss2[p2.x], ss3v = g_ss2[p3.x];
            float v0 = g_h2[p0.x*32 + lane];
            float v1 = g_h2[p1.x*32 + lane];
            float v2 = g_h2[p2.x*32 + lane];
            float v3 = g_h2[p3.x*32 + lane];
            float n0 = __expf(lrelu(ss0  + sdv + __int_as_float(p0.y)*c));
            float n1 = __expf(lrelu(ss1v + sdv + __int_as_float(p1.y)*c));
            float n2 = __expf(lrelu(ss2v + sdv + __int_as_float(p2.y)*c));
            float n3 = __expf(lrelu(ss3v + sdv + __int_as_float(p3.y)*c));
            den += (n0 + n1) + (n2 + n3);
            acc += n0*v0 + n1*v1 + n2*v2 + n3*v3;
        }
        for (; i < end; i++) {
            int2 p0 = g_sa[i];
            float n0 = __expf(lrelu(g_ss2[p0.x] + sdv + __int_as_float(p0.y)*c));
            den += n0;
            acc += n0 * g_h2[p0.x*32 + lane];
        }
        float v = elu(acc / (den + 1e-16f) + bl);
        gacc += v;
        float p = wredsum(v * wl);
        if (lane == 0) g_scores[d] = p + bb;
    }
    atomicAdd(&sacc[lane], gacc);
    __syncthreads();
    if (t < 32) atomicAdd(&g_gsum[t], sacc[t]);
}

// softmax over [cash, scores[stock_idx]] + critic value
__global__ void k_head(const float* __restrict__ cash, const int* __restrict__ stock_idx,
                       const float* __restrict__ Wc, const float* __restrict__ bc,
                       int ns, float* __restrict__ out) {
    if (threadIdx.x < 32) {
        float p = wredsum(g_gsum[threadIdx.x] * (1.0f / Nn) * Wc[threadIdx.x]);
        if (threadIdx.x == 0) out[V_OFF] = p + bc[0];
    }
    __shared__ float sm[32];
    __shared__ float bM, bS;
    int t = threadIdx.x, lane = t & 31, w = t >> 5, nw = blockDim.x >> 5;
    int total = ns + 1;
    float m = -INF_;
    for (int i = t; i < total; i += blockDim.x) {
        float v = (i == 0) ? cash[0] : g_scores[stock_idx[i-1]];
        m = fmaxf(m, v);
    }
    m = wredmax(m);
    if (lane == 0) sm[w] = m;
    __syncthreads();
    if (w == 0) {
        float v = (lane < nw) ? sm[lane] : -INF_;
        v = wredmax(v);
        if (lane == 0) bM = v;
    }
    __syncthreads();
    float M = bM;
    float s = 0.f;
    for (int i = t; i < total; i += blockDim.x) {
        float v = (i == 0) ? cash[0] : g_scores[stock_idx[i-1]];
        s += __expf(v - M);
    }
    s = wredsum(s);
    __syncthreads();
    if (lane == 0) sm[w] = s;
    __syncthreads();
    if (w == 0) {
        float v = (lane < nw) ? sm[lane] : 0.f;
        v = wredsum(v);
        if (lane == 0) bS = v;
    }
    __syncthreads();
    float inv = 1.0f / bS;
    for (int i = t; i < total; i += blockDim.x) {
        float v = (i == 0) ? cash[0] : g_scores[stock_idx[i-1]];
        out[W_OFF + i] = __expf(v - M) * inv;
    }
}

// ---------------- launch ----------------
extern "C" void kernel_launch(void* const* d_in, const int* in_sizes, int n_in,
                              void* d_out, int out_size) {
    const float* x    = (const float*)d_in[0];
    const float* ea   = (const float*)d_in[1];
    const float* W1   = (const float*)d_in[2];
    const float* as1  = (const float*)d_in[3];
    const float* ad1  = (const float*)d_in[4];
    const float* We1  = (const float*)d_in[5];
    const float* ae1  = (const float*)d_in[6];
    const float* b1   = (const float*)d_in[7];
    const float* W2   = (const float*)d_in[8];
    const float* as2  = (const float*)d_in[9];
    const float* ad2  = (const float*)d_in[10];
    const float* We2  = (const float*)d_in[11];
    const float* ae2  = (const float*)d_in[12];
    const float* b2   = (const float*)d_in[13];
    const float* Wa   = (const float*)d_in[14];
    const float* ba   = (const float*)d_in[15];
    const float* cash = (const float*)d_in[16];
    const float* Wc   = (const float*)d_in[17];
    const float* bc   = (const float*)d_in[18];
    const int*   ei   = (const int*)  d_in[19];
    const int*   sidx = (const int*)  d_in[20];
    float* out = (float*)d_out;
    int ns = in_sizes[20];

    // lazy one-time stream/event setup (host-side objects only; no device mem)
    static cudaStream_t sA = nullptr, sB = nullptr;
    static cudaEvent_t evFork, evConsts, evNode1, evAgg1, evAlpha, evEnd;
    if (!sA) {
        cudaStreamCreateWithFlags(&sA, cudaStreamNonBlocking);
        cudaStreamCreateWithFlags(&sB, cudaStreamNonBlocking);
        cudaEventCreateWithFlags(&evFork,   cudaEventDisableTiming);
        cudaEventCreateWithFlags(&evConsts, cudaEventDisableTiming);
        cudaEventCreateWithFlags(&evNode1,  cudaEventDisableTiming);
        cudaEventCreateWithFlags(&evAgg1,   cudaEventDisableTiming);
        cudaEventCreateWithFlags(&evAlpha,  cudaEventDisableTiming);
        cudaEventCreateWithFlags(&evEnd,    cudaEventDisableTiming);
    }

    // fork from the harness's (captured) stream
    cudaEventRecord(evFork, 0);
    cudaStreamWaitEvent(sA, evFork, 0);
    cudaStreamWaitEvent(sB, evFork, 0);

    // stream B: easum -> consts -> node1 -> edge_index_full (all independent of CSR)
    k_easum <<<1024, 256, 0, sB>>>(ea);
    k_consts<<<1, 128, 0, sB>>>(We1, ae1, We2, ae2);
    cudaEventRecord(evConsts, sB);
    k_node1 <<<592, 256, 0, sB>>>(x, W1, as1, ad1);
    cudaEventRecord(evNode1, sB);
    k_eif   <<<(EF + 255) / 256, 256, 0, sB>>>(ei, out);

    // stream A: CSR build -> aggregate -> layer2 -> head
    k_init  <<<256, 256, 0, sA>>>();
    k_hist  <<<(Ee + 255) / 256, 256, 0, sA>>>(ei);
    k_scan  <<<1, 1024, 0, sA>>>();
    cudaStreamWaitEvent(sA, evConsts, 0);               // eamean
    k_scatter<<<(EF + 255) / 256, 256, 0, sA>>>(ei, ea);
    cudaStreamWaitEvent(sA, evNode1, 0);                // h1, ss1, sd1
    k_agg1  <<<1184, 256, 0, sA>>>();
    cudaEventRecord(evAgg1, sA);

    // stream B: alpha writer overlaps node2/agg2 (disjoint data)
    cudaStreamWaitEvent(sB, evAgg1, 0);                 // denominators
    k_alphaE<<<(EF + 255) / 256, 256, 0, sB>>>(ei, ea, out);
    cudaEventRecord(evAlpha, sB);

    k_node2 <<<592, 256, 0, sA>>>(W2, b1, as2, ad2);
    k_agg2  <<<1184, 256, 0, sA>>>(b2, Wa, ba);
    k_head  <<<1, 1024, 0, sA>>>(cash, sidx, Wc, bc, ns, out);
    cudaEventRecord(evEnd, sA);

    // join both streams back into the harness stream
    cudaStreamWaitEvent(0, evEnd, 0);
    cudaStreamWaitEvent(0, evAlpha, 0);
}

// round 7
// speedup vs baseline: 1.8864x; 1.0952x over previous
#include <cuda_runtime.h>
#include <math.h>

// ---------------- problem constants ----------------
#define Nn    50000
#define Ee    1600000
#define EF    1650000          // E + N self loops
#define INF_  3.402823466e38f

// output layout (float32, flattened in return order)
#define W_OFF  0               // weights [25001]
#define V_OFF  25001           // value   [1]
#define EI_OFF 25002           // edge_index_full [2, EF]
#define A1_OFF (25002 + 2*EF)  // alpha1 [EF, 4]  (8B-aligned only!)

// ---------------- device scratch ----------------
__device__ __align__(16) float g_h1  [Nn*128];   // layer1 projected features
__device__ __align__(16) float g_ss1 [Nn*4];     // s_src1
__device__ __align__(16) float g_sdd1[Nn*8];     // [sd1(4) | den1(4)] per node
__device__ __align__(16) float g_h2  [Nn*32];    // layer2 projected features
__device__ float g_ss2[Nn], g_sd2[Nn];
__device__ float g_scores[Nn];
__device__ float g_gsum[32];
__device__ float g_easum, g_eamean;
__device__ float g_c1[4], g_c2;
// CSR-by-dst structures
__device__ __align__(16) int  g_cnt[Nn];
__device__ __align__(16) int  g_off[Nn + 4];
__device__ __align__(16) int  g_pos[Nn];
__device__ __align__(16) int2 g_sa [EF];         // (src, bitcast(edge_attr)) in CSR order

// ---------------- helpers ----------------
__device__ __forceinline__ float wredsum(float v) {
#pragma unroll
    for (int o = 16; o; o >>= 1) v += __shfl_xor_sync(0xffffffffu, v, o);
    return v;
}
__device__ __forceinline__ float wredmax(float v) {
#pragma unroll
    for (int o = 16; o; o >>= 1) v = fmaxf(v, __shfl_xor_sync(0xffffffffu, v, o));
    return v;
}
__device__ __forceinline__ float lrelu(float x) { return x >= 0.f ? x : 0.2f * x; }
__device__ __forceinline__ float elu(float x)   { return x > 0.f ? x : expm1f(x); }

// ---------------- kernels ----------------
__global__ void k_init() {
    int stride = gridDim.x * blockDim.x;
    int t = blockIdx.x * blockDim.x + threadIdx.x;
    for (int i = t; i < Nn; i += stride) g_cnt[i] = 1;   // self loop pre-counted
    if (t < 32) g_gsum[t] = 0.f;
    if (t == 0) g_easum = 0.f;
}

__global__ void k_easum(const float* __restrict__ ea) {
    float s = 0.f;
    for (int i = blockIdx.x * blockDim.x + threadIdx.x; i < Ee; i += gridDim.x * blockDim.x)
        s += ea[i];
    s = wredsum(s);
    __shared__ float sm[8];
    int lane = threadIdx.x & 31, w = threadIdx.x >> 5;
    if (lane == 0) sm[w] = s;
    __syncthreads();
    if (threadIdx.x == 0) {
        float b = 0.f;
        for (int i = 0; i < (int)(blockDim.x >> 5); i++) b += sm[i];
        atomicAdd(&g_easum, b);
    }
}

__global__ void k_consts(const float* __restrict__ We1, const float* __restrict__ ae1,
                         const float* __restrict__ We2, const float* __restrict__ ae2) {
    int t = threadIdx.x;            // 128 threads
    float p = We1[t] * ae1[t];
    p = wredsum(p);
    if ((t & 31) == 0) g_c1[t >> 5] = p;
    if (t < 32) {
        float q = We2[t] * ae2[t];
        q = wredsum(q);
        if (t == 0) { g_c2 = q; g_eamean = g_easum * (1.0f / Ee); }
    }
}

// emit edge_index_full output (depends only on ei) — runs on side stream
__global__ void k_eif(const int* __restrict__ ei, float* __restrict__ out) {
    int e = blockIdx.x * blockDim.x + threadIdx.x;
    if (e >= EF) return;
    int s, d;
    if (e < Ee) { s = ei[e]; d = ei[Ee + e]; }
    else        { s = e - Ee; d = s; }
    out[EI_OFF + e]      = (float)s;
    out[EI_OFF + EF + e] = (float)d;
}

// histogram of dst over real edges only (self loops pre-counted in init)
__global__ void k_hist(const int* __restrict__ ei) {
    int e = blockIdx.x * blockDim.x + threadIdx.x;
    if (e >= Ee) return;
    atomicAdd(&g_cnt[ei[Ee + e]], 1);
}

// single-block exclusive scan of g_cnt -> g_off, g_pos (int4 vectorized, 13 iters)
__global__ void k_scan() {
    __shared__ int wsum[32];
    int t = threadIdx.x, lane = t & 31, w = t >> 5;
    int carry = 0;
    const int4* cnt4 = (const int4*)g_cnt;
    int4* off4 = (int4*)g_off;
    int4* pos4 = (int4*)g_pos;
    const int M4 = Nn / 4;                 // 12500
    for (int base = 0; base < M4; base += 1024) {
        int idx = base + t;
        int4 v = (idx < M4) ? cnt4[idx] : make_int4(0, 0, 0, 0);
        int tsum = v.x + v.y + v.z + v.w;
        int val = tsum;
#pragma unroll
        for (int o = 1; o < 32; o <<= 1) { int x = __shfl_up_sync(0xffffffffu, val, o); if (lane >= o) val += x; }
        if (lane == 31) wsum[w] = val;
        __syncthreads();
        if (w == 0) {
            int b = wsum[lane];
#pragma unroll
            for (int o = 1; o < 32; o <<= 1) { int x = __shfl_up_sync(0xffffffffu, b, o); if (lane >= o) b += x; }
            wsum[lane] = b;
        }
        __syncthreads();
        int add = (w > 0) ? wsum[w - 1] : 0;
        int excl = carry + add + val - tsum;
        if (idx < M4) {
            int4 o;
            o.x = excl; o.y = excl + v.x; o.z = o.y + v.y; o.w = o.z + v.z;
            off4[idx] = o; pos4[idx] = o;
        }
        carry += wsum[31];
        __syncthreads();
    }
    if (t == 0) g_off[Nn] = carry;
}

// scatter edges into CSR order as (src, edge_attr) pairs
__global__ void k_scatter(const int* __restrict__ ei, const float* __restrict__ ea) {
    int e = blockIdx.x * blockDim.x + threadIdx.x;
    if (e >= EF) return;
    int s, d; float a;
    if (e < Ee) { s = ei[e]; d = ei[Ee + e]; a = ea[e]; }
    else        { s = e - Ee; d = s; a = g_eamean; }
    int p = atomicAdd(&g_pos[d], 1);
    g_sa[p] = make_int2(s, __float_as_int(a));
}

// layer-1 projection + attention scores: grid-stride, warp per node
__global__ void k_node1(const float* __restrict__ x, const float* __restrict__ W1,
                        const float* __restrict__ as1, const float* __restrict__ ad1) {
    __shared__ float W1s[5*128];
    __shared__ float s_as[128], s_ad[128];
    int t = threadIdx.x;
    for (int i = t; i < 640; i += 256) W1s[i] = W1[i];
    if (t < 128) { s_as[t] = as1[t]; s_ad[t] = ad1[t]; }
    __syncthreads();
    int lane = t & 31;
    int warp = (blockIdx.x * blockDim.x + t) >> 5;
    int nwarps = (gridDim.x * blockDim.x) >> 5;
    for (int n = warp; n < Nn; n += nwarps) {
        float x0 = x[n*5+0], x1 = x[n*5+1], x2 = x[n*5+2], x3 = x[n*5+3], x4 = x[n*5+4];
#pragma unroll
        for (int k = 0; k < 4; k++) {
            int ch = lane + 32 * k;
            float acc = x0*W1s[ch] + x1*W1s[128+ch] + x2*W1s[256+ch] + x3*W1s[384+ch] + x4*W1s[512+ch];
            g_h1[n*128 + ch] = acc;
            float ps = wredsum(acc * s_as[ch]);
            float pd = wredsum(acc * s_ad[ch]);
            if (lane == 0) { g_ss1[n*4+k] = ps; g_sdd1[n*8+k] = pd; }
        }
    }
}

// FUSED layer-1 aggregation + layer-2 projection: warp per node, unroll x4.
// Per-lane single-head exp; after aggregation the normalized o1 row lives in
// registers, so the 128x32 W2 projection + elu(+b1) happens right here —
// g_o1 never exists in memory, node2 kernel is gone.
__global__ void k_agg1f(const float* __restrict__ W2, const float* __restrict__ b1,
                        const float* __restrict__ as2, const float* __restrict__ ad2) {
    __shared__ float W2s[128*32];
    __shared__ float hs[8][128];
    int t = threadIdx.x, lane = t & 31, w = t >> 5;
    for (int i = t; i < 4096; i += 256) W2s[i] = W2[i];
    __syncthreads();
    int warp = (blockIdx.x * blockDim.x + t) >> 5;
    int nwarps = (gridDim.x * blockDim.x) >> 5;
    int h = lane >> 3;                       // this lane's head (4 channels each)
    float ch = g_c1[h];
    float4 bb = ((const float4*)b1)[lane];
    float asv = as2[lane], adv = ad2[lane];
    for (int d = warp; d < Nn; d += nwarps) {
        int beg = g_off[d], end = g_off[d+1];
        float sdh = g_sdd1[d*8 + h];
        float4 acc = make_float4(0.f, 0.f, 0.f, 0.f);
        float den = 0.f;
        int i = beg;
        for (; i + 3 < end; i += 4) {
            int2 p0 = g_sa[i], p1 = g_sa[i+1], p2 = g_sa[i+2], p3 = g_sa[i+3];
            float sa0 = g_ss1[p0.x*4 + h];
            float sa1 = g_ss1[p1.x*4 + h];
            float sa2 = g_ss1[p2.x*4 + h];
            float sa3 = g_ss1[p3.x*4 + h];
            float4 v0 = ((const float4*)g_h1)[p0.x*32 + lane];
            float4 v1 = ((const float4*)g_h1)[p1.x*32 + lane];
            float4 v2 = ((const float4*)g_h1)[p2.x*32 + lane];
            float4 v3 = ((const float4*)g_h1)[p3.x*32 + lane];
            float n0 = __expf(lrelu(sa0 + sdh + __int_as_float(p0.y)*ch));
            float n1 = __expf(lrelu(sa1 + sdh + __int_as_float(p1.y)*ch));
            float n2 = __expf(lrelu(sa2 + sdh + __int_as_float(p2.y)*ch));
            float n3 = __expf(lrelu(sa3 + sdh + __int_as_float(p3.y)*ch));
            den += (n0 + n1) + (n2 + n3);
            acc.x += n0*v0.x + n1*v1.x + n2*v2.x + n3*v3.x;
            acc.y += n0*v0.y + n1*v1.y + n2*v2.y + n3*v3.y;
            acc.z += n0*v0.z + n1*v1.z + n2*v2.z + n3*v3.z;
            acc.w += n0*v0.w + n1*v1.w + n2*v2.w + n3*v3.w;
        }
        for (; i < end; i++) {
            int2 p0 = g_sa[i];
            float sa0 = g_ss1[p0.x*4 + h];
            float4 v0 = ((const float4*)g_h1)[p0.x*32 + lane];
            float n0 = __expf(lrelu(sa0 + sdh + __int_as_float(p0.y)*ch));
            den += n0;
            acc.x += n0*v0.x; acc.y += n0*v0.y; acc.z += n0*v0.z; acc.w += n0*v0.w;
        }
        float d0 = __shfl_sync(0xffffffffu, den, 0);
        float d1 = __shfl_sync(0xffffffffu, den, 8);
        float d2 = __shfl_sync(0xffffffffu, den, 16);
        float d3 = __shfl_sync(0xffffffffu, den, 24);
        if (lane == 0)
            ((float4*)g_sdd1)[d*2 + 1] = make_float4(d0, d1, d2, d3);
        float invh = 1.0f / (den + 1e-16f);
        // ---- fused layer-2 projection epilogue (was k_node2) ----
        hs[w][lane*4+0] = elu(acc.x*invh + bb.x);
        hs[w][lane*4+1] = elu(acc.y*invh + bb.y);
        hs[w][lane*4+2] = elu(acc.z*invh + bb.z);
        hs[w][lane*4+3] = elu(acc.w*invh + bb.w);
        __syncwarp();
        float acc2 = 0.f;
#pragma unroll 16
        for (int j = 0; j < 128; j++)
            acc2 += hs[w][j] * W2s[j*32 + lane];
        g_h2[d*32 + lane] = acc2;
        float ps = wredsum(acc2 * asv);
        float pd = wredsum(acc2 * adv);
        if (lane == 0) { g_ss2[d] = ps; g_sd2[d] = pd; }
        __syncwarp();
    }
}

// edge-parallel alpha1 writer: original edge order -> coalesced output stores
__global__ void k_alphaE(const int* __restrict__ ei, const float* __restrict__ ea,
                         float* __restrict__ out) {
    int e = blockIdx.x * blockDim.x + threadIdx.x;
    if (e >= EF) return;
    int s, d; float a;
    if (e < Ee) { s = ei[e]; d = ei[Ee + e]; a = ea[e]; }
    else        { s = e - Ee; d = s; a = g_eamean; }
    float4 ss = ((const float4*)g_ss1)[s];
    float4 sd = ((const float4*)g_sdd1)[d*2];
    float4 dd = ((const float4*)g_sdd1)[d*2 + 1];
    float n0 = __expf(lrelu(ss.x + sd.x + a*g_c1[0])) / (dd.x + 1e-16f);
    float n1 = __expf(lrelu(ss.y + sd.y + a*g_c1[1])) / (dd.y + 1e-16f);
    float n2 = __expf(lrelu(ss.z + sd.z + a*g_c1[2])) / (dd.z + 1e-16f);
    float n3 = __expf(lrelu(ss.w + sd.w + a*g_c1[3])) / (dd.w + 1e-16f);
    float2* ao = (float2*)(out + A1_OFF + 4*e);
    ao[0] = make_float2(n0, n1);
    ao[1] = make_float2(n2, n3);
}

// layer-2 aggregation + final node head, fused: warp per node, unroll x4
__global__ void k_agg2(const float* __restrict__ b2, const float* __restrict__ Wa,
                       const float* __restrict__ ba) {
    __shared__ float sacc[32];
    int t = threadIdx.x, lane = t & 31;
    if (t < 32) sacc[t] = 0.f;
    __syncthreads();
    int warp = (blockIdx.x * blockDim.x + t) >> 5;
    int nwarps = (gridDim.x * blockDim.x) >> 5;
    float c = g_c2;
    float bl = b2[lane], wl = Wa[lane], bb = ba[0];
    float gacc = 0.f;
    for (int d = warp; d < Nn; d += nwarps) {
        int beg = g_off[d], end = g_off[d+1];
        float sdv = g_sd2[d];
        float acc = 0.f, den = 0.f;
        int i = beg;
        for (; i + 3 < end; i += 4) {
            int2 p0 = g_sa[i], p1 = g_sa[i+1], p2 = g_sa[i+2], p3 = g_sa[i+3];
            float ss0 = g_ss2[p0.x], ss1v = g_ss2[p1.x];
            float ss2v = g_ss2[p2.x], ss3v = g_ss2[p3.x];
            float v0 = g_h2[p0.x*32 + lane];
            float v1 = g_h2[p1.x*32 + lane];
            float v2 = g_h2[p2.x*32 + lane];
            float v3 = g_h2[p3.x*32 + lane];
            float n0 = __expf(lrelu(ss0  + sdv + __int_as_float(p0.y)*c));
            float n1 = __expf(lrelu(ss1v + sdv + __int_as_float(p1.y)*c));
            float n2 = __expf(lrelu(ss2v + sdv + __int_as_float(p2.y)*c));
            float n3 = __expf(lrelu(ss3v + sdv + __int_as_float(p3.y)*c));
            den += (n0 + n1) + (n2 + n3);
            acc += n0*v0 + n1*v1 + n2*v2 + n3*v3;
        }
        for (; i < end; i++) {
            int2 p0 = g_sa[i];
            float n0 = __expf(lrelu(g_ss2[p0.x] + sdv + __int_as_float(p0.y)*c));
            den += n0;
            acc += n0 * g_h2[p0.x*32 + lane];
        }
        float v = elu(acc / (den + 1e-16f) + bl);
        gacc += v;
        float p = wredsum(v * wl);
        if (lane == 0) g_scores[d] = p + bb;
    }
    atomicAdd(&sacc[lane], gacc);
    __syncthreads();
    if (t < 32) atomicAdd(&g_gsum[t], sacc[t]);
}

// softmax over [cash, scores[stock_idx]] + critic value
__global__ void k_head(const float* __restrict__ cash, const int* __restrict__ stock_idx,
                       const float* __restrict__ Wc, const float* __restrict__ bc,
                       int ns, float* __restrict__ out) {
    if (threadIdx.x < 32) {
        float p = wredsum(g_gsum[threadIdx.x] * (1.0f / Nn) * Wc[threadIdx.x]);
        if (threadIdx.x == 0) out[V_OFF] = p + bc[0];
    }
    __shared__ float sm[32];
    __shared__ float bM, bS;
    int t = threadIdx.x, lane = t & 31, w = t >> 5, nw = blockDim.x >> 5;
    int total = ns + 1;
    float m = -INF_;
    for (int i = t; i < total; i += blockDim.x) {
        float v = (i == 0) ? cash[0] : g_scores[stock_idx[i-1]];
        m = fmaxf(m, v);
    }
    m = wredmax(m);
    if (lane == 0) sm[w] = m;
    __syncthreads();
    if (w == 0) {
        float v = (lane < nw) ? sm[lane] : -INF_;
        v = wredmax(v);
        if (lane == 0) bM = v;
    }
    __syncthreads();
    float M = bM;
    float s = 0.f;
    for (int i = t; i < total; i += blockDim.x) {
        float v = (i == 0) ? cash[0] : g_scores[stock_idx[i-1]];
        s += __expf(v - M);
    }
    s = wredsum(s);
    __syncthreads();
    if (lane == 0) sm[w] = s;
    __syncthreads();
    if (w == 0) {
        float v = (lane < nw) ? sm[lane] : 0.f;
        v = wredsum(v);
        if (lane == 0) bS = v;
    }
    __syncthreads();
    float inv = 1.0f / bS;
    for (int i = t; i < total; i += blockDim.x) {
        float v = (i == 0) ? cash[0] : g_scores[stock_idx[i-1]];
        out[W_OFF + i] = __expf(v - M) * inv;
    }
}

// ---------------- launch ----------------
extern "C" void kernel_launch(void* const* d_in, const int* in_sizes, int n_in,
                              void* d_out, int out_size) {
    const float* x    = (const float*)d_in[0];
    const float* ea   = (const float*)d_in[1];
    const float* W1   = (const float*)d_in[2];
    const float* as1  = (const float*)d_in[3];
    const float* ad1  = (const float*)d_in[4];
    const float* We1  = (const float*)d_in[5];
    const float* ae1  = (const float*)d_in[6];
    const float* b1   = (const float*)d_in[7];
    const float* W2   = (const float*)d_in[8];
    const float* as2  = (const float*)d_in[9];
    const float* ad2  = (const float*)d_in[10];
    const float* We2  = (const float*)d_in[11];
    const float* ae2  = (const float*)d_in[12];
    const float* b2   = (const float*)d_in[13];
    const float* Wa   = (const float*)d_in[14];
    const float* ba   = (const float*)d_in[15];
    const float* cash = (const float*)d_in[16];
    const float* Wc   = (const float*)d_in[17];
    const float* bc   = (const float*)d_in[18];
    const int*   ei   = (const int*)  d_in[19];
    const int*   sidx = (const int*)  d_in[20];
    float* out = (float*)d_out;
    int ns = in_sizes[20];

    // lazy one-time stream/event setup (host-side objects only; no device mem)
    static cudaStream_t sA = nullptr, sB = nullptr;
    static cudaEvent_t evFork, evConsts, evNode1, evAgg1, evAlpha, evEnd;
    if (!sA) {
        cudaStreamCreateWithFlags(&sA, cudaStreamNonBlocking);
        cudaStreamCreateWithFlags(&sB, cudaStreamNonBlocking);
        cudaEventCreateWithFlags(&evFork,   cudaEventDisableTiming);
        cudaEventCreateWithFlags(&evConsts, cudaEventDisableTiming);
        cudaEventCreateWithFlags(&evNode1,  cudaEventDisableTiming);
        cudaEventCreateWithFlags(&evAgg1,   cudaEventDisableTiming);
        cudaEventCreateWithFlags(&evAlpha,  cudaEventDisableTiming);
        cudaEventCreateWithFlags(&evEnd,    cudaEventDisableTiming);
    }

    // fork from the harness's (captured) stream
    cudaEventRecord(evFork, 0);
    cudaStreamWaitEvent(sA, evFork, 0);
    cudaStreamWaitEvent(sB, evFork, 0);

    // stream B: easum -> consts -> node1 -> edge_index_full (all independent of CSR)
    k_easum <<<1024, 256, 0, sB>>>(ea);
    k_consts<<<1, 128, 0, sB>>>(We1, ae1, We2, ae2);
    cudaEventRecord(evConsts, sB);
    k_node1 <<<592, 256, 0, sB>>>(x, W1, as1, ad1);
    cudaEventRecord(evNode1, sB);
    k_eif   <<<(EF + 255) / 256, 256, 0, sB>>>(ei, out);

    // stream A: CSR build -> fused aggregate+layer2 -> agg2 -> head
    k_init  <<<256, 256, 0, sA>>>();
    k_hist  <<<(Ee + 255) / 256, 256, 0, sA>>>(ei);
    k_scan  <<<1, 1024, 0, sA>>>();
    cudaStreamWaitEvent(sA, evConsts, 0);               // eamean
    k_scatter<<<(EF + 255) / 256, 256, 0, sA>>>(ei, ea);
    cudaStreamWaitEvent(sA, evNode1, 0);                // h1, ss1, sd1
    k_agg1f <<<1184, 256, 0, sA>>>(W2, b1, as2, ad2);
    cudaEventRecord(evAgg1, sA);

    // stream B: alpha writer overlaps agg2 (disjoint data)
    cudaStreamWaitEvent(sB, evAgg1, 0);                 // denominators
    k_alphaE<<<(EF + 255) / 256, 256, 0, sB>>>(ei, ea, out);
    cudaEventRecord(evAlpha, sB);

    k_agg2  <<<1184, 256, 0, sA>>>(b2, Wa, ba);
    k_head  <<<1, 1024, 0, sA>>>(cash, sidx, Wc, bc, ns, out);
    cudaEventRecord(evEnd, sA);

    // join both streams back into the harness stream
    cudaStreamWaitEvent(0, evEnd, 0);
    cudaStreamWaitEvent(0, evAlpha, 0);
}

// round 8
// speedup vs baseline: 2.0798x; 1.1025x over previous
#include <cuda_runtime.h>
#include <cuda_fp16.h>
#include <math.h>

// ---------------- problem constants ----------------
#define Nn    50000
#define Ee    1600000
#define EF    1650000          // E + N self loops
#define INF_  3.402823466e38f

// output layout (float32, flattened in return order)
#define W_OFF  0               // weights [25001]
#define V_OFF  25001           // value   [1]
#define EI_OFF 25002           // edge_index_full [2, EF]
#define A1_OFF (25002 + 2*EF)  // alpha1 [EF, 4]  (8B-aligned only!)

// ---------------- device scratch ----------------
__device__ __align__(16) __half2 g_h1h[Nn*64];   // layer1 features, fp16 pairs (128 ch)
__device__ __align__(16) float g_ss1 [Nn*4];     // s_src1
__device__ __align__(16) float g_sdd1[Nn*8];     // [sd1(4) | den1(4)] per node
__device__ __align__(16) __half  g_h2h[Nn*32];   // layer2 features, fp16 (32 ch)
__device__ float g_ss2[Nn], g_sd2[Nn];
__device__ float g_scores[Nn];
__device__ float g_gsum[32];
__device__ float g_easum, g_eamean;
__device__ float g_c1[4], g_c2;
// CSR-by-dst structures
__device__ __align__(16) int  g_cnt[Nn];
__device__ __align__(16) int  g_off[Nn + 4];
__device__ __align__(16) int  g_pos[Nn];
__device__ __align__(16) int2 g_sa [EF];         // (src, bitcast(edge_attr)) in CSR order

// ---------------- helpers ----------------
__device__ __forceinline__ float wredsum(float v) {
#pragma unroll
    for (int o = 16; o; o >>= 1) v += __shfl_xor_sync(0xffffffffu, v, o);
    return v;
}
__device__ __forceinline__ float wredmax(float v) {
#pragma unroll
    for (int o = 16; o; o >>= 1) v = fmaxf(v, __shfl_xor_sync(0xffffffffu, v, o));
    return v;
}
__device__ __forceinline__ float lrelu(float x) { return x >= 0.f ? x : 0.2f * x; }
__device__ __forceinline__ float elu(float x)   { return x > 0.f ? x : expm1f(x); }

// ---------------- kernels ----------------
__global__ void k_init() {
    int stride = gridDim.x * blockDim.x;
    int t = blockIdx.x * blockDim.x + threadIdx.x;
    for (int i = t; i < Nn; i += stride) g_cnt[i] = 1;   // self loop pre-counted
    if (t < 32) g_gsum[t] = 0.f;
    if (t == 0) g_easum = 0.f;
}

__global__ void k_easum(const float* __restrict__ ea) {
    float s = 0.f;
    for (int i = blockIdx.x * blockDim.x + threadIdx.x; i < Ee; i += gridDim.x * blockDim.x)
        s += ea[i];
    s = wredsum(s);
    __shared__ float sm[8];
    int lane = threadIdx.x & 31, w = threadIdx.x >> 5;
    if (lane == 0) sm[w] = s;
    __syncthreads();
    if (threadIdx.x == 0) {
        float b = 0.f;
        for (int i = 0; i < (int)(blockDim.x >> 5); i++) b += sm[i];
        atomicAdd(&g_easum, b);
    }
}

__global__ void k_consts(const float* __restrict__ We1, const float* __restrict__ ae1,
                         const float* __restrict__ We2, const float* __restrict__ ae2) {
    int t = threadIdx.x;            // 128 threads
    float p = We1[t] * ae1[t];
    p = wredsum(p);
    if ((t & 31) == 0) g_c1[t >> 5] = p;
    if (t < 32) {
        float q = We2[t] * ae2[t];
        q = wredsum(q);
        if (t == 0) { g_c2 = q; g_eamean = g_easum * (1.0f / Ee); }
    }
}

// emit edge_index_full output (depends only on ei) — runs on side stream
__global__ void k_eif(const int* __restrict__ ei, float* __restrict__ out) {
    int e = blockIdx.x * blockDim.x + threadIdx.x;
    if (e >= EF) return;
    int s, d;
    if (e < Ee) { s = ei[e]; d = ei[Ee + e]; }
    else        { s = e - Ee; d = s; }
    out[EI_OFF + e]      = (float)s;
    out[EI_OFF + EF + e] = (float)d;
}

// histogram of dst over real edges only (self loops pre-counted in init)
__global__ void k_hist(const int* __restrict__ ei) {
    int e = blockIdx.x * blockDim.x + threadIdx.x;
    if (e >= Ee) return;
    atomicAdd(&g_cnt[ei[Ee + e]], 1);
}

// single-block exclusive scan of g_cnt -> g_off, g_pos (int4 vectorized, 13 iters)
__global__ void k_scan() {
    __shared__ int wsum[32];
    int t = threadIdx.x, lane = t & 31, w = t >> 5;
    int carry = 0;
    const int4* cnt4 = (const int4*)g_cnt;
    int4* off4 = (int4*)g_off;
    int4* pos4 = (int4*)g_pos;
    const int M4 = Nn / 4;                 // 12500
    for (int base = 0; base < M4; base += 1024) {
        int idx = base + t;
        int4 v = (idx < M4) ? cnt4[idx] : make_int4(0, 0, 0, 0);
        int tsum = v.x + v.y + v.z + v.w;
        int val = tsum;
#pragma unroll
        for (int o = 1; o < 32; o <<= 1) { int x = __shfl_up_sync(0xffffffffu, val, o); if (lane >= o) val += x; }
        if (lane == 31) wsum[w] = val;
        __syncthreads();
        if (w == 0) {
            int b = wsum[lane];
#pragma unroll
            for (int o = 1; o < 32; o <<= 1) { int x = __shfl_up_sync(0xffffffffu, b, o); if (lane >= o) b += x; }
            wsum[lane] = b;
        }
        __syncthreads();
        int add = (w > 0) ? wsum[w - 1] : 0;
        int excl = carry + add + val - tsum;
        if (idx < M4) {
            int4 o;
            o.x = excl; o.y = excl + v.x; o.z = o.y + v.y; o.w = o.z + v.z;
            off4[idx] = o; pos4[idx] = o;
        }
        carry += wsum[31];
        __syncthreads();
    }
    if (t == 0) g_off[Nn] = carry;
}

// scatter edges into CSR order as (src, edge_attr) pairs
__global__ void k_scatter(const int* __restrict__ ei, const float* __restrict__ ea) {
    int e = blockIdx.x * blockDim.x + threadIdx.x;
    if (e >= EF) return;
    int s, d; float a;
    if (e < Ee) { s = ei[e]; d = ei[Ee + e]; a = ea[e]; }
    else        { s = e - Ee; d = s; a = g_eamean; }
    int p = atomicAdd(&g_pos[d], 1);
    g_sa[p] = make_int2(s, __float_as_int(a));
}

// layer-1 projection + attention scores: grid-stride, warp per node.
// Lane owns channels [4*lane, 4*lane+4) (matches agg1f layout); emits packed
// half2 pairs with a single 8B store. Per-head scores via 8-lane reductions.
__global__ void k_node1(const float* __restrict__ x, const float* __restrict__ W1,
                        const float* __restrict__ as1, const float* __restrict__ ad1) {
    __shared__ float W1s[5*128];
    __shared__ float s_as[128], s_ad[128];
    int t = threadIdx.x;
    for (int i = t; i < 640; i += 256) W1s[i] = W1[i];
    if (t < 128) { s_as[t] = as1[t]; s_ad[t] = ad1[t]; }
    __syncthreads();
    int lane = t & 31;
    int warp = (blockIdx.x * blockDim.x + t) >> 5;
    int nwarps = (gridDim.x * blockDim.x) >> 5;
    for (int n = warp; n < Nn; n += nwarps) {
        float x0 = x[n*5+0], x1 = x[n*5+1], x2 = x[n*5+2], x3 = x[n*5+3], x4 = x[n*5+4];
        float av[4];
        float ps = 0.f, pd = 0.f;
#pragma unroll
        for (int j = 0; j < 4; j++) {
            int ch = lane*4 + j;
            float acc = x0*W1s[ch] + x1*W1s[128+ch] + x2*W1s[256+ch] + x3*W1s[384+ch] + x4*W1s[512+ch];
            av[j] = acc;
            ps += acc * s_as[ch];
            pd += acc * s_ad[ch];
        }
        __half2 p0 = __floats2half2_rn(av[0], av[1]);
        __half2 p1 = __floats2half2_rn(av[2], av[3]);
        uint2 u = make_uint2(*reinterpret_cast<unsigned*>(&p0),
                             *reinterpret_cast<unsigned*>(&p1));
        ((uint2*)g_h1h)[n*32 + lane] = u;
        // reduce within 8-lane head groups
#pragma unroll
        for (int o = 1; o < 8; o <<= 1) {
            ps += __shfl_xor_sync(0xffffffffu, ps, o);
            pd += __shfl_xor_sync(0xffffffffu, pd, o);
        }
        if ((lane & 7) == 0) {
            int h = lane >> 3;
            g_ss1[n*4 + h] = ps;
            g_sdd1[n*8 + h] = pd;
        }
    }
}

// FUSED layer-1 aggregation + layer-2 projection: warp per node, unroll x4.
// fp16 h1 gathers (8B/lane/edge). Per-lane single-head exp. Epilogue does the
// 128x32 W2 projection from registers; h2 stored as fp16.
__global__ void k_agg1f(const float* __restrict__ W2, const float* __restrict__ b1,
                        const float* __restrict__ as2, const float* __restrict__ ad2) {
    __shared__ float W2s[128*32];
    __shared__ float hs[8][128];
    int t = threadIdx.x, lane = t & 31, w = t >> 5;
    for (int i = t; i < 4096; i += 256) W2s[i] = W2[i];
    __syncthreads();
    int warp = (blockIdx.x * blockDim.x + t) >> 5;
    int nwarps = (gridDim.x * blockDim.x) >> 5;
    int h = lane >> 3;                       // this lane's head (4 channels each)
    float ch = g_c1[h];
    float4 bb = ((const float4*)b1)[lane];
    float asv = as2[lane], adv = ad2[lane];
    for (int d = warp; d < Nn; d += nwarps) {
        int beg = g_off[d], end = g_off[d+1];
        float sdh = g_sdd1[d*8 + h];
        float4 acc = make_float4(0.f, 0.f, 0.f, 0.f);
        float den = 0.f;
        int i = beg;
        for (; i + 3 < end; i += 4) {
            int2 p0 = g_sa[i], p1 = g_sa[i+1], p2 = g_sa[i+2], p3 = g_sa[i+3];
            float sa0 = g_ss1[p0.x*4 + h];
            float sa1 = g_ss1[p1.x*4 + h];
            float sa2 = g_ss1[p2.x*4 + h];
            float sa3 = g_ss1[p3.x*4 + h];
            uint2 q0 = ((const uint2*)g_h1h)[p0.x*32 + lane];
            uint2 q1 = ((const uint2*)g_h1h)[p1.x*32 + lane];
            uint2 q2 = ((const uint2*)g_h1h)[p2.x*32 + lane];
            uint2 q3 = ((const uint2*)g_h1h)[p3.x*32 + lane];
            float n0 = __expf(lrelu(sa0 + sdh + __int_as_float(p0.y)*ch));
            float n1 = __expf(lrelu(sa1 + sdh + __int_as_float(p1.y)*ch));
            float n2 = __expf(lrelu(sa2 + sdh + __int_as_float(p2.y)*ch));
            float n3 = __expf(lrelu(sa3 + sdh + __int_as_float(p3.y)*ch));
            den += (n0 + n1) + (n2 + n3);
            float2 a0 = __half22float2(*(__half2*)&q0.x), b0 = __half22float2(*(__half2*)&q0.y);
            float2 a1 = __half22float2(*(__half2*)&q1.x), b1v = __half22float2(*(__half2*)&q1.y);
            float2 a2 = __half22float2(*(__half2*)&q2.x), b2v = __half22float2(*(__half2*)&q2.y);
            float2 a3 = __half22float2(*(__half2*)&q3.x), b3v = __half22float2(*(__half2*)&q3.y);
            acc.x += n0*a0.x + n1*a1.x + n2*a2.x + n3*a3.x;
            acc.y += n0*a0.y + n1*a1.y + n2*a2.y + n3*a3.y;
            acc.z += n0*b0.x + n1*b1v.x + n2*b2v.x + n3*b3v.x;
            acc.w += n0*b0.y + n1*b1v.y + n2*b2v.y + n3*b3v.y;
        }
        for (; i < end; i++) {
            int2 p0 = g_sa[i];
            float sa0 = g_ss1[p0.x*4 + h];
            uint2 q0 = ((const uint2*)g_h1h)[p0.x*32 + lane];
            float n0 = __expf(lrelu(sa0 + sdh + __int_as_float(p0.y)*ch));
            den += n0;
            float2 a0 = __half22float2(*(__half2*)&q0.x), b0 = __half22float2(*(__half2*)&q0.y);
            acc.x += n0*a0.x; acc.y += n0*a0.y; acc.z += n0*b0.x; acc.w += n0*b0.y;
        }
        float d0 = __shfl_sync(0xffffffffu, den, 0);
        float d1 = __shfl_sync(0xffffffffu, den, 8);
        float d2 = __shfl_sync(0xffffffffu, den, 16);
        float d3 = __shfl_sync(0xffffffffu, den, 24);
        if (lane == 0)
            ((float4*)g_sdd1)[d*2 + 1] = make_float4(d0, d1, d2, d3);
        float invh = 1.0f / (den + 1e-16f);
        // ---- fused layer-2 projection epilogue ----
        hs[w][lane*4+0] = elu(acc.x*invh + bb.x);
        hs[w][lane*4+1] = elu(acc.y*invh + bb.y);
        hs[w][lane*4+2] = elu(acc.z*invh + bb.z);
        hs[w][lane*4+3] = elu(acc.w*invh + bb.w);
        __syncwarp();
        float acc2 = 0.f;
#pragma unroll 16
        for (int j = 0; j < 128; j++)
            acc2 += hs[w][j] * W2s[j*32 + lane];
        g_h2h[d*32 + lane] = __float2half_rn(acc2);
        float ps = wredsum(acc2 * asv);
        float pd = wredsum(acc2 * adv);
        if (lane == 0) { g_ss2[d] = ps; g_sd2[d] = pd; }
        __syncwarp();
    }
}

// edge-parallel alpha1 writer: original edge order -> coalesced output stores
__global__ void k_alphaE(const int* __restrict__ ei, const float* __restrict__ ea,
                         float* __restrict__ out) {
    int e = blockIdx.x * blockDim.x + threadIdx.x;
    if (e >= EF) return;
    int s, d; float a;
    if (e < Ee) { s = ei[e]; d = ei[Ee + e]; a = ea[e]; }
    else        { s = e - Ee; d = s; a = g_eamean; }
    float4 ss = ((const float4*)g_ss1)[s];
    float4 sd = ((const float4*)g_sdd1)[d*2];
    float4 dd = ((const float4*)g_sdd1)[d*2 + 1];
    float n0 = __expf(lrelu(ss.x + sd.x + a*g_c1[0])) / (dd.x + 1e-16f);
    float n1 = __expf(lrelu(ss.y + sd.y + a*g_c1[1])) / (dd.y + 1e-16f);
    float n2 = __expf(lrelu(ss.z + sd.z + a*g_c1[2])) / (dd.z + 1e-16f);
    float n3 = __expf(lrelu(ss.w + sd.w + a*g_c1[3])) / (dd.w + 1e-16f);
    float2* ao = (float2*)(out + A1_OFF + 4*e);
    ao[0] = make_float2(n0, n1);
    ao[1] = make_float2(n2, n3);
}

// layer-2 aggregation + final node head, fused: warp per node, unroll x4 (fp16 h2)
__global__ void k_agg2(const float* __restrict__ b2, const float* __restrict__ Wa,
                       const float* __restrict__ ba) {
    __shared__ float sacc[32];
    int t = threadIdx.x, lane = t & 31;
    if (t < 32) sacc[t] = 0.f;
    __syncthreads();
    int warp = (blockIdx.x * blockDim.x + t) >> 5;
    int nwarps = (gridDim.x * blockDim.x) >> 5;
    float c = g_c2;
    float bl = b2[lane], wl = Wa[lane], bb = ba[0];
    float gacc = 0.f;
    for (int d = warp; d < Nn; d += nwarps) {
        int beg = g_off[d], end = g_off[d+1];
        float sdv = g_sd2[d];
        float acc = 0.f, den = 0.f;
        int i = beg;
        for (; i + 3 < end; i += 4) {
            int2 p0 = g_sa[i], p1 = g_sa[i+1], p2 = g_sa[i+2], p3 = g_sa[i+3];
            float ss0 = g_ss2[p0.x], ss1v = g_ss2[p1.x];
            float ss2v = g_ss2[p2.x], ss3v = g_ss2[p3.x];
            float v0 = __half2float(g_h2h[p0.x*32 + lane]);
            float v1 = __half2float(g_h2h[p1.x*32 + lane]);
            float v2 = __half2float(g_h2h[p2.x*32 + lane]);
            float v3 = __half2float(g_h2h[p3.x*32 + lane]);
            float n0 = __expf(lrelu(ss0  + sdv + __int_as_float(p0.y)*c));
            float n1 = __expf(lrelu(ss1v + sdv + __int_as_float(p1.y)*c));
            float n2 = __expf(lrelu(ss2v + sdv + __int_as_float(p2.y)*c));
            float n3 = __expf(lrelu(ss3v + sdv + __int_as_float(p3.y)*c));
            den += (n0 + n1) + (n2 + n3);
            acc += n0*v0 + n1*v1 + n2*v2 + n3*v3;
        }
        for (; i < end; i++) {
            int2 p0 = g_sa[i];
            float n0 = __expf(lrelu(g_ss2[p0.x] + sdv + __int_as_float(p0.y)*c));
            den += n0;
            acc += n0 * __half2float(g_h2h[p0.x*32 + lane]);
        }
        float v = elu(acc / (den + 1e-16f) + bl);
        gacc += v;
        float p = wredsum(v * wl);
        if (lane == 0) g_scores[d] = p + bb;
    }
    atomicAdd(&sacc[lane], gacc);
    __syncthreads();
    if (t < 32) atomicAdd(&g_gsum[t], sacc[t]);
}

// softmax over [cash, scores[stock_idx]] + critic value
__global__ void k_head(const float* __restrict__ cash, const int* __restrict__ stock_idx,
                       const float* __restrict__ Wc, const float* __restrict__ bc,
                       int ns, float* __restrict__ out) {
    if (threadIdx.x < 32) {
        float p = wredsum(g_gsum[threadIdx.x] * (1.0f / Nn) * Wc[threadIdx.x]);
        if (threadIdx.x == 0) out[V_OFF] = p + bc[0];
    }
    __shared__ float sm[32];
    __shared__ float bM, bS;
    int t = threadIdx.x, lane = t & 31, w = t >> 5, nw = blockDim.x >> 5;
    int total = ns + 1;
    float m = -INF_;
    for (int i = t; i < total; i += blockDim.x) {
        float v = (i == 0) ? cash[0] : g_scores[stock_idx[i-1]];
        m = fmaxf(m, v);
    }
    m = wredmax(m);
    if (lane == 0) sm[w] = m;
    __syncthreads();
    if (w == 0) {
        float v = (lane < nw) ? sm[lane] : -INF_;
        v = wredmax(v);
        if (lane == 0) bM = v;
    }
    __syncthreads();
    float M = bM;
    float s = 0.f;
    for (int i = t; i < total; i += blockDim.x) {
        float v = (i == 0) ? cash[0] : g_scores[stock_idx[i-1]];
        s += __expf(v - M);
    }
    s = wredsum(s);
    __syncthreads();
    if (lane == 0) sm[w] = s;
    __syncthreads();
    if (w == 0) {
        float v = (lane < nw) ? sm[lane] : 0.f;
        v = wredsum(v);
        if (lane == 0) bS = v;
    }
    __syncthreads();
    float inv = 1.0f / bS;
    for (int i = t; i < total; i += blockDim.x) {
        float v = (i == 0) ? cash[0] : g_scores[stock_idx[i-1]];
        out[W_OFF + i] = __expf(v - M) * inv;
    }
}

// ---------------- launch ----------------
extern "C" void kernel_launch(void* const* d_in, const int* in_sizes, int n_in,
                              void* d_out, int out_size) {
    const float* x    = (const float*)d_in[0];
    const float* ea   = (const float*)d_in[1];
    const float* W1   = (const float*)d_in[2];
    const float* as1  = (const float*)d_in[3];
    const float* ad1  = (const float*)d_in[4];
    const float* We1  = (const float*)d_in[5];
    const float* ae1  = (const float*)d_in[6];
    const float* b1   = (const float*)d_in[7];
    const float* W2   = (const float*)d_in[8];
    const float* as2  = (const float*)d_in[9];
    const float* ad2  = (const float*)d_in[10];
    const float* We2  = (const float*)d_in[11];
    const float* ae2  = (const float*)d_in[12];
    const float* b2   = (const float*)d_in[13];
    const float* Wa   = (const float*)d_in[14];
    const float* ba   = (const float*)d_in[15];
    const float* cash = (const float*)d_in[16];
    const float* Wc   = (const float*)d_in[17];
    const float* bc   = (const float*)d_in[18];
    const int*   ei   = (const int*)  d_in[19];
    const int*   sidx = (const int*)  d_in[20];
    float* out = (float*)d_out;
    int ns = in_sizes[20];

    // lazy one-time stream/event setup (host-side objects only; no device mem)
    static cudaStream_t sA = nullptr, sB = nullptr;
    static cudaEvent_t evFork, evConsts, evNode1, evAgg1, evAlpha, evEnd;
    if (!sA) {
        cudaStreamCreateWithFlags(&sA, cudaStreamNonBlocking);
        cudaStreamCreateWithFlags(&sB, cudaStreamNonBlocking);
        cudaEventCreateWithFlags(&evFork,   cudaEventDisableTiming);
        cudaEventCreateWithFlags(&evConsts, cudaEventDisableTiming);
        cudaEventCreateWithFlags(&evNode1,  cudaEventDisableTiming);
        cudaEventCreateWithFlags(&evAgg1,   cudaEventDisableTiming);
        cudaEventCreateWithFlags(&evAlpha,  cudaEventDisableTiming);
        cudaEventCreateWithFlags(&evEnd,    cudaEventDisableTiming);
    }

    // fork from the harness's (captured) stream
    cudaEventRecord(evFork, 0);
    cudaStreamWaitEvent(sA, evFork, 0);
    cudaStreamWaitEvent(sB, evFork, 0);

    // stream B: easum -> consts -> node1 -> edge_index_full (all independent of CSR)
    k_easum <<<1024, 256, 0, sB>>>(ea);
    k_consts<<<1, 128, 0, sB>>>(We1, ae1, We2, ae2);
    cudaEventRecord(evConsts, sB);
    k_node1 <<<592, 256, 0, sB>>>(x, W1, as1, ad1);
    cudaEventRecord(evNode1, sB);
    k_eif   <<<(EF + 255) / 256, 256, 0, sB>>>(ei, out);

    // stream A: CSR build -> fused aggregate+layer2 -> agg2 -> head
    k_init  <<<256, 256, 0, sA>>>();
    k_hist  <<<(Ee + 255) / 256, 256, 0, sA>>>(ei);
    k_scan  <<<1, 1024, 0, sA>>>();
    cudaStreamWaitEvent(sA, evConsts, 0);               // eamean
    k_scatter<<<(EF + 255) / 256, 256, 0, sA>>>(ei, ea);
    cudaStreamWaitEvent(sA, evNode1, 0);                // h1, ss1, sd1
    k_agg1f <<<1184, 256, 0, sA>>>(W2, b1, as2, ad2);
    cudaEventRecord(evAgg1, sA);

    // stream B: alpha writer overlaps agg2 (disjoint data)
    cudaStreamWaitEvent(sB, evAgg1, 0);                 // denominators
    k_alphaE<<<(EF + 255) / 256, 256, 0, sB>>>(ei, ea, out);
    cudaEventRecord(evAlpha, sB);

    k_agg2  <<<1184, 256, 0, sA>>>(b2, Wa, ba);
    k_head  <<<1, 1024, 0, sA>>>(cash, sidx, Wc, bc, ns, out);
    cudaEventRecord(evEnd, sA);

    // join both streams back into the harness stream
    cudaStreamWaitEvent(0, evEnd, 0);
    cudaStreamWaitEvent(0, evAlpha, 0);
}

// round 9
// speedup vs baseline: 2.0990x; 1.0092x over previous
#include <cuda_runtime.h>
#include <cuda_fp16.h>
#include <math.h>

// ---------------- problem constants ----------------
#define Nn    50000
#define Ee    1600000
#define EF    1650000          // E + N self loops
#define INF_  3.402823466e38f

// output layout (float32, flattened in return order)
#define W_OFF  0               // weights [25001]
#define V_OFF  25001           // value   [1]
#define EI_OFF 25002           // edge_index_full [2, EF]
#define A1_OFF (25002 + 2*EF)  // alpha1 [EF, 4]  (8B-aligned only!)

// ---------------- device scratch ----------------
__device__ __align__(16) __half2 g_h1h[Nn*64];   // layer1 features, fp16 pairs (128 ch)
__device__ __align__(16) float g_ss1 [Nn*4];     // s_src1
__device__ __align__(16) float g_sdd1[Nn*8];     // [sd1(4) | den1(4)] per node
__device__ __align__(16) __half  g_h2h[Nn*32];   // layer2 features, fp16 (32 ch)
__device__ float g_ss2[Nn], g_sd2[Nn];
__device__ float g_scores[Nn];
__device__ float g_gsum[32];
__device__ float g_easum, g_eamean;
__device__ float g_c1[4], g_c2;
// CSR-by-dst structures (real edges only; self loops handled analytically)
__device__ __align__(16) int g_cnt[Nn];
__device__ __align__(16) int g_off[Nn + 4];
__device__ __align__(16) int g_pos[Nn];
__device__ __align__(16) unsigned g_sa[Ee];      // [fp16 a | uint16 src] per edge

// ---------------- helpers ----------------
__device__ __forceinline__ float wredsum(float v) {
#pragma unroll
    for (int o = 16; o; o >>= 1) v += __shfl_xor_sync(0xffffffffu, v, o);
    return v;
}
__device__ __forceinline__ float wredmax(float v) {
#pragma unroll
    for (int o = 16; o; o >>= 1) v = fmaxf(v, __shfl_xor_sync(0xffffffffu, v, o));
    return v;
}
__device__ __forceinline__ float lrelu(float x) { return x >= 0.f ? x : 0.2f * x; }
__device__ __forceinline__ float elu(float x)   { return x > 0.f ? x : expm1f(x); }
__device__ __forceinline__ int   sa_src(unsigned q) { return (int)(q & 0xFFFFu); }
__device__ __forceinline__ float sa_a(unsigned q) {
    return __half2float(__ushort_as_half((unsigned short)(q >> 16)));
}

// ---------------- kernels ----------------
__global__ void k_init() {
    int stride = gridDim.x * blockDim.x;
    int t = blockIdx.x * blockDim.x + threadIdx.x;
    for (int i = t; i < Nn; i += stride) g_cnt[i] = 0;
    if (t < 32) g_gsum[t] = 0.f;
    if (t == 0) g_easum = 0.f;
}

__global__ void k_easum(const float* __restrict__ ea) {
    float s = 0.f;
    for (int i = blockIdx.x * blockDim.x + threadIdx.x; i < Ee; i += gridDim.x * blockDim.x)
        s += ea[i];
    s = wredsum(s);
    __shared__ float sm[8];
    int lane = threadIdx.x & 31, w = threadIdx.x >> 5;
    if (lane == 0) sm[w] = s;
    __syncthreads();
    if (threadIdx.x == 0) {
        float b = 0.f;
        for (int i = 0; i < (int)(blockDim.x >> 5); i++) b += sm[i];
        atomicAdd(&g_easum, b);
    }
}

__global__ void k_consts(const float* __restrict__ We1, const float* __restrict__ ae1,
                         const float* __restrict__ We2, const float* __restrict__ ae2) {
    int t = threadIdx.x;            // 128 threads
    float p = We1[t] * ae1[t];
    p = wredsum(p);
    if ((t & 31) == 0) g_c1[t >> 5] = p;
    if (t < 32) {
        float q = We2[t] * ae2[t];
        q = wredsum(q);
        if (t == 0) { g_c2 = q; g_eamean = g_easum * (1.0f / Ee); }
    }
}

// emit edge_index_full output (depends only on ei) — runs on side stream
__global__ void k_eif(const int* __restrict__ ei, float* __restrict__ out) {
    int e = blockIdx.x * blockDim.x + threadIdx.x;
    if (e >= EF) return;
    int s, d;
    if (e < Ee) { s = ei[e]; d = ei[Ee + e]; }
    else        { s = e - Ee; d = s; }
    out[EI_OFF + e]      = (float)s;
    out[EI_OFF + EF + e] = (float)d;
}

// histogram of dst over real edges
__global__ void k_hist(const int* __restrict__ ei) {
    int e = blockIdx.x * blockDim.x + threadIdx.x;
    if (e >= Ee) return;
    atomicAdd(&g_cnt[ei[Ee + e]], 1);
}

// single-block exclusive scan of g_cnt -> g_off, g_pos (int4 vectorized, 13 iters)
__global__ void k_scan() {
    __shared__ int wsum[32];
    int t = threadIdx.x, lane = t & 31, w = t >> 5;
    int carry = 0;
    const int4* cnt4 = (const int4*)g_cnt;
    int4* off4 = (int4*)g_off;
    int4* pos4 = (int4*)g_pos;
    const int M4 = Nn / 4;                 // 12500
    for (int base = 0; base < M4; base += 1024) {
        int idx = base + t;
        int4 v = (idx < M4) ? cnt4[idx] : make_int4(0, 0, 0, 0);
        int tsum = v.x + v.y + v.z + v.w;
        int val = tsum;
#pragma unroll
        for (int o = 1; o < 32; o <<= 1) { int x = __shfl_up_sync(0xffffffffu, val, o); if (lane >= o) val += x; }
        if (lane == 31) wsum[w] = val;
        __syncthreads();
        if (w == 0) {
            int b = wsum[lane];
#pragma unroll
            for (int o = 1; o < 32; o <<= 1) { int x = __shfl_up_sync(0xffffffffu, b, o); if (lane >= o) b += x; }
            wsum[lane] = b;
        }
        __syncthreads();
        int add = (w > 0) ? wsum[w - 1] : 0;
        int excl = carry + add + val - tsum;
        if (idx < M4) {
            int4 o;
            o.x = excl; o.y = excl + v.x; o.z = o.y + v.y; o.w = o.z + v.z;
            off4[idx] = o; pos4[idx] = o;
        }
        carry += wsum[31];
        __syncthreads();
    }
    if (t == 0) g_off[Nn] = carry;
}

// scatter real edges into CSR order as packed (fp16 a | uint16 src)
__global__ void k_scatter(const int* __restrict__ ei, const float* __restrict__ ea) {
    int e = blockIdx.x * blockDim.x + threadIdx.x;
    if (e >= Ee) return;
    int s = ei[e], d = ei[Ee + e];
    unsigned ah = (unsigned)__half_as_ushort(__float2half_rn(ea[e]));
    int p = atomicAdd(&g_pos[d], 1);
    g_sa[p] = (unsigned)s | (ah << 16);
}

// layer-1 projection + attention scores: grid-stride, warp per node.
// Lane owns channels [4*lane, 4*lane+4); emits packed half2 pairs (8B store).
__global__ void k_node1(const float* __restrict__ x, const float* __restrict__ W1,
                        const float* __restrict__ as1, const float* __restrict__ ad1) {
    __shared__ float W1s[5*128];
    __shared__ float s_as[128], s_ad[128];
    int t = threadIdx.x;
    for (int i = t; i < 640; i += 256) W1s[i] = W1[i];
    if (t < 128) { s_as[t] = as1[t]; s_ad[t] = ad1[t]; }
    __syncthreads();
    int lane = t & 31;
    int warp = (blockIdx.x * blockDim.x + t) >> 5;
    int nwarps = (gridDim.x * blockDim.x) >> 5;
    for (int n = warp; n < Nn; n += nwarps) {
        float x0 = x[n*5+0], x1 = x[n*5+1], x2 = x[n*5+2], x3 = x[n*5+3], x4 = x[n*5+4];
        float av[4];
        float ps = 0.f, pd = 0.f;
#pragma unroll
        for (int j = 0; j < 4; j++) {
            int ch = lane*4 + j;
            float acc = x0*W1s[ch] + x1*W1s[128+ch] + x2*W1s[256+ch] + x3*W1s[384+ch] + x4*W1s[512+ch];
            av[j] = acc;
            ps += acc * s_as[ch];
            pd += acc * s_ad[ch];
        }
        __half2 p0 = __floats2half2_rn(av[0], av[1]);
        __half2 p1 = __floats2half2_rn(av[2], av[3]);
        uint2 u = make_uint2(*reinterpret_cast<unsigned*>(&p0),
                             *reinterpret_cast<unsigned*>(&p1));
        ((uint2*)g_h1h)[n*32 + lane] = u;
#pragma unroll
        for (int o = 1; o < 8; o <<= 1) {
            ps += __shfl_xor_sync(0xffffffffu, ps, o);
            pd += __shfl_xor_sync(0xffffffffu, pd, o);
        }
        if ((lane & 7) == 0) {
            int h = lane >> 3;
            g_ss1[n*4 + h] = ps;
            g_sdd1[n*8 + h] = pd;
        }
    }
}

// FUSED layer-1 aggregation + layer-2 projection: warp per node, unroll x4.
// Real edges from 4B-packed CSR; self loop added analytically (coalesced reads).
__global__ void k_agg1f(const float* __restrict__ W2, const float* __restrict__ b1,
                        const float* __restrict__ as2, const float* __restrict__ ad2) {
    __shared__ float W2s[128*32];
    __shared__ float hs[8][128];
    int t = threadIdx.x, lane = t & 31, w = t >> 5;
    for (int i = t; i < 4096; i += 256) W2s[i] = W2[i];
    __syncthreads();
    int warp = (blockIdx.x * blockDim.x + t) >> 5;
    int nwarps = (gridDim.x * blockDim.x) >> 5;
    int h = lane >> 3;                       // this lane's head (4 channels each)
    float ch = g_c1[h];
    float eam = g_eamean;
    float4 bb = ((const float4*)b1)[lane];
    float asv = as2[lane], adv = ad2[lane];
    for (int d = warp; d < Nn; d += nwarps) {
        int beg = g_off[d], end = g_off[d+1];
        float sdh = g_sdd1[d*8 + h];
        // self loop: src = d, a = eamean (coalesced own-row read)
        float nself = __expf(lrelu(g_ss1[d*4 + h] + sdh + eam*ch));
        uint2 qs = ((const uint2*)g_h1h)[d*32 + lane];
        float2 sa_ = __half22float2(*(__half2*)&qs.x), sb_ = __half22float2(*(__half2*)&qs.y);
        float4 acc = make_float4(nself*sa_.x, nself*sa_.y, nself*sb_.x, nself*sb_.y);
        float den = nself;
        int i = beg;
        for (; i + 3 < end; i += 4) {
            unsigned e0 = g_sa[i], e1 = g_sa[i+1], e2 = g_sa[i+2], e3 = g_sa[i+3];
            int s0 = sa_src(e0), s1 = sa_src(e1), s2 = sa_src(e2), s3 = sa_src(e3);
            float sa0 = g_ss1[s0*4 + h];
            float sa1 = g_ss1[s1*4 + h];
            float sa2 = g_ss1[s2*4 + h];
            float sa3 = g_ss1[s3*4 + h];
            uint2 q0 = ((const uint2*)g_h1h)[s0*32 + lane];
            uint2 q1 = ((const uint2*)g_h1h)[s1*32 + lane];
            uint2 q2 = ((const uint2*)g_h1h)[s2*32 + lane];
            uint2 q3 = ((const uint2*)g_h1h)[s3*32 + lane];
            float n0 = __expf(lrelu(sa0 + sdh + sa_a(e0)*ch));
            float n1 = __expf(lrelu(sa1 + sdh + sa_a(e1)*ch));
            float n2 = __expf(lrelu(sa2 + sdh + sa_a(e2)*ch));
            float n3 = __expf(lrelu(sa3 + sdh + sa_a(e3)*ch));
            den += (n0 + n1) + (n2 + n3);
            float2 a0 = __half22float2(*(__half2*)&q0.x), b0 = __half22float2(*(__half2*)&q0.y);
            float2 a1 = __half22float2(*(__half2*)&q1.x), b1v = __half22float2(*(__half2*)&q1.y);
            float2 a2 = __half22float2(*(__half2*)&q2.x), b2v = __half22float2(*(__half2*)&q2.y);
            float2 a3 = __half22float2(*(__half2*)&q3.x), b3v = __half22float2(*(__half2*)&q3.y);
            acc.x += n0*a0.x + n1*a1.x + n2*a2.x + n3*a3.x;
            acc.y += n0*a0.y + n1*a1.y + n2*a2.y + n3*a3.y;
            acc.z += n0*b0.x + n1*b1v.x + n2*b2v.x + n3*b3v.x;
            acc.w += n0*b0.y + n1*b1v.y + n2*b2v.y + n3*b3v.y;
        }
        for (; i < end; i++) {
            unsigned e0 = g_sa[i];
            int s0 = sa_src(e0);
            float sa0 = g_ss1[s0*4 + h];
            uint2 q0 = ((const uint2*)g_h1h)[s0*32 + lane];
            float n0 = __expf(lrelu(sa0 + sdh + sa_a(e0)*ch));
            den += n0;
            float2 a0 = __half22float2(*(__half2*)&q0.x), b0 = __half22float2(*(__half2*)&q0.y);
            acc.x += n0*a0.x; acc.y += n0*a0.y; acc.z += n0*b0.x; acc.w += n0*b0.y;
        }
        float d0 = __shfl_sync(0xffffffffu, den, 0);
        float d1 = __shfl_sync(0xffffffffu, den, 8);
        float d2 = __shfl_sync(0xffffffffu, den, 16);
        float d3 = __shfl_sync(0xffffffffu, den, 24);
        if (lane == 0)
            ((float4*)g_sdd1)[d*2 + 1] = make_float4(d0, d1, d2, d3);
        float invh = 1.0f / (den + 1e-16f);
        // ---- fused layer-2 projection epilogue ----
        hs[w][lane*4+0] = elu(acc.x*invh + bb.x);
        hs[w][lane*4+1] = elu(acc.y*invh + bb.y);
        hs[w][lane*4+2] = elu(acc.z*invh + bb.z);
        hs[w][lane*4+3] = elu(acc.w*invh + bb.w);
        __syncwarp();
        float acc2 = 0.f;
#pragma unroll 16
        for (int j = 0; j < 128; j++)
            acc2 += hs[w][j] * W2s[j*32 + lane];
        g_h2h[d*32 + lane] = __float2half_rn(acc2);
        float ps = wredsum(acc2 * asv);
        float pd = wredsum(acc2 * adv);
        if (lane == 0) { g_ss2[d] = ps; g_sd2[d] = pd; }
        __syncwarp();
    }
}

// edge-parallel alpha1 writer: original edge order -> coalesced output stores
// (uses fp32 ea directly — alpha precision unaffected by the packed CSR)
__global__ void k_alphaE(const int* __restrict__ ei, const float* __restrict__ ea,
                         float* __restrict__ out) {
    int e = blockIdx.x * blockDim.x + threadIdx.x;
    if (e >= EF) return;
    int s, d; float a;
    if (e < Ee) { s = ei[e]; d = ei[Ee + e]; a = ea[e]; }
    else        { s = e - Ee; d = s; a = g_eamean; }
    float4 ss = ((const float4*)g_ss1)[s];
    float4 sd = ((const float4*)g_sdd1)[d*2];
    float4 dd = ((const float4*)g_sdd1)[d*2 + 1];
    float n0 = __expf(lrelu(ss.x + sd.x + a*g_c1[0])) / (dd.x + 1e-16f);
    float n1 = __expf(lrelu(ss.y + sd.y + a*g_c1[1])) / (dd.y + 1e-16f);
    float n2 = __expf(lrelu(ss.z + sd.z + a*g_c1[2])) / (dd.z + 1e-16f);
    float n3 = __expf(lrelu(ss.w + sd.w + a*g_c1[3])) / (dd.w + 1e-16f);
    float2* ao = (float2*)(out + A1_OFF + 4*e);
    ao[0] = make_float2(n0, n1);
    ao[1] = make_float2(n2, n3);
}

// layer-2 aggregation + final node head: warp per node, unroll x4, analytic self loop
__global__ void k_agg2(const float* __restrict__ b2, const float* __restrict__ Wa,
                       const float* __restrict__ ba) {
    __shared__ float sacc[32];
    int t = threadIdx.x, lane = t & 31;
    if (t < 32) sacc[t] = 0.f;
    __syncthreads();
    int warp = (blockIdx.x * blockDim.x + t) >> 5;
    int nwarps = (gridDim.x * blockDim.x) >> 5;
    float c = g_c2, eam = g_eamean;
    float bl = b2[lane], wl = Wa[lane], bb = ba[0];
    float gacc = 0.f;
    for (int d = warp; d < Nn; d += nwarps) {
        int beg = g_off[d], end = g_off[d+1];
        float sdv = g_sd2[d];
        // self loop
        float nself = __expf(lrelu(g_ss2[d] + sdv + eam*c));
        float acc = nself * __half2float(g_h2h[d*32 + lane]);
        float den = nself;
        int i = beg;
        for (; i + 3 < end; i += 4) {
            unsigned e0 = g_sa[i], e1 = g_sa[i+1], e2 = g_sa[i+2], e3 = g_sa[i+3];
            int s0 = sa_src(e0), s1 = sa_src(e1), s2 = sa_src(e2), s3 = sa_src(e3);
            float ss0 = g_ss2[s0], ss1v = g_ss2[s1];
            float ss2v = g_ss2[s2], ss3v = g_ss2[s3];
            float v0 = __half2float(g_h2h[s0*32 + lane]);
            float v1 = __half2float(g_h2h[s1*32 + lane]);
            float v2 = __half2float(g_h2h[s2*32 + lane]);
            float v3 = __half2float(g_h2h[s3*32 + lane]);
            float n0 = __expf(lrelu(ss0  + sdv + sa_a(e0)*c));
            float n1 = __expf(lrelu(ss1v + sdv + sa_a(e1)*c));
            float n2 = __expf(lrelu(ss2v + sdv + sa_a(e2)*c));
            float n3 = __expf(lrelu(ss3v + sdv + sa_a(e3)*c));
            den += (n0 + n1) + (n2 + n3);
            acc += n0*v0 + n1*v1 + n2*v2 + n3*v3;
        }
        for (; i < end; i++) {
            unsigned e0 = g_sa[i];
            int s0 = sa_src(e0);
            float n0 = __expf(lrelu(g_ss2[s0] + sdv + sa_a(e0)*c));
            den += n0;
            acc += n0 * __half2float(g_h2h[s0*32 + lane]);
        }
        float v = elu(acc / (den + 1e-16f) + bl);
        gacc += v;
        float p = wredsum(v * wl);
        if (lane == 0) g_scores[d] = p + bb;
    }
    atomicAdd(&sacc[lane], gacc);
    __syncthreads();
    if (t < 32) atomicAdd(&g_gsum[t], sacc[t]);
}

// softmax over [cash, scores[stock_idx]] + critic value
__global__ void k_head(const float* __restrict__ cash, const int* __restrict__ stock_idx,
                       const float* __restrict__ Wc, const float* __restrict__ bc,
                       int ns, float* __restrict__ out) {
    if (threadIdx.x < 32) {
        float p = wredsum(g_gsum[threadIdx.x] * (1.0f / Nn) * Wc[threadIdx.x]);
        if (threadIdx.x == 0) out[V_OFF] = p + bc[0];
    }
    __shared__ float sm[32];
    __shared__ float bM, bS;
    int t = threadIdx.x, lane = t & 31, w = t >> 5, nw = blockDim.x >> 5;
    int total = ns + 1;
    float m = -INF_;
    for (int i = t; i < total; i += blockDim.x) {
        float v = (i == 0) ? cash[0] : g_scores[stock_idx[i-1]];
        m = fmaxf(m, v);
    }
    m = wredmax(m);
    if (lane == 0) sm[w] = m;
    __syncthreads();
    if (w == 0) {
        float v = (lane < nw) ? sm[lane] : -INF_;
        v = wredmax(v);
        if (lane == 0) bM = v;
    }
    __syncthreads();
    float M = bM;
    float s = 0.f;
    for (int i = t; i < total; i += blockDim.x) {
        float v = (i == 0) ? cash[0] : g_scores[stock_idx[i-1]];
        s += __expf(v - M);
    }
    s = wredsum(s);
    __syncthreads();
    if (lane == 0) sm[w] = s;
    __syncthreads();
    if (w == 0) {
        float v = (lane < nw) ? sm[lane] : 0.f;
        v = wredsum(v);
        if (lane == 0) bS = v;
    }
    __syncthreads();
    float inv = 1.0f / bS;
    for (int i = t; i < total; i += blockDim.x) {
        float v = (i == 0) ? cash[0] : g_scores[stock_idx[i-1]];
        out[W_OFF + i] = __expf(v - M) * inv;
    }
}

// ---------------- launch ----------------
extern "C" void kernel_launch(void* const* d_in, const int* in_sizes, int n_in,
                              void* d_out, int out_size) {
    const float* x    = (const float*)d_in[0];
    const float* ea   = (const float*)d_in[1];
    const float* W1   = (const float*)d_in[2];
    const float* as1  = (const float*)d_in[3];
    const float* ad1  = (const float*)d_in[4];
    const float* We1  = (const float*)d_in[5];
    const float* ae1  = (const float*)d_in[6];
    const float* b1   = (const float*)d_in[7];
    const float* W2   = (const float*)d_in[8];
    const float* as2  = (const float*)d_in[9];
    const float* ad2  = (const float*)d_in[10];
    const float* We2  = (const float*)d_in[11];
    const float* ae2  = (const float*)d_in[12];
    const float* b2   = (const float*)d_in[13];
    const float* Wa   = (const float*)d_in[14];
    const float* ba   = (const float*)d_in[15];
    const float* cash = (const float*)d_in[16];
    const float* Wc   = (const float*)d_in[17];
    const float* bc   = (const float*)d_in[18];
    const int*   ei   = (const int*)  d_in[19];
    const int*   sidx = (const int*)  d_in[20];
    float* out = (float*)d_out;
    int ns = in_sizes[20];

    // lazy one-time stream/event setup (host-side objects only; no device mem)
    static cudaStream_t sA = nullptr, sB = nullptr;
    static cudaEvent_t evFork, evNode1, evAgg1, evAlpha, evEnd;
    if (!sA) {
        cudaStreamCreateWithFlags(&sA, cudaStreamNonBlocking);
        cudaStreamCreateWithFlags(&sB, cudaStreamNonBlocking);
        cudaEventCreateWithFlags(&evFork,  cudaEventDisableTiming);
        cudaEventCreateWithFlags(&evNode1, cudaEventDisableTiming);
        cudaEventCreateWithFlags(&evAgg1,  cudaEventDisableTiming);
        cudaEventCreateWithFlags(&evAlpha, cudaEventDisableTiming);
        cudaEventCreateWithFlags(&evEnd,   cudaEventDisableTiming);
    }

    // fork from the harness's (captured) stream
    cudaEventRecord(evFork, 0);
    cudaStreamWaitEvent(sA, evFork, 0);
    cudaStreamWaitEvent(sB, evFork, 0);

    // stream B: easum -> consts -> node1 -> edge_index_full (independent of CSR)
    k_easum <<<1024, 256, 0, sB>>>(ea);
    k_consts<<<1, 128, 0, sB>>>(We1, ae1, We2, ae2);
    k_node1 <<<592, 256, 0, sB>>>(x, W1, as1, ad1);
    cudaEventRecord(evNode1, sB);      // also implies consts (g_c1/g_c2/eamean) done
    k_eif   <<<(EF + 255) / 256, 256, 0, sB>>>(ei, out);

    // stream A: CSR build (real edges only, no consts dependency) -> fused agg -> head
    k_init   <<<256, 256, 0, sA>>>();
    k_hist   <<<(Ee + 255) / 256, 256, 0, sA>>>(ei);
    k_scan   <<<1, 1024, 0, sA>>>();
    k_scatter<<<(Ee + 255) / 256, 256, 0, sA>>>(ei, ea);
    cudaStreamWaitEvent(sA, evNode1, 0);                // h1, ss1, sd1, consts
    k_agg1f  <<<1184, 256, 0, sA>>>(W2, b1, as2, ad2);
    cudaEventRecord(evAgg1, sA);

    // stream B: alpha writer overlaps agg2 (disjoint data)
    cudaStreamWaitEvent(sB, evAgg1, 0);                 // denominators
    k_alphaE<<<(EF + 255) / 256, 256, 0, sB>>>(ei, ea, out);
    cudaEventRecord(evAlpha, sB);

    k_agg2  <<<1184, 256, 0, sA>>>(b2, Wa, ba);
    k_head  <<<1, 1024, 0, sA>>>(cash, sidx, Wc, bc, ns, out);
    cudaEventRecord(evEnd, sA);

    // join both streams back into the harness stream
    cudaStreamWaitEvent(0, evEnd, 0);
    cudaStreamWaitEvent(0, evAlpha, 0);
}

// round 10
// speedup vs baseline: 2.2180x; 1.0567x over previous
#include <cuda_runtime.h>
#include <cuda_fp16.h>
#include <math.h>

// ---------------- problem constants ----------------
#define Nn    50000
#define Ee    1600000
#define EF    1650000          // E + N self loops
#define INF_  3.402823466e38f

// output layout (float32, flattened in return order)
#define W_OFF  0               // weights [25001]
#define V_OFF  25001           // value   [1]
#define EI_OFF 25002           // edge_index_full [2, EF]
#define A1_OFF (25002 + 2*EF)  // alpha1 [EF, 4]  (8B-aligned only!)

// ---------------- device scratch ----------------
// node record: rec[2n] = ss1 (fp32 x4), rec[2n+1] = x (fp16 x5, packed, padded)
__device__ __align__(16) float4 g_rec [Nn*2];
__device__ __align__(16) float  g_sdd1[Nn*8];    // [sd1(4) | den1(4)] per node
__device__ __align__(16) __half g_h2h [Nn*32];   // layer2 features, fp16 (32 ch)
__device__ float g_ss2[Nn], g_sd2[Nn];
__device__ float g_scores[Nn];
__device__ float g_gsum[32];
__device__ float g_easum, g_eamean;
__device__ __align__(16) float g_c1[4];
__device__ float g_c2;
__device__ float g_Ms[20], g_Md[20];             // (5 x 4) score matrices: x @ M = s
// CSR-by-dst structures (real edges only; self loops handled analytically)
__device__ __align__(16) int g_cnt[Nn];
__device__ __align__(16) int g_off[Nn + 4];
__device__ __align__(16) int g_pos[Nn];
__device__ __align__(16) unsigned g_sa[Ee];      // [fp16 a | uint16 src] per edge

// ---------------- helpers ----------------
__device__ __forceinline__ float wredsum(float v) {
#pragma unroll
    for (int o = 16; o; o >>= 1) v += __shfl_xor_sync(0xffffffffu, v, o);
    return v;
}
__device__ __forceinline__ float wredmax(float v) {
#pragma unroll
    for (int o = 16; o; o >>= 1) v = fmaxf(v, __shfl_xor_sync(0xffffffffu, v, o));
    return v;
}
__device__ __forceinline__ float lrelu(float x) { return x >= 0.f ? x : 0.2f * x; }
__device__ __forceinline__ float elu(float x)   { return x > 0.f ? x : expm1f(x); }
__device__ __forceinline__ int   sa_src(unsigned q) { return (int)(q & 0xFFFFu); }
__device__ __forceinline__ float sa_a(unsigned q) {
    return __half2float(__ushort_as_half((unsigned short)(q >> 16)));
}

// ---------------- kernels ----------------
__global__ void k_init() {
    int stride = gridDim.x * blockDim.x;
    int t = blockIdx.x * blockDim.x + threadIdx.x;
    for (int i = t; i < Nn; i += stride) g_cnt[i] = 0;
    if (t < 32) g_gsum[t] = 0.f;
    if (t == 0) g_easum = 0.f;
}

__global__ void k_easum(const float* __restrict__ ea) {
    float s = 0.f;
    for (int i = blockIdx.x * blockDim.x + threadIdx.x; i < Ee; i += gridDim.x * blockDim.x)
        s += ea[i];
    s = wredsum(s);
    __shared__ float sm[8];
    int lane = threadIdx.x & 31, w = threadIdx.x >> 5;
    if (lane == 0) sm[w] = s;
    __syncthreads();
    if (threadIdx.x == 0) {
        float b = 0.f;
        for (int i = 0; i < (int)(blockDim.x >> 5); i++) b += sm[i];
        atomicAdd(&g_easum, b);
    }
}

// consts: c1/c2/eamean + score matrices Ms/Md (5x4) so node1 never needs W1
__global__ void k_consts(const float* __restrict__ W1,
                         const float* __restrict__ as1, const float* __restrict__ ad1,
                         const float* __restrict__ We1, const float* __restrict__ ae1,
                         const float* __restrict__ We2, const float* __restrict__ ae2) {
    int t = threadIdx.x;            // 128 threads; warp == head
    int lane = t & 31, h = t >> 5;
    float p = We1[t] * ae1[t];
    p = wredsum(p);
    if (lane == 0) g_c1[h] = p;
    float asv = as1[t], adv = ad1[t];
#pragma unroll
    for (int k = 0; k < 5; k++) {
        float ms = wredsum(W1[k*128 + t] * asv);
        float md = wredsum(W1[k*128 + t] * adv);
        if (lane == 0) { g_Ms[k*4 + h] = ms; g_Md[k*4 + h] = md; }
    }
    if (t < 32) {
        float q = We2[t] * ae2[t];
        q = wredsum(q);
        if (t == 0) { g_c2 = q; g_eamean = g_easum * (1.0f / Ee); }
    }
}

// emit edge_index_full output (depends only on ei) — runs on side stream
__global__ void k_eif(const int* __restrict__ ei, float* __restrict__ out) {
    int e = blockIdx.x * blockDim.x + threadIdx.x;
    if (e >= EF) return;
    int s, d;
    if (e < Ee) { s = ei[e]; d = ei[Ee + e]; }
    else        { s = e - Ee; d = s; }
    out[EI_OFF + e]      = (float)s;
    out[EI_OFF + EF + e] = (float)d;
}

// histogram of dst over real edges
__global__ void k_hist(const int* __restrict__ ei) {
    int e = blockIdx.x * blockDim.x + threadIdx.x;
    if (e >= Ee) return;
    atomicAdd(&g_cnt[ei[Ee + e]], 1);
}

// single-block exclusive scan of g_cnt -> g_off, g_pos (int4 vectorized, 13 iters)
__global__ void k_scan() {
    __shared__ int wsum[32];
    int t = threadIdx.x, lane = t & 31, w = t >> 5;
    int carry = 0;
    const int4* cnt4 = (const int4*)g_cnt;
    int4* off4 = (int4*)g_off;
    int4* pos4 = (int4*)g_pos;
    const int M4 = Nn / 4;                 // 12500
    for (int base = 0; base < M4; base += 1024) {
        int idx = base + t;
        int4 v = (idx < M4) ? cnt4[idx] : make_int4(0, 0, 0, 0);
        int tsum = v.x + v.y + v.z + v.w;
        int val = tsum;
#pragma unroll
        for (int o = 1; o < 32; o <<= 1) { int x = __shfl_up_sync(0xffffffffu, val, o); if (lane >= o) val += x; }
        if (lane == 31) wsum[w] = val;
        __syncthreads();
        if (w == 0) {
            int b = wsum[lane];
#pragma unroll
            for (int o = 1; o < 32; o <<= 1) { int x = __shfl_up_sync(0xffffffffu, b, o); if (lane >= o) b += x; }
            wsum[lane] = b;
        }
        __syncthreads();
        int add = (w > 0) ? wsum[w - 1] : 0;
        int excl = carry + add + val - tsum;
        if (idx < M4) {
            int4 o;
            o.x = excl; o.y = excl + v.x; o.z = o.y + v.y; o.w = o.z + v.z;
            off4[idx] = o; pos4[idx] = o;
        }
        carry += wsum[31];
        __syncthreads();
    }
    if (t == 0) g_off[Nn] = carry;
}

// scatter real edges into CSR order as packed (fp16 a | uint16 src)
__global__ void k_scatter(const int* __restrict__ ei, const float* __restrict__ ea) {
    int e = blockIdx.x * blockDim.x + threadIdx.x;
    if (e >= Ee) return;
    int s = ei[e], d = ei[Ee + e];
    unsigned ah = (unsigned)__half_as_ushort(__float2half_rn(ea[e]));
    int p = atomicAdd(&g_pos[d], 1);
    g_sa[p] = (unsigned)s | (ah << 16);
}

// node prep: thread per node. ss1/sd1 = x @ Ms/Md (5x4). Writes the packed
// node record [ss1 fp32 | x fp16] and sd1. h1 is NEVER materialized.
__global__ void k_node1(const float* __restrict__ x) {
    __shared__ float Ms[20], Md[20];
    int t = threadIdx.x;
    if (t < 20) { Ms[t] = g_Ms[t]; Md[t] = g_Md[t]; }
    __syncthreads();
    int stride = gridDim.x * blockDim.x;
    for (int n = blockIdx.x * blockDim.x + t; n < Nn; n += stride) {
        float xk[5];
#pragma unroll
        for (int k = 0; k < 5; k++) xk[k] = x[n*5 + k];
        float ss[4] = {0,0,0,0}, sd[4] = {0,0,0,0};
#pragma unroll
        for (int k = 0; k < 5; k++)
#pragma unroll
            for (int h = 0; h < 4; h++) {
                ss[h] += xk[k] * Ms[k*4 + h];
                sd[h] += xk[k] * Md[k*4 + h];
            }
        g_rec[2*n] = make_float4(ss[0], ss[1], ss[2], ss[3]);
        __half2 p01 = __floats2half2_rn(xk[0], xk[1]);
        __half2 p23 = __floats2half2_rn(xk[2], xk[3]);
        __half2 p4z = __floats2half2_rn(xk[4], 0.f);
        uint4 u;
        u.x = *reinterpret_cast<unsigned*>(&p01);
        u.y = *reinterpret_cast<unsigned*>(&p23);
        u.z = *reinterpret_cast<unsigned*>(&p4z);
        u.w = 0u;
        ((uint4*)g_rec)[2*n + 1] = u;
        ((float4*)g_sdd1)[n*2] = make_float4(sd[0], sd[1], sd[2], sd[3]);
    }
}

// FUSED layer-1 aggregation + layer-2 projection: warp per node, LANE PER EDGE.
// Aggregates 5-dim x per head (h1 is linear in x: o1 = aggx @ W1), so the per-edge
// gather is one 32B record instead of a 256B feature row. Epilogue rebuilds o1,
// applies elu+b1, projects through W2, stores fp16 h2 + layer-2 scores.
__global__ void k_agg1f(const float* __restrict__ W1, const float* __restrict__ W2,
                        const float* __restrict__ b1,
                        const float* __restrict__ as2, const float* __restrict__ ad2) {
    __shared__ float W1s[640];
    __shared__ float W2s[128*32];
    __shared__ float hs[8][128];
    int t = threadIdx.x, lane = t & 31, w = t >> 5;
    for (int i = t; i < 640; i += 256) W1s[i] = W1[i];
    for (int i = t; i < 4096; i += 256) W2s[i] = W2[i];
    __syncthreads();
    int warp = (blockIdx.x * blockDim.x + t) >> 5;
    int nwarps = (gridDim.x * blockDim.x) >> 5;
    float4 cc = *(const float4*)g_c1;
    float eam = g_eamean;
    float4 bb = ((const float4*)b1)[lane];
    float asv = as2[lane], adv = ad2[lane];
    int hl = lane >> 3;                      // this lane's output head
    for (int d = warp; d < Nn; d += nwarps) {
        int beg = g_off[d], end = g_off[d+1];
        float4 sdv = ((const float4*)g_sdd1)[d*2];
        float den[4] = {0,0,0,0};
        float ax[4][5] = {{0,0,0,0,0},{0,0,0,0,0},{0,0,0,0,0},{0,0,0,0,0}};
        // self loop (lane 0): src = d, a = eamean
        if (lane == 0) {
            float4 ssv = g_rec[2*d];
            uint4 xp = ((const uint4*)g_rec)[2*d + 1];
            float2 x01 = __half22float2(*(__half2*)&xp.x);
            float2 x23 = __half22float2(*(__half2*)&xp.y);
            float2 x4_ = __half22float2(*(__half2*)&xp.z);
            float xk[5] = {x01.x, x01.y, x23.x, x23.y, x4_.x};
            float nh[4];
            nh[0] = __expf(lrelu(ssv.x + sdv.x + eam*cc.x));
            nh[1] = __expf(lrelu(ssv.y + sdv.y + eam*cc.y));
            nh[2] = __expf(lrelu(ssv.z + sdv.z + eam*cc.z));
            nh[3] = __expf(lrelu(ssv.w + sdv.w + eam*cc.w));
#pragma unroll
            for (int h = 0; h < 4; h++) {
                den[h] += nh[h];
#pragma unroll
                for (int k = 0; k < 5; k++) ax[h][k] += nh[h]*xk[k];
            }
        }
        // real edges: lane-striped (contiguous, coalesced metadata)
        for (int i = beg + lane; i < end; i += 32) {
            unsigned m = g_sa[i];
            int s = sa_src(m);
            float a = sa_a(m);
            float4 ssv = g_rec[2*s];
            uint4 xp = ((const uint4*)g_rec)[2*s + 1];
            float2 x01 = __half22float2(*(__half2*)&xp.x);
            float2 x23 = __half22float2(*(__half2*)&xp.y);
            float2 x4_ = __half22float2(*(__half2*)&xp.z);
            float xk[5] = {x01.x, x01.y, x23.x, x23.y, x4_.x};
            float nh[4];
            nh[0] = __expf(lrelu(ssv.x + sdv.x + a*cc.x));
            nh[1] = __expf(lrelu(ssv.y + sdv.y + a*cc.y));
            nh[2] = __expf(lrelu(ssv.z + sdv.z + a*cc.z));
            nh[3] = __expf(lrelu(ssv.w + sdv.w + a*cc.w));
#pragma unroll
            for (int h = 0; h < 4; h++) {
                den[h] += nh[h];
#pragma unroll
                for (int k = 0; k < 5; k++) ax[h][k] += nh[h]*xk[k];
            }
        }
        // reduce 24 partials across the warp (butterfly: result in all lanes)
#pragma unroll
        for (int h = 0; h < 4; h++) den[h] = wredsum(den[h]);
#pragma unroll
        for (int h = 0; h < 4; h++)
#pragma unroll
            for (int k = 0; k < 5; k++) ax[h][k] = wredsum(ax[h][k]);
        if (lane == 0)
            ((float4*)g_sdd1)[d*2 + 1] = make_float4(den[0], den[1], den[2], den[3]);
        // select this lane's head values (static selects, no local-mem indexing)
        float axh[5], denh;
        denh = (hl == 0) ? den[0] : (hl == 1) ? den[1] : (hl == 2) ? den[2] : den[3];
#pragma unroll
        for (int k = 0; k < 5; k++)
            axh[k] = (hl == 0) ? ax[0][k] : (hl == 1) ? ax[1][k] : (hl == 2) ? ax[2][k] : ax[3][k];
        float inv = 1.0f / (denh + 1e-16f);
        // o1 channels [4*lane .. 4*lane+3] = aggx @ W1, normalize, elu + b1
        float hv[4];
#pragma unroll
        for (int j = 0; j < 4; j++) {
            int chn = lane*4 + j;
            float o = axh[0]*W1s[chn] + axh[1]*W1s[128+chn] + axh[2]*W1s[256+chn]
                    + axh[3]*W1s[384+chn] + axh[4]*W1s[512+chn];
            hv[j] = o * inv;
        }
        hs[w][lane*4+0] = elu(hv[0] + bb.x);
        hs[w][lane*4+1] = elu(hv[1] + bb.y);
        hs[w][lane*4+2] = elu(hv[2] + bb.z);
        hs[w][lane*4+3] = elu(hv[3] + bb.w);
        __syncwarp();
        float acc2 = 0.f;
#pragma unroll 16
        for (int j = 0; j < 128; j++)
            acc2 += hs[w][j] * W2s[j*32 + lane];
        g_h2h[d*32 + lane] = __float2half_rn(acc2);
        float ps = wredsum(acc2 * asv);
        float pd = wredsum(acc2 * adv);
        if (lane == 0) { g_ss2[d] = ps; g_sd2[d] = pd; }
        __syncwarp();
    }
}

// edge-parallel alpha1 writer: original edge order -> coalesced output stores
// (ss1 read from the fp32 half of the node record; alpha precision unchanged)
__global__ void k_alphaE(const int* __restrict__ ei, const float* __restrict__ ea,
                         float* __restrict__ out) {
    int e = blockIdx.x * blockDim.x + threadIdx.x;
    if (e >= EF) return;
    int s, d; float a;
    if (e < Ee) { s = ei[e]; d = ei[Ee + e]; a = ea[e]; }
    else        { s = e - Ee; d = s; a = g_eamean; }
    float4 ss = g_rec[2*s];
    float4 sd = ((const float4*)g_sdd1)[d*2];
    float4 dd = ((const float4*)g_sdd1)[d*2 + 1];
    float n0 = __expf(lrelu(ss.x + sd.x + a*g_c1[0])) / (dd.x + 1e-16f);
    float n1 = __expf(lrelu(ss.y + sd.y + a*g_c1[1])) / (dd.y + 1e-16f);
    float n2 = __expf(lrelu(ss.z + sd.z + a*g_c1[2])) / (dd.z + 1e-16f);
    float n3 = __expf(lrelu(ss.w + sd.w + a*g_c1[3])) / (dd.w + 1e-16f);
    float2* ao = (float2*)(out + A1_OFF + 4*e);
    ao[0] = make_float2(n0, n1);
    ao[1] = make_float2(n2, n3);
}

// layer-2 aggregation + final node head: warp per node, unroll x4, analytic self loop
__global__ void k_agg2(const float* __restrict__ b2, const float* __restrict__ Wa,
                       const float* __restrict__ ba) {
    __shared__ float sacc[32];
    int t = threadIdx.x, lane = t & 31;
    if (t < 32) sacc[t] = 0.f;
    __syncthreads();
    int warp = (blockIdx.x * blockDim.x + t) >> 5;
    int nwarps = (gridDim.x * blockDim.x) >> 5;
    float c = g_c2, eam = g_eamean;
    float bl = b2[lane], wl = Wa[lane], bb = ba[0];
    float gacc = 0.f;
    for (int d = warp; d < Nn; d += nwarps) {
        int beg = g_off[d], end = g_off[d+1];
        float sdv = g_sd2[d];
        float nself = __expf(lrelu(g_ss2[d] + sdv + eam*c));
        float acc = nself * __half2float(g_h2h[d*32 + lane]);
        float den = nself;
        int i = beg;
        for (; i + 3 < end; i += 4) {
            unsigned e0 = g_sa[i], e1 = g_sa[i+1], e2 = g_sa[i+2], e3 = g_sa[i+3];
            int s0 = sa_src(e0), s1 = sa_src(e1), s2 = sa_src(e2), s3 = sa_src(e3);
            float ss0 = g_ss2[s0], ss1v = g_ss2[s1];
            float ss2v = g_ss2[s2], ss3v = g_ss2[s3];
            float v0 = __half2float(g_h2h[s0*32 + lane]);
            float v1 = __half2float(g_h2h[s1*32 + lane]);
            float v2 = __half2float(g_h2h[s2*32 + lane]);
            float v3 = __half2float(g_h2h[s3*32 + lane]);
            float n0 = __expf(lrelu(ss0  + sdv + sa_a(e0)*c));
            float n1 = __expf(lrelu(ss1v + sdv + sa_a(e1)*c));
            float n2 = __expf(lrelu(ss2v + sdv + sa_a(e2)*c));
            float n3 = __expf(lrelu(ss3v + sdv + sa_a(e3)*c));
            den += (n0 + n1) + (n2 + n3);
            acc += n0*v0 + n1*v1 + n2*v2 + n3*v3;
        }
        for (; i < end; i++) {
            unsigned e0 = g_sa[i];
            int s0 = sa_src(e0);
            float n0 = __expf(lrelu(g_ss2[s0] + sdv + sa_a(e0)*c));
            den += n0;
            acc += n0 * __half2float(g_h2h[s0*32 + lane]);
        }
        float v = elu(acc / (den + 1e-16f) + bl);
        gacc += v;
        float p = wredsum(v * wl);
        if (lane == 0) g_scores[d] = p + bb;
    }
    atomicAdd(&sacc[lane], gacc);
    __syncthreads();
    if (t < 32) atomicAdd(&g_gsum[t], sacc[t]);
}

// softmax over [cash, scores[stock_idx]] + critic value
__global__ void k_head(const float* __restrict__ cash, const int* __restrict__ stock_idx,
                       const float* __restrict__ Wc, const float* __restrict__ bc,
                       int ns, float* __restrict__ out) {
    if (threadIdx.x < 32) {
        float p = wredsum(g_gsum[threadIdx.x] * (1.0f / Nn) * Wc[threadIdx.x]);
        if (threadIdx.x == 0) out[V_OFF] = p + bc[0];
    }
    __shared__ float sm[32];
    __shared__ float bM, bS;
    int t = threadIdx.x, lane = t & 31, w = t >> 5, nw = blockDim.x >> 5;
    int total = ns + 1;
    float m = -INF_;
    for (int i = t; i < total; i += blockDim.x) {
        float v = (i == 0) ? cash[0] : g_scores[stock_idx[i-1]];
        m = fmaxf(m, v);
    }
    m = wredmax(m);
    if (lane == 0) sm[w] = m;
    __syncthreads();
    if (w == 0) {
        float v = (lane < nw) ? sm[lane] : -INF_;
        v = wredmax(v);
        if (lane == 0) bM = v;
    }
    __syncthreads();
    float M = bM;
    float s = 0.f;
    for (int i = t; i < total; i += blockDim.x) {
        float v = (i == 0) ? cash[0] : g_scores[stock_idx[i-1]];
        s += __expf(v - M);
    }
    s = wredsum(s);
    __syncthreads();
    if (lane == 0) sm[w] = s;
    __syncthreads();
    if (w == 0) {
        float v = (lane < nw) ? sm[lane] : 0.f;
        v = wredsum(v);
        if (lane == 0) bS = v;
    }
    __syncthreads();
    float inv = 1.0f / bS;
    for (int i = t; i < total; i += blockDim.x) {
        float v = (i == 0) ? cash[0] : g_scores[stock_idx[i-1]];
        out[W_OFF + i] = __expf(v - M) * inv;
    }
}

// ---------------- launch ----------------
extern "C" void kernel_launch(void* const* d_in, const int* in_sizes, int n_in,
                              void* d_out, int out_size) {
    const float* x    = (const float*)d_in[0];
    const float* ea   = (const float*)d_in[1];
    const float* W1   = (const float*)d_in[2];
    const float* as1  = (const float*)d_in[3];
    const float* ad1  = (const float*)d_in[4];
    const float* We1  = (const float*)d_in[5];
    const float* ae1  = (const float*)d_in[6];
    const float* b1   = (const float*)d_in[7];
    const float* W2   = (const float*)d_in[8];
    const float* as2  = (const float*)d_in[9];
    const float* ad2  = (const float*)d_in[10];
    const float* We2  = (const float*)d_in[11];
    const float* ae2  = (const float*)d_in[12];
    const float* b2   = (const float*)d_in[13];
    const float* Wa   = (const float*)d_in[14];
    const float* ba   = (const float*)d_in[15];
    const float* cash = (const float*)d_in[16];
    const float* Wc   = (const float*)d_in[17];
    const float* bc   = (const float*)d_in[18];
    const int*   ei   = (const int*)  d_in[19];
    const int*   sidx = (const int*)  d_in[20];
    float* out = (float*)d_out;
    int ns = in_sizes[20];

    // lazy one-time stream/event setup (host-side objects only; no device mem)
    static cudaStream_t sA = nullptr, sB = nullptr;
    static cudaEvent_t evFork, evNode1, evAgg1, evAlpha, evEnd;
    if (!sA) {
        cudaStreamCreateWithFlags(&sA, cudaStreamNonBlocking);
        cudaStreamCreateWithFlags(&sB, cudaStreamNonBlocking);
        cudaEventCreateWithFlags(&evFork,  cudaEventDisableTiming);
        cudaEventCreateWithFlags(&evNode1, cudaEventDisableTiming);
        cudaEventCreateWithFlags(&evAgg1,  cudaEventDisableTiming);
        cudaEventCreateWithFlags(&evAlpha, cudaEventDisableTiming);
        cudaEventCreateWithFlags(&evEnd,   cudaEventDisableTiming);
    }

    // fork from the harness's (captured) stream
    cudaEventRecord(evFork, 0);
    cudaStreamWaitEvent(sA, evFork, 0);
    cudaStreamWaitEvent(sB, evFork, 0);

    // stream B: easum -> consts (+M matrices) -> node1 -> edge_index_full
    k_easum <<<1024, 256, 0, sB>>>(ea);
    k_consts<<<1, 128, 0, sB>>>(W1, as1, ad1, We1, ae1, We2, ae2);
    k_node1 <<<196, 256, 0, sB>>>(x);
    cudaEventRecord(evNode1, sB);      // implies consts done too
    k_eif   <<<(EF + 255) / 256, 256, 0, sB>>>(ei, out);

    // stream A: CSR build -> fused agg+proj -> agg2 -> head
    k_init   <<<256, 256, 0, sA>>>();
    k_hist   <<<(Ee + 255) / 256, 256, 0, sA>>>(ei);
    k_scan   <<<1, 1024, 0, sA>>>();
    k_scatter<<<(Ee + 255) / 256, 256, 0, sA>>>(ei, ea);
    cudaStreamWaitEvent(sA, evNode1, 0);                // records, sd1, consts
    k_agg1f  <<<1184, 256, 0, sA>>>(W1, W2, b1, as2, ad2);
    cudaEventRecord(evAgg1, sA);

    // stream B: alpha writer overlaps agg2 (disjoint data)
    cudaStreamWaitEvent(sB, evAgg1, 0);                 // denominators
    k_alphaE<<<(EF + 255) / 256, 256, 0, sB>>>(ei, ea, out);
    cudaEventRecord(evAlpha, sB);

    k_agg2  <<<1184, 256, 0, sA>>>(b2, Wa, ba);
    k_head  <<<1, 1024, 0, sA>>>(cash, sidx, Wc, bc, ns, out);
    cudaEventRecord(evEnd, sA);

    // join both streams back into the harness stream
    cudaStreamWaitEvent(0, evEnd, 0);
    cudaStreamWaitEvent(0, evAlpha, 0);
}

// round 11
// speedup vs baseline: 2.3104x; 1.0417x over previous
#include <cuda_runtime.h>
#include <cuda_fp16.h>
#include <math.h>

// ---------------- problem constants ----------------
#define Nn    50000
#define Ee    1600000
#define EF    1650000          // E + N self loops
#define INF_  3.402823466e38f
#define SCANB 13               // scan blocks: 13*1024 int4 = 53248 >= 12500

// output layout (float32, flattened in return order)
#define W_OFF  0               // weights [25001]
#define V_OFF  25001           // value   [1]
#define EI_OFF 25002           // edge_index_full [2, EF]
#define A1_OFF (25002 + 2*EF)  // alpha1 [EF, 4]  (8B-aligned only!)

// ---------------- device scratch ----------------
// node record: rec[2n] = ss1 (fp32 x4), rec[2n+1] = x (fp16 x5, packed, padded)
__device__ __align__(16) float4 g_rec [Nn*2];
__device__ __align__(16) float  g_sdd1[Nn*8];    // [sd1(4) | den1(4)] per node
__device__ __align__(16) __half g_h2h [Nn*32];   // layer2 features, fp16 (32 ch)
__device__ float g_ss2[Nn], g_sd2[Nn];
__device__ float g_scores[Nn];
__device__ float g_gsum[32];
__device__ float g_easum, g_eamean;
__device__ __align__(16) float g_c1[4];
__device__ float g_c2;
__device__ float g_Ms[20], g_Md[20];             // (5 x 4) score matrices: x @ M = s
// CSR-by-dst structures (real edges only; self loops handled analytically)
__device__ __align__(16) int g_cnt[Nn];
__device__ __align__(16) int g_off[Nn + 4];
__device__ __align__(16) int g_pos[Nn];
__device__ __align__(16) unsigned g_sa[Ee];      // [fp16 a | uint16 src] per edge
__device__ int g_bpref[32];                      // chained-scan mailboxes (-1 = empty)

// ---------------- helpers ----------------
__device__ __forceinline__ float wredsum(float v) {
#pragma unroll
    for (int o = 16; o; o >>= 1) v += __shfl_xor_sync(0xffffffffu, v, o);
    return v;
}
__device__ __forceinline__ float wredmax(float v) {
#pragma unroll
    for (int o = 16; o; o >>= 1) v = fmaxf(v, __shfl_xor_sync(0xffffffffu, v, o));
    return v;
}
__device__ __forceinline__ float lrelu(float x) { return x >= 0.f ? x : 0.2f * x; }
__device__ __forceinline__ float elu(float x)   { return x > 0.f ? x : expm1f(x); }
__device__ __forceinline__ int   sa_src(unsigned q) { return (int)(q & 0xFFFFu); }
__device__ __forceinline__ float sa_a(unsigned q) {
    return __half2float(__ushort_as_half((unsigned short)(q >> 16)));
}

// ---------------- kernels ----------------
__global__ void k_init() {
    int stride = gridDim.x * blockDim.x;
    int t = blockIdx.x * blockDim.x + threadIdx.x;
    for (int i = t; i < Nn; i += stride) g_cnt[i] = 0;
    if (t < 32) { g_gsum[t] = 0.f; g_bpref[t] = (t == 0) ? 0 : -1; }
    if (t == 0) g_easum = 0.f;
}

__global__ void k_easum(const float* __restrict__ ea) {
    float s = 0.f;
    for (int i = blockIdx.x * blockDim.x + threadIdx.x; i < Ee; i += gridDim.x * blockDim.x)
        s += ea[i];
    s = wredsum(s);
    __shared__ float sm[8];
    int lane = threadIdx.x & 31, w = threadIdx.x >> 5;
    if (lane == 0) sm[w] = s;
    __syncthreads();
    if (threadIdx.x == 0) {
        float b = 0.f;
        for (int i = 0; i < (int)(blockDim.x >> 5); i++) b += sm[i];
        atomicAdd(&g_easum, b);
    }
}

// consts: c1/c2/eamean + score matrices Ms/Md (5x4) so node1 never needs W1
__global__ void k_consts(const float* __restrict__ W1,
                         const float* __restrict__ as1, const float* __restrict__ ad1,
                         const float* __restrict__ We1, const float* __restrict__ ae1,
                         const float* __restrict__ We2, const float* __restrict__ ae2) {
    int t = threadIdx.x;            // 128 threads; warp == head
    int lane = t & 31, h = t >> 5;
    float p = We1[t] * ae1[t];
    p = wredsum(p);
    if (lane == 0) g_c1[h] = p;
    float asv = as1[t], adv = ad1[t];
#pragma unroll
    for (int k = 0; k < 5; k++) {
        float ms = wredsum(W1[k*128 + t] * asv);
        float md = wredsum(W1[k*128 + t] * adv);
        if (lane == 0) { g_Ms[k*4 + h] = ms; g_Md[k*4 + h] = md; }
    }
    if (t < 32) {
        float q = We2[t] * ae2[t];
        q = wredsum(q);
        if (t == 0) { g_c2 = q; g_eamean = g_easum * (1.0f / Ee); }
    }
}

// emit edge_index_full output (depends only on ei) — runs on side stream
__global__ void k_eif(const int* __restrict__ ei, float* __restrict__ out) {
    int e = blockIdx.x * blockDim.x + threadIdx.x;
    if (e >= EF) return;
    int s, d;
    if (e < Ee) { s = ei[e]; d = ei[Ee + e]; }
    else        { s = e - Ee; d = s; }
    out[EI_OFF + e]      = (float)s;
    out[EI_OFF + EF + e] = (float)d;
}

// histogram of dst over real edges
__global__ void k_hist(const int* __restrict__ ei) {
    int e = blockIdx.x * blockDim.x + threadIdx.x;
    if (e >= Ee) return;
    atomicAdd(&g_cnt[ei[Ee + e]], 1);
}

// decoupled chained scan: SCANB blocks x 1024 threads, one int4 per thread.
// Block b scans its 4096 counts locally, receives the exclusive prefix from
// block b-1 via an atomic mailbox, writes g_off/g_pos, forwards prefix+total.
// SCANB << SM count -> single wave, no deadlock.
__global__ void __launch_bounds__(1024) k_scan() {
    __shared__ int wsum[32];
    __shared__ int s_pref;
    const int M4 = Nn / 4;                 // 12500
    int b = blockIdx.x, t = threadIdx.x, lane = t & 31, w = t >> 5;
    int idx = b * 1024 + t;
    int4 v = (idx < M4) ? ((const int4*)g_cnt)[idx] : make_int4(0, 0, 0, 0);
    int tsum = v.x + v.y + v.z + v.w;
    int val = tsum;
#pragma unroll
    for (int o = 1; o < 32; o <<= 1) { int x = __shfl_up_sync(0xffffffffu, val, o); if (lane >= o) val += x; }
    if (lane == 31) wsum[w] = val;
    __syncthreads();
    if (w == 0) {
        int x = wsum[lane];
#pragma unroll
        for (int o = 1; o < 32; o <<= 1) { int y = __shfl_up_sync(0xffffffffu, x, o); if (lane >= o) x += y; }
        wsum[lane] = x;
    }
    __syncthreads();
    int btot = wsum[31];
    int excl = ((w > 0) ? wsum[w - 1] : 0) + val - tsum;   // exclusive within block
    if (t == 0) {
        int pref = 0;
        if (b > 0) {
            while ((pref = atomicAdd(&g_bpref[b], 0)) < 0) __nanosleep(64);
        }
        atomicExch(&g_bpref[b + 1], pref + btot);
        s_pref = pref;
    }
    __syncthreads();
    int base = s_pref;
    if (idx < M4) {
        int4 o;
        o.x = base + excl; o.y = o.x + v.x; o.z = o.y + v.y; o.w = o.z + v.z;
        ((int4*)g_off)[idx] = o;
        ((int4*)g_pos)[idx] = o;
        if (idx == M4 - 1) g_off[Nn] = o.w + v.w;
    }
}

// scatter real edges into CSR order as packed (fp16 a | uint16 src)
__global__ void k_scatter(const int* __restrict__ ei, const float* __restrict__ ea) {
    int e = blockIdx.x * blockDim.x + threadIdx.x;
    if (e >= Ee) return;
    int s = ei[e], d = ei[Ee + e];
    unsigned ah = (unsigned)__half_as_ushort(__float2half_rn(ea[e]));
    int p = atomicAdd(&g_pos[d], 1);
    g_sa[p] = (unsigned)s | (ah << 16);
}

// node prep: thread per node. ss1/sd1 = x @ Ms/Md (5x4). Writes the packed
// node record [ss1 fp32 | x fp16] and sd1. h1 is NEVER materialized.
__global__ void k_node1(const float* __restrict__ x) {
    __shared__ float Ms[20], Md[20];
    int t = threadIdx.x;
    if (t < 20) { Ms[t] = g_Ms[t]; Md[t] = g_Md[t]; }
    __syncthreads();
    int stride = gridDim.x * blockDim.x;
    for (int n = blockIdx.x * blockDim.x + t; n < Nn; n += stride) {
        float xk[5];
#pragma unroll
        for (int k = 0; k < 5; k++) xk[k] = x[n*5 + k];
        float ss[4] = {0,0,0,0}, sd[4] = {0,0,0,0};
#pragma unroll
        for (int k = 0; k < 5; k++)
#pragma unroll
            for (int h = 0; h < 4; h++) {
                ss[h] += xk[k] * Ms[k*4 + h];
                sd[h] += xk[k] * Md[k*4 + h];
            }
        g_rec[2*n] = make_float4(ss[0], ss[1], ss[2], ss[3]);
        __half2 p01 = __floats2half2_rn(xk[0], xk[1]);
        __half2 p23 = __floats2half2_rn(xk[2], xk[3]);
        __half2 p4z = __floats2half2_rn(xk[4], 0.f);
        uint4 u;
        u.x = *reinterpret_cast<unsigned*>(&p01);
        u.y = *reinterpret_cast<unsigned*>(&p23);
        u.z = *reinterpret_cast<unsigned*>(&p4z);
        u.w = 0u;
        ((uint4*)g_rec)[2*n + 1] = u;
        ((float4*)g_sdd1)[n*2] = make_float4(sd[0], sd[1], sd[2], sd[3]);
    }
}

// FUSED layer-1 aggregation + layer-2 projection: warp per node, LANE PER EDGE.
// Aggregates 5-dim x per head (o1 = aggx @ W1), 32B record gather per edge.
__global__ void __launch_bounds__(256) k_agg1f(
        const float* __restrict__ W1, const float* __restrict__ W2,
        const float* __restrict__ b1,
        const float* __restrict__ as2, const float* __restrict__ ad2) {
    __shared__ float W1s[640];
    __shared__ float W2s[128*32];
    __shared__ float hs[8][128];
    int t = threadIdx.x, lane = t & 31, w = t >> 5;
    for (int i = t; i < 640; i += 256) W1s[i] = W1[i];
    for (int i = t; i < 4096; i += 256) W2s[i] = W2[i];
    __syncthreads();
    int warp = (blockIdx.x * blockDim.x + t) >> 5;
    int nwarps = (gridDim.x * blockDim.x) >> 5;
    float4 cc = *(const float4*)g_c1;
    float eam = g_eamean;
    float4 bb = ((const float4*)b1)[lane];
    float asv = as2[lane], adv = ad2[lane];
    int hl = lane >> 3;                      // this lane's output head
    for (int d = warp; d < Nn; d += nwarps) {
        int beg = g_off[d], end = g_off[d+1];
        float4 sdv = ((const float4*)g_sdd1)[d*2];
        float den[4] = {0,0,0,0};
        float ax[4][5] = {{0,0,0,0,0},{0,0,0,0,0},{0,0,0,0,0},{0,0,0,0,0}};
        // self loop (lane 0): src = d, a = eamean
        if (lane == 0) {
            float4 ssv = g_rec[2*d];
            uint4 xp = ((const uint4*)g_rec)[2*d + 1];
            float2 x01 = __half22float2(*(__half2*)&xp.x);
            float2 x23 = __half22float2(*(__half2*)&xp.y);
            float2 x4_ = __half22float2(*(__half2*)&xp.z);
            float xk[5] = {x01.x, x01.y, x23.x, x23.y, x4_.x};
            float nh[4];
            nh[0] = __expf(lrelu(ssv.x + sdv.x + eam*cc.x));
            nh[1] = __expf(lrelu(ssv.y + sdv.y + eam*cc.y));
            nh[2] = __expf(lrelu(ssv.z + sdv.z + eam*cc.z));
            nh[3] = __expf(lrelu(ssv.w + sdv.w + eam*cc.w));
#pragma unroll
            for (int h = 0; h < 4; h++) {
                den[h] += nh[h];
#pragma unroll
                for (int k = 0; k < 5; k++) ax[h][k] += nh[h]*xk[k];
            }
        }
        // real edges: lane-striped (contiguous, coalesced metadata)
        for (int i = beg + lane; i < end; i += 32) {
            unsigned m = g_sa[i];
            int s = sa_src(m);
            float a = sa_a(m);
            float4 ssv = g_rec[2*s];
            uint4 xp = ((const uint4*)g_rec)[2*s + 1];
            float2 x01 = __half22float2(*(__half2*)&xp.x);
            float2 x23 = __half22float2(*(__half2*)&xp.y);
            float2 x4_ = __half22float2(*(__half2*)&xp.z);
            float xk[5] = {x01.x, x01.y, x23.x, x23.y, x4_.x};
            float nh[4];
            nh[0] = __expf(lrelu(ssv.x + sdv.x + a*cc.x));
            nh[1] = __expf(lrelu(ssv.y + sdv.y + a*cc.y));
            nh[2] = __expf(lrelu(ssv.z + sdv.z + a*cc.z));
            nh[3] = __expf(lrelu(ssv.w + sdv.w + a*cc.w));
#pragma unroll
            for (int h = 0; h < 4; h++) {
                den[h] += nh[h];
#pragma unroll
                for (int k = 0; k < 5; k++) ax[h][k] += nh[h]*xk[k];
            }
        }
        // reduce 24 partials across the warp (butterfly: result in all lanes)
#pragma unroll
        for (int h = 0; h < 4; h++) den[h] = wredsum(den[h]);
#pragma unroll
        for (int h = 0; h < 4; h++)
#pragma unroll
            for (int k = 0; k < 5; k++) ax[h][k] = wredsum(ax[h][k]);
        if (lane == 0)
            ((float4*)g_sdd1)[d*2 + 1] = make_float4(den[0], den[1], den[2], den[3]);
        // select this lane's head values (static selects)
        float axh[5], denh;
        denh = (hl == 0) ? den[0] : (hl == 1) ? den[1] : (hl == 2) ? den[2] : den[3];
#pragma unroll
        for (int k = 0; k < 5; k++)
            axh[k] = (hl == 0) ? ax[0][k] : (hl == 1) ? ax[1][k] : (hl == 2) ? ax[2][k] : ax[3][k];
        float inv = 1.0f / (denh + 1e-16f);
        // o1 channels [4*lane .. 4*lane+3] = aggx @ W1, normalize, elu + b1
        float hv[4];
#pragma unroll
        for (int j = 0; j < 4; j++) {
            int chn = lane*4 + j;
            float o = axh[0]*W1s[chn] + axh[1]*W1s[128+chn] + axh[2]*W1s[256+chn]
                    + axh[3]*W1s[384+chn] + axh[4]*W1s[512+chn];
            hv[j] = o * inv;
        }
        hs[w][lane*4+0] = elu(hv[0] + bb.x);
        hs[w][lane*4+1] = elu(hv[1] + bb.y);
        hs[w][lane*4+2] = elu(hv[2] + bb.z);
        hs[w][lane*4+3] = elu(hv[3] + bb.w);
        __syncwarp();
        float acc2 = 0.f;
#pragma unroll 16
        for (int j = 0; j < 128; j++)
            acc2 += hs[w][j] * W2s[j*32 + lane];
        g_h2h[d*32 + lane] = __float2half_rn(acc2);
        float ps = wredsum(acc2 * asv);
        float pd = wredsum(acc2 * adv);
        if (lane == 0) { g_ss2[d] = ps; g_sd2[d] = pd; }
        __syncwarp();
    }
}

// edge-parallel alpha1 writer: original edge order -> coalesced output stores
__global__ void k_alphaE(const int* __restrict__ ei, const float* __restrict__ ea,
                         float* __restrict__ out) {
    int e = blockIdx.x * blockDim.x + threadIdx.x;
    if (e >= EF) return;
    int s, d; float a;
    if (e < Ee) { s = ei[e]; d = ei[Ee + e]; a = ea[e]; }
    else        { s = e - Ee; d = s; a = g_eamean; }
    float4 ss = g_rec[2*s];
    float4 sd = ((const float4*)g_sdd1)[d*2];
    float4 dd = ((const float4*)g_sdd1)[d*2 + 1];
    float n0 = __expf(lrelu(ss.x + sd.x + a*g_c1[0])) / (dd.x + 1e-16f);
    float n1 = __expf(lrelu(ss.y + sd.y + a*g_c1[1])) / (dd.y + 1e-16f);
    float n2 = __expf(lrelu(ss.z + sd.z + a*g_c1[2])) / (dd.z + 1e-16f);
    float n3 = __expf(lrelu(ss.w + sd.w + a*g_c1[3])) / (dd.w + 1e-16f);
    float2* ao = (float2*)(out + A1_OFF + 4*e);
    ao[0] = make_float2(n0, n1);
    ao[1] = make_float2(n2, n3);
}

// layer-2 aggregation + final node head: warp per node, unroll x4, analytic self loop
__global__ void __launch_bounds__(256) k_agg2(
        const float* __restrict__ b2, const float* __restrict__ Wa,
        const float* __restrict__ ba) {
    __shared__ float sacc[32];
    int t = threadIdx.x, lane = t & 31;
    if (t < 32) sacc[t] = 0.f;
    __syncthreads();
    int warp = (blockIdx.x * blockDim.x + t) >> 5;
    int nwarps = (gridDim.x * blockDim.x) >> 5;
    float c = g_c2, eam = g_eamean;
    float bl = b2[lane], wl = Wa[lane], bb = ba[0];
    float gacc = 0.f;
    for (int d = warp; d < Nn; d += nwarps) {
        int beg = g_off[d], end = g_off[d+1];
        float sdv = g_sd2[d];
        float nself = __expf(lrelu(g_ss2[d] + sdv + eam*c));
        float acc = nself * __half2float(g_h2h[d*32 + lane]);
        float den = nself;
        int i = beg;
        for (; i + 3 < end; i += 4) {
            unsigned e0 = g_sa[i], e1 = g_sa[i+1], e2 = g_sa[i+2], e3 = g_sa[i+3];
            int s0 = sa_src(e0), s1 = sa_src(e1), s2 = sa_src(e2), s3 = sa_src(e3);
            float ss0 = g_ss2[s0], ss1v = g_ss2[s1];
            float ss2v = g_ss2[s2], ss3v = g_ss2[s3];
            float v0 = __half2float(g_h2h[s0*32 + lane]);
            float v1 = __half2float(g_h2h[s1*32 + lane]);
            float v2 = __half2float(g_h2h[s2*32 + lane]);
            float v3 = __half2float(g_h2h[s3*32 + lane]);
            float n0 = __expf(lrelu(ss0  + sdv + sa_a(e0)*c));
            float n1 = __expf(lrelu(ss1v + sdv + sa_a(e1)*c));
            float n2 = __expf(lrelu(ss2v + sdv + sa_a(e2)*c));
            float n3 = __expf(lrelu(ss3v + sdv + sa_a(e3)*c));
            den += (n0 + n1) + (n2 + n3);
            acc += n0*v0 + n1*v1 + n2*v2 + n3*v3;
        }
        for (; i < end; i++) {
            unsigned e0 = g_sa[i];
            int s0 = sa_src(e0);
            float n0 = __expf(lrelu(g_ss2[s0] + sdv + sa_a(e0)*c));
            den += n0;
            acc += n0 * __half2float(g_h2h[s0*32 + lane]);
        }
        float v = elu(acc / (den + 1e-16f) + bl);
        gacc += v;
        float p = wredsum(v * wl);
        if (lane == 0) g_scores[d] = p + bb;
    }
    atomicAdd(&sacc[lane], gacc);
    __syncthreads();
    if (t < 32) atomicAdd(&g_gsum[t], sacc[t]);
}

// softmax over [cash, scores[stock_idx]] + critic value
__global__ void k_head(const float* __restrict__ cash, const int* __restrict__ stock_idx,
                       const float* __restrict__ Wc, const float* __restrict__ bc,
                       int ns, float* __restrict__ out) {
    if (threadIdx.x < 32) {
        float p = wredsum(g_gsum[threadIdx.x] * (1.0f / Nn) * Wc[threadIdx.x]);
        if (threadIdx.x == 0) out[V_OFF] = p + bc[0];
    }
    __shared__ float sm[32];
    __shared__ float bM, bS;
    int t = threadIdx.x, lane = t & 31, w = t >> 5, nw = blockDim.x >> 5;
    int total = ns + 1;
    float m = -INF_;
    for (int i = t; i < total; i += blockDim.x) {
        float v = (i == 0) ? cash[0] : g_scores[stock_idx[i-1]];
        m = fmaxf(m, v);
    }
    m = wredmax(m);
    if (lane == 0) sm[w] = m;
    __syncthreads();
    if (w == 0) {
        float v = (lane < nw) ? sm[lane] : -INF_;
        v = wredmax(v);
        if (lane == 0) bM = v;
    }
    __syncthreads();
    float M = bM;
    float s = 0.f;
    for (int i = t; i < total; i += blockDim.x) {
        float v = (i == 0) ? cash[0] : g_scores[stock_idx[i-1]];
        s += __expf(v - M);
    }
    s = wredsum(s);
    __syncthreads();
    if (lane == 0) sm[w] = s;
    __syncthreads();
    if (w == 0) {
        float v = (lane < nw) ? sm[lane] : 0.f;
        v = wredsum(v);
        if (lane == 0) bS = v;
    }
    __syncthreads();
    float inv = 1.0f / bS;
    for (int i = t; i < total; i += blockDim.x) {
        float v = (i == 0) ? cash[0] : g_scores[stock_idx[i-1]];
        out[W_OFF + i] = __expf(v - M) * inv;
    }
}

// ---------------- launch ----------------
extern "C" void kernel_launch(void* const* d_in, const int* in_sizes, int n_in,
                              void* d_out, int out_size) {
    const float* x    = (const float*)d_in[0];
    const float* ea   = (const float*)d_in[1];
    const float* W1   = (const float*)d_in[2];
    const float* as1  = (const float*)d_in[3];
    const float* ad1  = (const float*)d_in[4];
    const float* We1  = (const float*)d_in[5];
    const float* ae1  = (const float*)d_in[6];
    const float* b1   = (const float*)d_in[7];
    const float* W2   = (const float*)d_in[8];
    const float* as2  = (const float*)d_in[9];
    const float* ad2  = (const float*)d_in[10];
    const float* We2  = (const float*)d_in[11];
    const float* ae2  = (const float*)d_in[12];
    const float* b2   = (const float*)d_in[13];
    const float* Wa   = (const float*)d_in[14];
    const float* ba   = (const float*)d_in[15];
    const float* cash = (const float*)d_in[16];
    const float* Wc   = (const float*)d_in[17];
    const float* bc   = (const float*)d_in[18];
    const int*   ei   = (const int*)  d_in[19];
    const int*   sidx = (const int*)  d_in[20];
    float* out = (float*)d_out;
    int ns = in_sizes[20];

    // lazy one-time stream/event/occupancy setup (host-side objects only)
    static cudaStream_t sA = nullptr, sB = nullptr;
    static cudaEvent_t evFork, evNode1, evAgg1, evAlpha, evEnd;
    static int gridA1 = 0, gridA2 = 0;
    if (!sA) {
        cudaStreamCreateWithFlags(&sA, cudaStreamNonBlocking);
        cudaStreamCreateWithFlags(&sB, cudaStreamNonBlocking);
        cudaEventCreateWithFlags(&evFork,  cudaEventDisableTiming);
        cudaEventCreateWithFlags(&evNode1, cudaEventDisableTiming);
        cudaEventCreateWithFlags(&evAgg1,  cudaEventDisableTiming);
        cudaEventCreateWithFlags(&evAlpha, cudaEventDisableTiming);
        cudaEventCreateWithFlags(&evEnd,   cudaEventDisableTiming);
        int sms = 148, nb = 0;
        cudaDeviceGetAttribute(&sms, cudaDevAttrMultiProcessorCount, 0);
        cudaOccupancyMaxActiveBlocksPerMultiprocessor(&nb, k_agg1f, 256, 0);
        gridA1 = (nb > 0 ? nb : 4) * sms;
        cudaOccupancyMaxActiveBlocksPerMultiprocessor(&nb, k_agg2, 256, 0);
        gridA2 = (nb > 0 ? nb : 8) * sms;
        if (gridA2 > 6250) gridA2 = 6250;   // no more than one warp per node
        if (gridA1 > 6250) gridA1 = 6250;
    }

    // fork from the harness's (captured) stream
    cudaEventRecord(evFork, 0);
    cudaStreamWaitEvent(sA, evFork, 0);
    cudaStreamWaitEvent(sB, evFork, 0);

    // stream B: easum -> consts (+M matrices) -> node1 -> edge_index_full
    k_easum <<<1024, 256, 0, sB>>>(ea);
    k_consts<<<1, 128, 0, sB>>>(W1, as1, ad1, We1, ae1, We2, ae2);
    k_node1 <<<196, 256, 0, sB>>>(x);
    cudaEventRecord(evNode1, sB);      // implies consts done too
    k_eif   <<<(EF + 255) / 256, 256, 0, sB>>>(ei, out);

    // stream A: CSR build -> fused agg+proj -> agg2 -> head
    k_init   <<<256, 256, 0, sA>>>();
    k_hist   <<<(Ee + 255) / 256, 256, 0, sA>>>(ei);
    k_scan   <<<SCANB, 1024, 0, sA>>>();
    k_scatter<<<(Ee + 255) / 256, 256, 0, sA>>>(ei, ea);
    cudaStreamWaitEvent(sA, evNode1, 0);                // records, sd1, consts
    k_agg1f  <<<gridA1, 256, 0, sA>>>(W1, W2, b1, as2, ad2);
    cudaEventRecord(evAgg1, sA);

    // stream B: alpha writer overlaps agg2 (disjoint data)
    cudaStreamWaitEvent(sB, evAgg1, 0);                 // denominators
    k_alphaE<<<(EF + 255) / 256, 256, 0, sB>>>(ei, ea, out);
    cudaEventRecord(evAlpha, sB);

    k_agg2  <<<gridA2, 256, 0, sA>>>(b2, Wa, ba);
    k_head  <<<1, 1024, 0, sA>>>(cash, sidx, Wc, bc, ns, out);
    cudaEventRecord(evEnd, sA);

    // join both streams back into the harness stream
    cudaStreamWaitEvent(0, evEnd, 0);
    cudaStreamWaitEvent(0, evAlpha, 0);
}

// round 12
// speedup vs baseline: 2.4980x; 1.0812x over previous
#include <cuda_runtime.h>
#include <cuda_fp16.h>
#include <math.h>

// ---------------- problem constants ----------------
#define Nn    50000
#define Ee    1600000
#define EF    1650000          // E + N self loops
#define INF_  3.402823466e38f
#define SCANB 13               // scan blocks: 13*1024 int4 = 53248 >= 12500

// output layout (float32, flattened in return order)
#define W_OFF  0               // weights [25001]
#define V_OFF  25001           // value   [1]
#define EI_OFF 25002           // edge_index_full [2, EF]
#define A1_OFF (25002 + 2*EF)  // alpha1 [EF, 4]  (8B-aligned only!)

// ---------------- device scratch ----------------
// node record: rec[2n] = ss1 (fp32 x4), rec[2n+1] = x (fp16 x5, packed, padded)
__device__ __align__(16) float4 g_rec [Nn*2];
__device__ __align__(16) float  g_sdd1[Nn*8];    // [sd1(4) | den1(4)] per node
__device__ __align__(16) __half g_h2h [Nn*32];   // layer2 features, fp16 (32 ch)
__device__ float g_ss2[Nn], g_sd2[Nn];
__device__ float g_scores[Nn];
__device__ float g_gsum[32];
__device__ float g_wsum;                         // softmax denominator
__device__ float g_eap[512];                     // easum partials (overwrite-only)
__device__ float g_eamean;
__device__ __align__(16) float g_c1[4];
__device__ float g_c2;
__device__ float g_Ms[20], g_Md[20];             // (5 x 4) score matrices: x @ M = s
// CSR-by-dst structures (real edges only; self loops handled analytically)
__device__ __align__(16) int g_cnt[Nn];          // zero at start (BSS / self-restored)
__device__ __align__(16) int g_off[Nn + 4];
__device__ __align__(16) int g_pos[Nn];
__device__ __align__(16) unsigned g_sa[Ee];      // [fp16 a | uint16 src] per edge
__device__ int g_bpref[32];                      // mailboxes: 0 = empty, v = prefix+1

// ---------------- helpers ----------------
__device__ __forceinline__ float wredsum(float v) {
#pragma unroll
    for (int o = 16; o; o >>= 1) v += __shfl_xor_sync(0xffffffffu, v, o);
    return v;
}
__device__ __forceinline__ float lrelu(float x) { return x >= 0.f ? x : 0.2f * x; }
__device__ __forceinline__ float elu(float x)   { return x > 0.f ? x : expm1f(x); }
__device__ __forceinline__ int   sa_src(unsigned q) { return (int)(q & 0xFFFFu); }
__device__ __forceinline__ float sa_a(unsigned q) {
    return __half2float(__ushort_as_half((unsigned short)(q >> 16)));
}

// ---------------- kernels ----------------
// easum partials: overwrite-only, no pre-zeroing needed
__global__ void k_easum(const float* __restrict__ ea) {
    float s = 0.f;
    for (int i = blockIdx.x * blockDim.x + threadIdx.x; i < Ee; i += gridDim.x * blockDim.x)
        s += ea[i];
    s = wredsum(s);
    __shared__ float sm[8];
    int lane = threadIdx.x & 31, w = threadIdx.x >> 5;
    if (lane == 0) sm[w] = s;
    __syncthreads();
    if (threadIdx.x == 0) {
        float b = 0.f;
        for (int i = 0; i < (int)(blockDim.x >> 5); i++) b += sm[i];
        g_eap[blockIdx.x] = b;
    }
}

// consts: c1/c2/eamean (from partials) + score matrices Ms/Md (5x4)
__global__ void k_consts(const float* __restrict__ W1,
                         const float* __restrict__ as1, const float* __restrict__ ad1,
                         const float* __restrict__ We1, const float* __restrict__ ae1,
                         const float* __restrict__ We2, const float* __restrict__ ae2) {
    __shared__ float esm[4];
    int t = threadIdx.x;            // 128 threads; warp == head
    int lane = t & 31, h = t >> 5;
    // reduce easum partials
    float es = 0.f;
    for (int i = t; i < 512; i += 128) es += g_eap[i];
    es = wredsum(es);
    if (lane == 0) esm[h] = es;
    float p = We1[t] * ae1[t];
    p = wredsum(p);
    if (lane == 0) g_c1[h] = p;
    float asv = as1[t], adv = ad1[t];
#pragma unroll
    for (int k = 0; k < 5; k++) {
        float ms = wredsum(W1[k*128 + t] * asv);
        float md = wredsum(W1[k*128 + t] * adv);
        if (lane == 0) { g_Ms[k*4 + h] = ms; g_Md[k*4 + h] = md; }
    }
    if (t < 32) {
        float q = We2[t] * ae2[t];
        q = wredsum(q);
        if (t == 0) g_c2 = q;
    }
    __syncthreads();
    if (t == 0) g_eamean = (esm[0] + esm[1] + esm[2] + esm[3]) * (1.0f / Ee);
}

// emit edge_index_full output (depends only on ei) — runs on side stream
__global__ void k_eif(const int* __restrict__ ei, float* __restrict__ out) {
    int e = blockIdx.x * blockDim.x + threadIdx.x;
    if (e >= EF) return;
    int s, d;
    if (e < Ee) { s = ei[e]; d = ei[Ee + e]; }
    else        { s = e - Ee; d = s; }
    out[EI_OFF + e]      = (float)s;
    out[EI_OFF + EF + e] = (float)d;
}

// histogram of dst over real edges (g_cnt arrives zeroed: BSS on first run,
// re-zeroed by k_scan on every run)
__global__ void k_hist(const int* __restrict__ ei) {
    int e = blockIdx.x * blockDim.x + threadIdx.x;
    if (e >= Ee) return;
    atomicAdd(&g_cnt[ei[Ee + e]], 1);
}

// decoupled chained scan: SCANB blocks x 1024 threads, one int4 per thread.
// Self-restoring: zeroes g_cnt after reading, mailboxes use +1 encoding with
// consumer reset (0 = empty = initial BSS state). Also zeroes g_gsum/g_wsum.
__global__ void __launch_bounds__(1024) k_scan() {
    __shared__ int wsum[32];
    __shared__ int s_pref;
    const int M4 = Nn / 4;                 // 12500
    int b = blockIdx.x, t = threadIdx.x, lane = t & 31, w = t >> 5;
    if (b == 0) {
        if (t < 32) g_gsum[t] = 0.f;
        if (t == 32) g_wsum = 0.f;
    }
    int idx = b * 1024 + t;
    int4 v = (idx < M4) ? ((const int4*)g_cnt)[idx] : make_int4(0, 0, 0, 0);
    if (idx < M4) ((int4*)g_cnt)[idx] = make_int4(0, 0, 0, 0);   // restore for replay
    int tsum = v.x + v.y + v.z + v.w;
    int val = tsum;
#pragma unroll
    for (int o = 1; o < 32; o <<= 1) { int x = __shfl_up_sync(0xffffffffu, val, o); if (lane >= o) val += x; }
    if (lane == 31) wsum[w] = val;
    __syncthreads();
    if (w == 0) {
        int x = wsum[lane];
#pragma unroll
        for (int o = 1; o < 32; o <<= 1) { int y = __shfl_up_sync(0xffffffffu, x, o); if (lane >= o) x += y; }
        wsum[lane] = x;
    }
    __syncthreads();
    int btot = wsum[31];
    int excl = ((w > 0) ? wsum[w - 1] : 0) + val - tsum;   // exclusive within block
    if (t == 0) {
        int pref = 0;
        if (b > 0) {
            int m;
            while ((m = atomicAdd(&g_bpref[b], 0)) == 0) __nanosleep(64);
            pref = m - 1;
            atomicExch(&g_bpref[b], 0);                    // reset mailbox for replay
        }
        atomicExch(&g_bpref[b + 1], pref + btot + 1);
        s_pref = pref;
    }
    __syncthreads();
    int base = s_pref;
    if (idx < M4) {
        int4 o;
        o.x = base + excl; o.y = o.x + v.x; o.z = o.y + v.y; o.w = o.z + v.z;
        ((int4*)g_off)[idx] = o;
        ((int4*)g_pos)[idx] = o;
        if (idx == M4 - 1) g_off[Nn] = o.w + v.w;
    }
}

// scatter real edges into CSR order as packed (fp16 a | uint16 src)
__global__ void k_scatter(const int* __restrict__ ei, const float* __restrict__ ea) {
    int e = blockIdx.x * blockDim.x + threadIdx.x;
    if (e >= Ee) return;
    int s = ei[e], d = ei[Ee + e];
    unsigned ah = (unsigned)__half_as_ushort(__float2half_rn(ea[e]));
    int p = atomicAdd(&g_pos[d], 1);
    g_sa[p] = (unsigned)s | (ah << 16);
}

// node prep: thread per node. ss1/sd1 = x @ Ms/Md (5x4). Writes the packed
// node record [ss1 fp32 | x fp16] and sd1. h1 is NEVER materialized.
__global__ void k_node1(const float* __restrict__ x) {
    __shared__ float Ms[20], Md[20];
    int t = threadIdx.x;
    if (t < 20) { Ms[t] = g_Ms[t]; Md[t] = g_Md[t]; }
    __syncthreads();
    int stride = gridDim.x * blockDim.x;
    for (int n = blockIdx.x * blockDim.x + t; n < Nn; n += stride) {
        float xk[5];
#pragma unroll
        for (int k = 0; k < 5; k++) xk[k] = x[n*5 + k];
        float ss[4] = {0,0,0,0}, sd[4] = {0,0,0,0};
#pragma unroll
        for (int k = 0; k < 5; k++)
#pragma unroll
            for (int h = 0; h < 4; h++) {
                ss[h] += xk[k] * Ms[k*4 + h];
                sd[h] += xk[k] * Md[k*4 + h];
            }
        g_rec[2*n] = make_float4(ss[0], ss[1], ss[2], ss[3]);
        __half2 p01 = __floats2half2_rn(xk[0], xk[1]);
        __half2 p23 = __floats2half2_rn(xk[2], xk[3]);
        __half2 p4z = __floats2half2_rn(xk[4], 0.f);
        uint4 u;
        u.x = *reinterpret_cast<unsigned*>(&p01);
        u.y = *reinterpret_cast<unsigned*>(&p23);
        u.z = *reinterpret_cast<unsigned*>(&p4z);
        u.w = 0u;
        ((uint4*)g_rec)[2*n + 1] = u;
        ((float4*)g_sdd1)[n*2] = make_float4(sd[0], sd[1], sd[2], sd[3]);
    }
}

// FUSED layer-1 aggregation + layer-2 projection: warp per node, LANE PER EDGE.
__global__ void __launch_bounds__(256) k_agg1f(
        const float* __restrict__ W1, const float* __restrict__ W2,
        const float* __restrict__ b1,
        const float* __restrict__ as2, const float* __restrict__ ad2) {
    __shared__ float W1s[640];
    __shared__ float W2s[128*32];
    __shared__ float hs[8][128];
    int t = threadIdx.x, lane = t & 31, w = t >> 5;
    for (int i = t; i < 640; i += 256) W1s[i] = W1[i];
    for (int i = t; i < 4096; i += 256) W2s[i] = W2[i];
    __syncthreads();
    int warp = (blockIdx.x * blockDim.x + t) >> 5;
    int nwarps = (gridDim.x * blockDim.x) >> 5;
    float4 cc = *(const float4*)g_c1;
    float eam = g_eamean;
    float4 bb = ((const float4*)b1)[lane];
    float asv = as2[lane], adv = ad2[lane];
    int hl = lane >> 3;                      // this lane's output head
    for (int d = warp; d < Nn; d += nwarps) {
        int beg = g_off[d], end = g_off[d+1];
        float4 sdv = ((const float4*)g_sdd1)[d*2];
        float den[4] = {0,0,0,0};
        float ax[4][5] = {{0,0,0,0,0},{0,0,0,0,0},{0,0,0,0,0},{0,0,0,0,0}};
        // self loop (lane 0): src = d, a = eamean
        if (lane == 0) {
            float4 ssv = g_rec[2*d];
            uint4 xp = ((const uint4*)g_rec)[2*d + 1];
            float2 x01 = __half22float2(*(__half2*)&xp.x);
            float2 x23 = __half22float2(*(__half2*)&xp.y);
            float2 x4_ = __half22float2(*(__half2*)&xp.z);
            float xk[5] = {x01.x, x01.y, x23.x, x23.y, x4_.x};
            float nh[4];
            nh[0] = __expf(lrelu(ssv.x + sdv.x + eam*cc.x));
            nh[1] = __expf(lrelu(ssv.y + sdv.y + eam*cc.y));
            nh[2] = __expf(lrelu(ssv.z + sdv.z + eam*cc.z));
            nh[3] = __expf(lrelu(ssv.w + sdv.w + eam*cc.w));
#pragma unroll
            for (int h = 0; h < 4; h++) {
                den[h] += nh[h];
#pragma unroll
                for (int k = 0; k < 5; k++) ax[h][k] += nh[h]*xk[k];
            }
        }
        // real edges: lane-striped (contiguous, coalesced metadata)
        for (int i = beg + lane; i < end; i += 32) {
            unsigned m = g_sa[i];
            int s = sa_src(m);
            float a = sa_a(m);
            float4 ssv = g_rec[2*s];
            uint4 xp = ((const uint4*)g_rec)[2*s + 1];
            float2 x01 = __half22float2(*(__half2*)&xp.x);
            float2 x23 = __half22float2(*(__half2*)&xp.y);
            float2 x4_ = __half22float2(*(__half2*)&xp.z);
            float xk[5] = {x01.x, x01.y, x23.x, x23.y, x4_.x};
            float nh[4];
            nh[0] = __expf(lrelu(ssv.x + sdv.x + a*cc.x));
            nh[1] = __expf(lrelu(ssv.y + sdv.y + a*cc.y));
            nh[2] = __expf(lrelu(ssv.z + sdv.z + a*cc.z));
            nh[3] = __expf(lrelu(ssv.w + sdv.w + a*cc.w));
#pragma unroll
            for (int h = 0; h < 4; h++) {
                den[h] += nh[h];
#pragma unroll
                for (int k = 0; k < 5; k++) ax[h][k] += nh[h]*xk[k];
            }
        }
        // reduce 24 partials across the warp (butterfly: result in all lanes)
#pragma unroll
        for (int h = 0; h < 4; h++) den[h] = wredsum(den[h]);
#pragma unroll
        for (int h = 0; h < 4; h++)
#pragma unroll
            for (int k = 0; k < 5; k++) ax[h][k] = wredsum(ax[h][k]);
        if (lane == 0)
            ((float4*)g_sdd1)[d*2 + 1] = make_float4(den[0], den[1], den[2], den[3]);
        float axh[5], denh;
        denh = (hl == 0) ? den[0] : (hl == 1) ? den[1] : (hl == 2) ? den[2] : den[3];
#pragma unroll
        for (int k = 0; k < 5; k++)
            axh[k] = (hl == 0) ? ax[0][k] : (hl == 1) ? ax[1][k] : (hl == 2) ? ax[2][k] : ax[3][k];
        float inv = 1.0f / (denh + 1e-16f);
        float hv[4];
#pragma unroll
        for (int j = 0; j < 4; j++) {
            int chn = lane*4 + j;
            float o = axh[0]*W1s[chn] + axh[1]*W1s[128+chn] + axh[2]*W1s[256+chn]
                    + axh[3]*W1s[384+chn] + axh[4]*W1s[512+chn];
            hv[j] = o * inv;
        }
        hs[w][lane*4+0] = elu(hv[0] + bb.x);
        hs[w][lane*4+1] = elu(hv[1] + bb.y);
        hs[w][lane*4+2] = elu(hv[2] + bb.z);
        hs[w][lane*4+3] = elu(hv[3] + bb.w);
        __syncwarp();
        float acc2 = 0.f;
#pragma unroll 16
        for (int j = 0; j < 128; j++)
            acc2 += hs[w][j] * W2s[j*32 + lane];
        g_h2h[d*32 + lane] = __float2half_rn(acc2);
        float ps = wredsum(acc2 * asv);
        float pd = wredsum(acc2 * adv);
        if (lane == 0) { g_ss2[d] = ps; g_sd2[d] = pd; }
        __syncwarp();
    }
}

// edge-parallel alpha1 writer: original edge order -> coalesced output stores
__global__ void k_alphaE(const int* __restrict__ ei, const float* __restrict__ ea,
                         float* __restrict__ out) {
    int e = blockIdx.x * blockDim.x + threadIdx.x;
    if (e >= EF) return;
    int s, d; float a;
    if (e < Ee) { s = ei[e]; d = ei[Ee + e]; a = ea[e]; }
    else        { s = e - Ee; d = s; a = g_eamean; }
    float4 ss = g_rec[2*s];
    float4 sd = ((const float4*)g_sdd1)[d*2];
    float4 dd = ((const float4*)g_sdd1)[d*2 + 1];
    float n0 = __expf(lrelu(ss.x + sd.x + a*g_c1[0])) / (dd.x + 1e-16f);
    float n1 = __expf(lrelu(ss.y + sd.y + a*g_c1[1])) / (dd.y + 1e-16f);
    float n2 = __expf(lrelu(ss.z + sd.z + a*g_c1[2])) / (dd.z + 1e-16f);
    float n3 = __expf(lrelu(ss.w + sd.w + a*g_c1[3])) / (dd.w + 1e-16f);
    float2* ao = (float2*)(out + A1_OFF + 4*e);
    ao[0] = make_float2(n0, n1);
    ao[1] = make_float2(n2, n3);
}

// layer-2 aggregation + final node head: warp per node, unroll x4, analytic self loop
__global__ void __launch_bounds__(256) k_agg2(
        const float* __restrict__ b2, const float* __restrict__ Wa,
        const float* __restrict__ ba) {
    __shared__ float sacc[32];
    int t = threadIdx.x, lane = t & 31;
    if (t < 32) sacc[t] = 0.f;
    __syncthreads();
    int warp = (blockIdx.x * blockDim.x + t) >> 5;
    int nwarps = (gridDim.x * blockDim.x) >> 5;
    float c = g_c2, eam = g_eamean;
    float bl = b2[lane], wl = Wa[lane], bb = ba[0];
    float gacc = 0.f;
    for (int d = warp; d < Nn; d += nwarps) {
        int beg = g_off[d], end = g_off[d+1];
        float sdv = g_sd2[d];
        float nself = __expf(lrelu(g_ss2[d] + sdv + eam*c));
        float acc = nself * __half2float(g_h2h[d*32 + lane]);
        float den = nself;
        int i = beg;
        for (; i + 3 < end; i += 4) {
            unsigned e0 = g_sa[i], e1 = g_sa[i+1], e2 = g_sa[i+2], e3 = g_sa[i+3];
            int s0 = sa_src(e0), s1 = sa_src(e1), s2 = sa_src(e2), s3 = sa_src(e3);
            float ss0 = g_ss2[s0], ss1v = g_ss2[s1];
            float ss2v = g_ss2[s2], ss3v = g_ss2[s3];
            float v0 = __half2float(g_h2h[s0*32 + lane]);
            float v1 = __half2float(g_h2h[s1*32 + lane]);
            float v2 = __half2float(g_h2h[s2*32 + lane]);
            float v3 = __half2float(g_h2h[s3*32 + lane]);
            float n0 = __expf(lrelu(ss0  + sdv + sa_a(e0)*c));
            float n1 = __expf(lrelu(ss1v + sdv + sa_a(e1)*c));
            float n2 = __expf(lrelu(ss2v + sdv + sa_a(e2)*c));
            float n3 = __expf(lrelu(ss3v + sdv + sa_a(e3)*c));
            den += (n0 + n1) + (n2 + n3);
            acc += n0*v0 + n1*v1 + n2*v2 + n3*v3;
        }
        for (; i < end; i++) {
            unsigned e0 = g_sa[i];
            int s0 = sa_src(e0);
            float n0 = __expf(lrelu(g_ss2[s0] + sdv + sa_a(e0)*c));
            den += n0;
            acc += n0 * __half2float(g_h2h[s0*32 + lane]);
        }
        float v = elu(acc / (den + 1e-16f) + bl);
        gacc += v;
        float p = wredsum(v * wl);
        if (lane == 0) g_scores[d] = p + bb;
    }
    atomicAdd(&sacc[lane], gacc);
    __syncthreads();
    if (t < 32) atomicAdd(&g_gsum[t], sacc[t]);
}

// parallel softmax head, pass 1: numerators to out + global denom.
// Scores are O(1) so exp without max-shift is safe (softmax shift-invariant).
__global__ void k_hsum(const float* __restrict__ cash, const int* __restrict__ stock_idx,
                       int ns, float* __restrict__ out) {
    __shared__ float sm[8];
    int i = blockIdx.x * blockDim.x + threadIdx.x;
    int lane = threadIdx.x & 31, w = threadIdx.x >> 5;
    float e = 0.f;
    if (i <= ns) {
        float v = (i == 0) ? cash[0] : g_scores[stock_idx[i-1]];
        e = __expf(v);
        out[W_OFF + i] = e;
    }
    float s = wredsum(e);
    if (lane == 0) sm[w] = s;
    __syncthreads();
    if (threadIdx.x == 0) {
        float b = 0.f;
        for (int j = 0; j < (int)(blockDim.x >> 5); j++) b += sm[j];
        atomicAdd(&g_wsum, b);
    }
}

// pass 2: scale weights in place + critic value
__global__ void k_hout(const float* __restrict__ Wc, const float* __restrict__ bc,
                       int ns, float* __restrict__ out) {
    if (blockIdx.x == 0 && threadIdx.x < 32) {
        float p = wredsum(g_gsum[threadIdx.x] * (1.0f / Nn) * Wc[threadIdx.x]);
        if (threadIdx.x == 0) out[V_OFF] = p + bc[0];
    }
    int i = blockIdx.x * blockDim.x + threadIdx.x;
    if (i <= ns) out[W_OFF + i] *= (1.0f / g_wsum);
}

// ---------------- launch ----------------
extern "C" void kernel_launch(void* const* d_in, const int* in_sizes, int n_in,
                              void* d_out, int out_size) {
    const float* x    = (const float*)d_in[0];
    const float* ea   = (const float*)d_in[1];
    const float* W1   = (const float*)d_in[2];
    const float* as1  = (const float*)d_in[3];
    const float* ad1  = (const float*)d_in[4];
    const float* We1  = (const float*)d_in[5];
    const float* ae1  = (const float*)d_in[6];
    const float* b1   = (const float*)d_in[7];
    const float* W2   = (const float*)d_in[8];
    const float* as2  = (const float*)d_in[9];
    const float* ad2  = (const float*)d_in[10];
    const float* We2  = (const float*)d_in[11];
    const float* ae2  = (const float*)d_in[12];
    const float* b2   = (const float*)d_in[13];
    const float* Wa   = (const float*)d_in[14];
    const float* ba   = (const float*)d_in[15];
    const float* cash = (const float*)d_in[16];
    const float* Wc   = (const float*)d_in[17];
    const float* bc   = (const float*)d_in[18];
    const int*   ei   = (const int*)  d_in[19];
    const int*   sidx = (const int*)  d_in[20];
    float* out = (float*)d_out;
    int ns = in_sizes[20];

    // lazy one-time stream/event/occupancy setup (host-side objects only)
    static cudaStream_t sA = nullptr, sB = nullptr;
    static cudaEvent_t evFork, evNode1, evAgg1, evAlpha, evEnd;
    static int gridA1 = 0, gridA2 = 0;
    if (!sA) {
        cudaStreamCreateWithFlags(&sA, cudaStreamNonBlocking);
        cudaStreamCreateWithFlags(&sB, cudaStreamNonBlocking);
        cudaEventCreateWithFlags(&evFork,  cudaEventDisableTiming);
        cudaEventCreateWithFlags(&evNode1, cudaEventDisableTiming);
        cudaEventCreateWithFlags(&evAgg1,  cudaEventDisableTiming);
        cudaEventCreateWithFlags(&evAlpha, cudaEventDisableTiming);
        cudaEventCreateWithFlags(&evEnd,   cudaEventDisableTiming);
        int sms = 148, nb = 0;
        cudaDeviceGetAttribute(&sms, cudaDevAttrMultiProcessorCount, 0);
        cudaOccupancyMaxActiveBlocksPerMultiprocessor(&nb, k_agg1f, 256, 0);
        gridA1 = (nb > 0 ? nb : 4) * sms;
        cudaOccupancyMaxActiveBlocksPerMultiprocessor(&nb, k_agg2, 256, 0);
        gridA2 = (nb > 0 ? nb : 8) * sms;
        if (gridA2 > 6250) gridA2 = 6250;   // no more than one warp per node
        if (gridA1 > 6250) gridA1 = 6250;
    }

    // fork from the harness's (captured) stream
    cudaEventRecord(evFork, 0);
    cudaStreamWaitEvent(sA, evFork, 0);
    cudaStreamWaitEvent(sB, evFork, 0);

    // stream B: easum -> consts (+M matrices) -> node1 -> edge_index_full
    k_easum <<<512, 256, 0, sB>>>(ea);
    k_consts<<<1, 128, 0, sB>>>(W1, as1, ad1, We1, ae1, We2, ae2);
    k_node1 <<<196, 256, 0, sB>>>(x);
    cudaEventRecord(evNode1, sB);      // implies consts done too
    k_eif   <<<(EF + 255) / 256, 256, 0, sB>>>(ei, out);

    // stream A: CSR build -> fused agg+proj -> agg2 -> head
    k_hist   <<<(Ee + 255) / 256, 256, 0, sA>>>(ei);
    k_scan   <<<SCANB, 1024, 0, sA>>>();
    k_scatter<<<(Ee + 255) / 256, 256, 0, sA>>>(ei, ea);
    cudaStreamWaitEvent(sA, evNode1, 0);                // records, sd1, consts
    k_agg1f  <<<gridA1, 256, 0, sA>>>(W1, W2, b1, as2, ad2);
    cudaEventRecord(evAgg1, sA);

    // stream B: alpha writer overlaps agg2 (disjoint data)
    cudaStreamWaitEvent(sB, evAgg1, 0);                 // denominators
    k_alphaE<<<(EF + 255) / 256, 256, 0, sB>>>(ei, ea, out);
    cudaEventRecord(evAlpha, sB);

    k_agg2  <<<gridA2, 256, 0, sA>>>(b2, Wa, ba);
    k_hsum  <<<(ns + 256) / 256, 256, 0, sA>>>(cash, sidx, ns, out);
    k_hout  <<<(ns + 256) / 256, 256, 0, sA>>>(Wc, bc, ns, out);
    cudaEventRecord(evEnd, sA);

    // join both streams back into the harness stream
    cudaStreamWaitEvent(0, evEnd, 0);
    cudaStreamWaitEvent(0, evAlpha, 0);
}

// round 13
// speedup vs baseline: 2.5910x; 1.0372x over previous
#include <cuda_runtime.h>
#include <cuda_fp16.h>
#include <math.h>

// ---------------- problem constants ----------------
#define Nn    50000
#define Ee    1600000
#define EF    1650000          // E + N self loops
#define INF_  3.402823466e38f
#define SCANB 13               // scan blocks: 13*1024 int4 = 53248 >= 12500

// output layout (float32, flattened in return order)
#define W_OFF  0               // weights [25001]
#define V_OFF  25001           // value   [1]
#define EI_OFF 25002           // edge_index_full [2, EF]
#define A1_OFF (25002 + 2*EF)  // alpha1 [EF, 4]  (8B-aligned only!)

// ---------------- device scratch ----------------
// node record: rec[2n] = ss1 (fp32 x4), rec[2n+1] = x (fp16 x5, packed, padded)
__device__ __align__(16) float4 g_rec [Nn*2];
__device__ __align__(16) float  g_sdd1[Nn*8];    // [sd1(4) | den1(4)] per node
__device__ __align__(16) __half g_h2h [Nn*32];   // layer2 features, fp16 (32 ch)
__device__ float g_ss2[Nn], g_sd2[Nn];
__device__ float g_scores[Nn];
__device__ float g_gsum[32];
__device__ float g_wsum;                         // softmax denominator
__device__ int   g_hctr;                         // head grid-barrier counter
__device__ float g_eap[512];                     // easum partials (overwrite-only)
__device__ float g_eamean;
__device__ __align__(16) float g_c1[4];
__device__ float g_c2;
__device__ float g_Ms[20], g_Md[20];             // (5 x 4) score matrices: x @ M = s
// CSR-by-dst structures (real edges only; self loops handled analytically)
__device__ __align__(16) int g_cnt[Nn];          // zero at start (BSS / self-restored)
__device__ __align__(16) int g_off[Nn + 4];
__device__ __align__(16) int g_pos[Nn];
__device__ __align__(16) unsigned g_sa[Ee];      // [fp16 a | uint16 src] per edge
__device__ int g_bpref[32];                      // mailboxes: 0 = empty, v = prefix+1

// ---------------- helpers ----------------
__device__ __forceinline__ float wredsum(float v) {
#pragma unroll
    for (int o = 16; o; o >>= 1) v += __shfl_xor_sync(0xffffffffu, v, o);
    return v;
}
__device__ __forceinline__ float lrelu(float x) { return x >= 0.f ? x : 0.2f * x; }
__device__ __forceinline__ float elu(float x)   { return x > 0.f ? x : expm1f(x); }
__device__ __forceinline__ int   sa_src(unsigned q) { return (int)(q & 0xFFFFu); }
__device__ __forceinline__ float sa_a(unsigned q) {
    return __half2float(__ushort_as_half((unsigned short)(q >> 16)));
}

// ---------------- kernels ----------------
// easum partials: overwrite-only, no pre-zeroing needed
__global__ void k_easum(const float* __restrict__ ea) {
    float s = 0.f;
    for (int i = blockIdx.x * blockDim.x + threadIdx.x; i < Ee; i += gridDim.x * blockDim.x)
        s += ea[i];
    s = wredsum(s);
    __shared__ float sm[8];
    int lane = threadIdx.x & 31, w = threadIdx.x >> 5;
    if (lane == 0) sm[w] = s;
    __syncthreads();
    if (threadIdx.x == 0) {
        float b = 0.f;
        for (int i = 0; i < (int)(blockDim.x >> 5); i++) b += sm[i];
        g_eap[blockIdx.x] = b;
    }
}

// consts: c1/c2/eamean (from partials) + score matrices Ms/Md (5x4)
__global__ void k_consts(const float* __restrict__ W1,
                         const float* __restrict__ as1, const float* __restrict__ ad1,
                         const float* __restrict__ We1, const float* __restrict__ ae1,
                         const float* __restrict__ We2, const float* __restrict__ ae2) {
    __shared__ float esm[4];
    int t = threadIdx.x;            // 128 threads; warp == head
    int lane = t & 31, h = t >> 5;
    float es = 0.f;
    for (int i = t; i < 512; i += 128) es += g_eap[i];
    es = wredsum(es);
    if (lane == 0) esm[h] = es;
    float p = We1[t] * ae1[t];
    p = wredsum(p);
    if (lane == 0) g_c1[h] = p;
    float asv = as1[t], adv = ad1[t];
#pragma unroll
    for (int k = 0; k < 5; k++) {
        float ms = wredsum(W1[k*128 + t] * asv);
        float md = wredsum(W1[k*128 + t] * adv);
        if (lane == 0) { g_Ms[k*4 + h] = ms; g_Md[k*4 + h] = md; }
    }
    if (t < 32) {
        float q = We2[t] * ae2[t];
        q = wredsum(q);
        if (t == 0) g_c2 = q;
    }
    __syncthreads();
    if (t == 0) g_eamean = (esm[0] + esm[1] + esm[2] + esm[3]) * (1.0f / Ee);
}

// emit edge_index_full: 2 edges/thread, int2 loads + float2 stores (8B-aligned dst)
__global__ void k_eif(const int* __restrict__ ei, float* __restrict__ out) {
    int p = blockIdx.x * blockDim.x + threadIdx.x;   // pair index
    int e = p * 2;
    if (e >= EF) return;
    float s0, s1, d0, d1;
    if (e < Ee) {        // Ee even: pair never straddles the boundary
        int2 sp = ((const int2*)ei)[p];
        int2 dp = *(const int2*)(ei + Ee + e);
        s0 = (float)sp.x; s1 = (float)sp.y;
        d0 = (float)dp.x; d1 = (float)dp.y;
    } else {
        s0 = d0 = (float)(e - Ee);
        s1 = d1 = (float)(e - Ee + 1);
    }
    *(float2*)(out + EI_OFF + e)      = make_float2(s0, s1);
    *(float2*)(out + EI_OFF + EF + e) = make_float2(d0, d1);
}

// histogram of dst over real edges: 4 edges/thread (int4 load + 4 REDs)
__global__ void k_hist(const int* __restrict__ ei) {
    int q = blockIdx.x * blockDim.x + threadIdx.x;   // quad index
    if (q * 4 >= Ee) return;
    int4 d = *(const int4*)(ei + Ee + q * 4);
    atomicAdd(&g_cnt[d.x], 1);
    atomicAdd(&g_cnt[d.y], 1);
    atomicAdd(&g_cnt[d.z], 1);
    atomicAdd(&g_cnt[d.w], 1);
}

// decoupled chained scan: self-restoring (zeroes g_cnt, resets mailboxes,
// zeroes g_gsum/g_wsum/g_hctr).
__global__ void __launch_bounds__(1024) k_scan() {
    __shared__ int wsum[32];
    __shared__ int s_pref;
    const int M4 = Nn / 4;                 // 12500
    int b = blockIdx.x, t = threadIdx.x, lane = t & 31, w = t >> 5;
    if (b == 0) {
        if (t < 32) g_gsum[t] = 0.f;
        if (t == 32) g_wsum = 0.f;
        if (t == 33) g_hctr = 0;
    }
    int idx = b * 1024 + t;
    int4 v = (idx < M4) ? ((const int4*)g_cnt)[idx] : make_int4(0, 0, 0, 0);
    if (idx < M4) ((int4*)g_cnt)[idx] = make_int4(0, 0, 0, 0);   // restore for replay
    int tsum = v.x + v.y + v.z + v.w;
    int val = tsum;
#pragma unroll
    for (int o = 1; o < 32; o <<= 1) { int x = __shfl_up_sync(0xffffffffu, val, o); if (lane >= o) val += x; }
    if (lane == 31) wsum[w] = val;
    __syncthreads();
    if (w == 0) {
        int x = wsum[lane];
#pragma unroll
        for (int o = 1; o < 32; o <<= 1) { int y = __shfl_up_sync(0xffffffffu, x, o); if (lane >= o) x += y; }
        wsum[lane] = x;
    }
    __syncthreads();
    int btot = wsum[31];
    int excl = ((w > 0) ? wsum[w - 1] : 0) + val - tsum;   // exclusive within block
    if (t == 0) {
        int pref = 0;
        if (b > 0) {
            int m;
            while ((m = atomicAdd(&g_bpref[b], 0)) == 0) __nanosleep(64);
            pref = m - 1;
            atomicExch(&g_bpref[b], 0);                    // reset mailbox for replay
        }
        atomicExch(&g_bpref[b + 1], pref + btot + 1);
        s_pref = pref;
    }
    __syncthreads();
    int base = s_pref;
    if (idx < M4) {
        int4 o;
        o.x = base + excl; o.y = o.x + v.x; o.z = o.y + v.y; o.w = o.z + v.z;
        ((int4*)g_off)[idx] = o;
        ((int4*)g_pos)[idx] = o;
        if (idx == M4 - 1) g_off[Nn] = o.w + v.w;
    }
}

// scatter: 4 edges/thread (int4 src/dst, float4 ea loads)
__global__ void k_scatter(const int* __restrict__ ei, const float* __restrict__ ea) {
    int q = blockIdx.x * blockDim.x + threadIdx.x;
    if (q * 4 >= Ee) return;
    int4 s4 = ((const int4*)ei)[q];
    int4 d4 = *(const int4*)(ei + Ee + q * 4);
    float4 a4 = ((const float4*)ea)[q];
    unsigned a0 = (unsigned)__half_as_ushort(__float2half_rn(a4.x));
    unsigned a1 = (unsigned)__half_as_ushort(__float2half_rn(a4.y));
    unsigned a2 = (unsigned)__half_as_ushort(__float2half_rn(a4.z));
    unsigned a3 = (unsigned)__half_as_ushort(__float2half_rn(a4.w));
    int p0 = atomicAdd(&g_pos[d4.x], 1); g_sa[p0] = (unsigned)s4.x | (a0 << 16);
    int p1 = atomicAdd(&g_pos[d4.y], 1); g_sa[p1] = (unsigned)s4.y | (a1 << 16);
    int p2 = atomicAdd(&g_pos[d4.z], 1); g_sa[p2] = (unsigned)s4.z | (a2 << 16);
    int p3 = atomicAdd(&g_pos[d4.w], 1); g_sa[p3] = (unsigned)s4.w | (a3 << 16);
}

// node prep: thread per node. ss1/sd1 = x @ Ms/Md (5x4). Packed node record.
__global__ void k_node1(const float* __restrict__ x) {
    __shared__ float Ms[20], Md[20];
    int t = threadIdx.x;
    if (t < 20) { Ms[t] = g_Ms[t]; Md[t] = g_Md[t]; }
    __syncthreads();
    int stride = gridDim.x * blockDim.x;
    for (int n = blockIdx.x * blockDim.x + t; n < Nn; n += stride) {
        float xk[5];
#pragma unroll
        for (int k = 0; k < 5; k++) xk[k] = x[n*5 + k];
        float ss[4] = {0,0,0,0}, sd[4] = {0,0,0,0};
#pragma unroll
        for (int k = 0; k < 5; k++)
#pragma unroll
            for (int h = 0; h < 4; h++) {
                ss[h] += xk[k] * Ms[k*4 + h];
                sd[h] += xk[k] * Md[k*4 + h];
            }
        g_rec[2*n] = make_float4(ss[0], ss[1], ss[2], ss[3]);
        __half2 p01 = __floats2half2_rn(xk[0], xk[1]);
        __half2 p23 = __floats2half2_rn(xk[2], xk[3]);
        __half2 p4z = __floats2half2_rn(xk[4], 0.f);
        uint4 u;
        u.x = *reinterpret_cast<unsigned*>(&p01);
        u.y = *reinterpret_cast<unsigned*>(&p23);
        u.z = *reinterpret_cast<unsigned*>(&p4z);
        u.w = 0u;
        ((uint4*)g_rec)[2*n + 1] = u;
        ((float4*)g_sdd1)[n*2] = make_float4(sd[0], sd[1], sd[2], sd[3]);
    }
}

// FUSED layer-1 aggregation + layer-2 projection: warp per node, LANE PER EDGE.
__global__ void __launch_bounds__(256) k_agg1f(
        const float* __restrict__ W1, const float* __restrict__ W2,
        const float* __restrict__ b1,
        const float* __restrict__ as2, const float* __restrict__ ad2) {
    __shared__ float W1s[640];
    __shared__ float W2s[128*32];
    __shared__ float hs[8][128];
    int t = threadIdx.x, lane = t & 31, w = t >> 5;
    for (int i = t; i < 640; i += 256) W1s[i] = W1[i];
    for (int i = t; i < 4096; i += 256) W2s[i] = W2[i];
    __syncthreads();
    int warp = (blockIdx.x * blockDim.x + t) >> 5;
    int nwarps = (gridDim.x * blockDim.x) >> 5;
    float4 cc = *(const float4*)g_c1;
    float eam = g_eamean;
    float4 bb = ((const float4*)b1)[lane];
    float asv = as2[lane], adv = ad2[lane];
    int hl = lane >> 3;                      // this lane's output head
    for (int d = warp; d < Nn; d += nwarps) {
        int beg = g_off[d], end = g_off[d+1];
        float4 sdv = ((const float4*)g_sdd1)[d*2];
        float den[4] = {0,0,0,0};
        float ax[4][5] = {{0,0,0,0,0},{0,0,0,0,0},{0,0,0,0,0},{0,0,0,0,0}};
        // self loop (lane 0): src = d, a = eamean
        if (lane == 0) {
            float4 ssv = g_rec[2*d];
            uint4 xp = ((const uint4*)g_rec)[2*d + 1];
            float2 x01 = __half22float2(*(__half2*)&xp.x);
            float2 x23 = __half22float2(*(__half2*)&xp.y);
            float2 x4_ = __half22float2(*(__half2*)&xp.z);
            float xk[5] = {x01.x, x01.y, x23.x, x23.y, x4_.x};
            float nh[4];
            nh[0] = __expf(lrelu(ssv.x + sdv.x + eam*cc.x));
            nh[1] = __expf(lrelu(ssv.y + sdv.y + eam*cc.y));
            nh[2] = __expf(lrelu(ssv.z + sdv.z + eam*cc.z));
            nh[3] = __expf(lrelu(ssv.w + sdv.w + eam*cc.w));
#pragma unroll
            for (int h = 0; h < 4; h++) {
                den[h] += nh[h];
#pragma unroll
                for (int k = 0; k < 5; k++) ax[h][k] += nh[h]*xk[k];
            }
        }
        // real edges: lane-striped (contiguous, coalesced metadata)
        for (int i = beg + lane; i < end; i += 32) {
            unsigned m = g_sa[i];
            int s = sa_src(m);
            float a = sa_a(m);
            float4 ssv = g_rec[2*s];
            uint4 xp = ((const uint4*)g_rec)[2*s + 1];
            float2 x01 = __half22float2(*(__half2*)&xp.x);
            float2 x23 = __half22float2(*(__half2*)&xp.y);
            float2 x4_ = __half22float2(*(__half2*)&xp.z);
            float xk[5] = {x01.x, x01.y, x23.x, x23.y, x4_.x};
            float nh[4];
            nh[0] = __expf(lrelu(ssv.x + sdv.x + a*cc.x));
            nh[1] = __expf(lrelu(ssv.y + sdv.y + a*cc.y));
            nh[2] = __expf(lrelu(ssv.z + sdv.z + a*cc.z));
            nh[3] = __expf(lrelu(ssv.w + sdv.w + a*cc.w));
#pragma unroll
            for (int h = 0; h < 4; h++) {
                den[h] += nh[h];
#pragma unroll
                for (int k = 0; k < 5; k++) ax[h][k] += nh[h]*xk[k];
            }
        }
#pragma unroll
        for (int h = 0; h < 4; h++) den[h] = wredsum(den[h]);
#pragma unroll
        for (int h = 0; h < 4; h++)
#pragma unroll
            for (int k = 0; k < 5; k++) ax[h][k] = wredsum(ax[h][k]);
        if (lane == 0)
            ((float4*)g_sdd1)[d*2 + 1] = make_float4(den[0], den[1], den[2], den[3]);
        float axh[5], denh;
        denh = (hl == 0) ? den[0] : (hl == 1) ? den[1] : (hl == 2) ? den[2] : den[3];
#pragma unroll
        for (int k = 0; k < 5; k++)
            axh[k] = (hl == 0) ? ax[0][k] : (hl == 1) ? ax[1][k] : (hl == 2) ? ax[2][k] : ax[3][k];
        float inv = 1.0f / (denh + 1e-16f);
        float hv[4];
#pragma unroll
        for (int j = 0; j < 4; j++) {
            int chn = lane*4 + j;
            float o = axh[0]*W1s[chn] + axh[1]*W1s[128+chn] + axh[2]*W1s[256+chn]
                    + axh[3]*W1s[384+chn] + axh[4]*W1s[512+chn];
            hv[j] = o * inv;
        }
        hs[w][lane*4+0] = elu(hv[0] + bb.x);
        hs[w][lane*4+1] = elu(hv[1] + bb.y);
        hs[w][lane*4+2] = elu(hv[2] + bb.z);
        hs[w][lane*4+3] = elu(hv[3] + bb.w);
        __syncwarp();
        float acc2 = 0.f;
#pragma unroll 16
        for (int j = 0; j < 128; j++)
            acc2 += hs[w][j] * W2s[j*32 + lane];
        g_h2h[d*32 + lane] = __float2half_rn(acc2);
        float ps = wredsum(acc2 * asv);
        float pd = wredsum(acc2 * adv);
        if (lane == 0) { g_ss2[d] = ps; g_sd2[d] = pd; }
        __syncwarp();
    }
}

// edge-parallel alpha1 writer: original edge order -> coalesced output stores
__global__ void k_alphaE(const int* __restrict__ ei, const float* __restrict__ ea,
                         float* __restrict__ out) {
    int e = blockIdx.x * blockDim.x + threadIdx.x;
    if (e >= EF) return;
    int s, d; float a;
    if (e < Ee) { s = ei[e]; d = ei[Ee + e]; a = ea[e]; }
    else        { s = e - Ee; d = s; a = g_eamean; }
    float4 ss = g_rec[2*s];
    float4 sd = ((const float4*)g_sdd1)[d*2];
    float4 dd = ((const float4*)g_sdd1)[d*2 + 1];
    float n0 = __expf(lrelu(ss.x + sd.x + a*g_c1[0])) / (dd.x + 1e-16f);
    float n1 = __expf(lrelu(ss.y + sd.y + a*g_c1[1])) / (dd.y + 1e-16f);
    float n2 = __expf(lrelu(ss.z + sd.z + a*g_c1[2])) / (dd.z + 1e-16f);
    float n3 = __expf(lrelu(ss.w + sd.w + a*g_c1[3])) / (dd.w + 1e-16f);
    float2* ao = (float2*)(out + A1_OFF + 4*e);
    ao[0] = make_float2(n0, n1);
    ao[1] = make_float2(n2, n3);
}

// layer-2 aggregation + final node head: warp per node, unroll x4, analytic self loop
__global__ void __launch_bounds__(256) k_agg2(
        const float* __restrict__ b2, const float* __restrict__ Wa,
        const float* __restrict__ ba) {
    __shared__ float sacc[32];
    int t = threadIdx.x, lane = t & 31;
    if (t < 32) sacc[t] = 0.f;
    __syncthreads();
    int warp = (blockIdx.x * blockDim.x + t) >> 5;
    int nwarps = (gridDim.x * blockDim.x) >> 5;
    float c = g_c2, eam = g_eamean;
    float bl = b2[lane], wl = Wa[lane], bb = ba[0];
    float gacc = 0.f;
    for (int d = warp; d < Nn; d += nwarps) {
        int beg = g_off[d], end = g_off[d+1];
        float sdv = g_sd2[d];
        float nself = __expf(lrelu(g_ss2[d] + sdv + eam*c));
        float acc = nself * __half2float(g_h2h[d*32 + lane]);
        float den = nself;
        int i = beg;
        for (; i + 3 < end; i += 4) {
            unsigned e0 = g_sa[i], e1 = g_sa[i+1], e2 = g_sa[i+2], e3 = g_sa[i+3];
            int s0 = sa_src(e0), s1 = sa_src(e1), s2 = sa_src(e2), s3 = sa_src(e3);
            float ss0 = g_ss2[s0], ss1v = g_ss2[s1];
            float ss2v = g_ss2[s2], ss3v = g_ss2[s3];
            float v0 = __half2float(g_h2h[s0*32 + lane]);
            float v1 = __half2float(g_h2h[s1*32 + lane]);
            float v2 = __half2float(g_h2h[s2*32 + lane]);
            float v3 = __half2float(g_h2h[s3*32 + lane]);
            float n0 = __expf(lrelu(ss0  + sdv + sa_a(e0)*c));
            float n1 = __expf(lrelu(ss1v + sdv + sa_a(e1)*c));
            float n2 = __expf(lrelu(ss2v + sdv + sa_a(e2)*c));
            float n3 = __expf(lrelu(ss3v + sdv + sa_a(e3)*c));
            den += (n0 + n1) + (n2 + n3);
            acc += n0*v0 + n1*v1 + n2*v2 + n3*v3;
        }
        for (; i < end; i++) {
            unsigned e0 = g_sa[i];
            int s0 = sa_src(e0);
            float n0 = __expf(lrelu(g_ss2[s0] + sdv + sa_a(e0)*c));
            den += n0;
            acc += n0 * __half2float(g_h2h[s0*32 + lane]);
        }
        float v = elu(acc / (den + 1e-16f) + bl);
        gacc += v;
        float p = wredsum(v * wl);
        if (lane == 0) g_scores[d] = p + bb;
    }
    atomicAdd(&sacc[lane], gacc);
    __syncthreads();
    if (t < 32) atomicAdd(&g_gsum[t], sacc[t]);
}

// fused softmax head: single kernel, spin grid barrier (<=148 blocks = 1 wave).
// Numerators stay in registers; one store per element. g_hctr/g_wsum zeroed by
// k_scan each replay. exp without max-shift is safe (scores O(1)).
__global__ void k_headF(const float* __restrict__ cash, const int* __restrict__ stock_idx,
                        const float* __restrict__ Wc, const float* __restrict__ bc,
                        int ns, float* __restrict__ out) {
    __shared__ float sm[8];
    __shared__ float sInv;
    int t = threadIdx.x, lane = t & 31, w = t >> 5;
    int i = blockIdx.x * blockDim.x + t;
    float e = 0.f;
    if (i <= ns) {
        float v = (i == 0) ? cash[0] : g_scores[stock_idx[i-1]];
        e = __expf(v);
    }
    float s = wredsum(e);
    if (lane == 0) sm[w] = s;
    __syncthreads();
    if (t == 0) {
        float b = 0.f;
        for (int j = 0; j < (int)(blockDim.x >> 5); j++) b += sm[j];
        atomicAdd(&g_wsum, b);
        __threadfence();
        atomicAdd(&g_hctr, 1);
    }
    // critic value while waiting (block 0; g_gsum final — agg2 precedes on stream)
    if (blockIdx.x == 0 && t < 32) {
        float p = wredsum(g_gsum[t] * (1.0f / Nn) * Wc[t]);
        if (t == 0) out[V_OFF] = p + bc[0];
    }
    if (t == 0) {
        while (atomicAdd(&g_hctr, 0) < (int)gridDim.x) __nanosleep(32);
        sInv = 1.0f / g_wsum;
    }
    __syncthreads();
    if (i <= ns) out[W_OFF + i] = e * sInv;
}

// ---------------- launch ----------------
extern "C" void kernel_launch(void* const* d_in, const int* in_sizes, int n_in,
                              void* d_out, int out_size) {
    const float* x    = (const float*)d_in[0];
    const float* ea   = (const float*)d_in[1];
    const float* W1   = (const float*)d_in[2];
    const float* as1  = (const float*)d_in[3];
    const float* ad1  = (const float*)d_in[4];
    const float* We1  = (const float*)d_in[5];
    const float* ae1  = (const float*)d_in[6];
    const float* b1   = (const float*)d_in[7];
    const float* W2   = (const float*)d_in[8];
    const float* as2  = (const float*)d_in[9];
    const float* ad2  = (const float*)d_in[10];
    const float* We2  = (const float*)d_in[11];
    const float* ae2  = (const float*)d_in[12];
    const float* b2   = (const float*)d_in[13];
    const float* Wa   = (const float*)d_in[14];
    const float* ba   = (const float*)d_in[15];
    const float* cash = (const float*)d_in[16];
    const float* Wc   = (const float*)d_in[17];
    const float* bc   = (const float*)d_in[18];
    const int*   ei   = (const int*)  d_in[19];
    const int*   sidx = (const int*)  d_in[20];
    float* out = (float*)d_out;
    int ns = in_sizes[20];

    // lazy one-time stream/event/occupancy setup (host-side objects only)
    static cudaStream_t sA = nullptr, sB = nullptr;
    static cudaEvent_t evFork, evNode1, evAgg1, evAlpha, evEnd;
    static int gridA1 = 0, gridA2 = 0;
    if (!sA) {
        cudaStreamCreateWithFlags(&sA, cudaStreamNonBlocking);
        cudaStreamCreateWithFlags(&sB, cudaStreamNonBlocking);
        cudaEventCreateWithFlags(&evFork,  cudaEventDisableTiming);
        cudaEventCreateWithFlags(&evNode1, cudaEventDisableTiming);
        cudaEventCreateWithFlags(&evAgg1,  cudaEventDisableTiming);
        cudaEventCreateWithFlags(&evAlpha, cudaEventDisableTiming);
        cudaEventCreateWithFlags(&evEnd,   cudaEventDisableTiming);
        int sms = 148, nb = 0;
        cudaDeviceGetAttribute(&sms, cudaDevAttrMultiProcessorCount, 0);
        cudaOccupancyMaxActiveBlocksPerMultiprocessor(&nb, k_agg1f, 256, 0);
        gridA1 = (nb > 0 ? nb : 4) * sms;
        cudaOccupancyMaxActiveBlocksPerMultiprocessor(&nb, k_agg2, 256, 0);
        gridA2 = (nb > 0 ? nb : 8) * sms;
        if (gridA2 > 6250) gridA2 = 6250;   // no more than one warp per node
        if (gridA1 > 6250) gridA1 = 6250;
    }

    // fork from the harness's (captured) stream
    cudaEventRecord(evFork, 0);
    cudaStreamWaitEvent(sA, evFork, 0);
    cudaStreamWaitEvent(sB, evFork, 0);

    // stream B: easum -> consts (+M matrices) -> node1 -> edge_index_full
    k_easum <<<512, 256, 0, sB>>>(ea);
    k_consts<<<1, 128, 0, sB>>>(W1, as1, ad1, We1, ae1, We2, ae2);
    k_node1 <<<196, 256, 0, sB>>>(x);
    cudaEventRecord(evNode1, sB);      // implies consts done too
    k_eif   <<<(EF/2 + 255) / 256, 256, 0, sB>>>(ei, out);

    // stream A: CSR build -> fused agg+proj -> agg2 -> head
    k_hist   <<<(Ee/4 + 255) / 256, 256, 0, sA>>>(ei);
    k_scan   <<<SCANB, 1024, 0, sA>>>();
    k_scatter<<<(Ee/4 + 255) / 256, 256, 0, sA>>>(ei, ea);
    cudaStreamWaitEvent(sA, evNode1, 0);                // records, sd1, consts
    k_agg1f  <<<gridA1, 256, 0, sA>>>(W1, W2, b1, as2, ad2);
    cudaEventRecord(evAgg1, sA);

    // stream B: alpha writer overlaps agg2 (disjoint data)
    cudaStreamWaitEvent(sB, evAgg1, 0);                 // denominators
    k_alphaE<<<(EF + 255) / 256, 256, 0, sB>>>(ei, ea, out);
    cudaEventRecord(evAlpha, sB);

    k_agg2  <<<gridA2, 256, 0, sA>>>(b2, Wa, ba);
    k_headF <<<(ns + 256) / 256, 256, 0, sA>>>(cash, sidx, Wc, bc, ns, out);
    cudaEventRecord(evEnd, sA);

    // join both streams back into the harness stream
    cudaStreamWaitEvent(0, evEnd, 0);
    cudaStreamWaitEvent(0, evAlpha, 0);
}

// round 14
// speedup vs baseline: 2.8003x; 1.0808x over previous
#include <cuda_runtime.h>
#include <cuda_fp16.h>
#include <math.h>

// ---------------- problem constants ----------------
#define Nn    50000
#define Ee    1600000
#define EF    1650000          // E + N self loops
#define SCANB 13               // scan blocks: 13*1024 int4 = 53248 >= 12500

// output layout (float32, flattened in return order)
#define W_OFF  0               // weights [25001]
#define V_OFF  25001           // value   [1]
#define EI_OFF 25002           // edge_index_full [2, EF]
#define A1_OFF (25002 + 2*EF)  // alpha1 [EF, 4]  (8B-aligned only!)

// ---------------- device scratch ----------------
// node record: rec[2n] = ss1 (fp32 x4), rec[2n+1] = x (fp16 x5, packed, padded)
__device__ __align__(16) float4 g_rec [Nn*2];
__device__ __align__(16) float  g_sdd1[Nn*8];    // [sd1(4) | den1(4)] per node
__device__ __align__(16) __half g_h2h [Nn*32];   // layer2 features, fp16 (32 ch)
__device__ float g_ss2[Nn], g_sd2[Nn];
__device__ float g_scores[Nn];
__device__ float g_gsum[32];
__device__ float g_wsum;                         // softmax denominator
__device__ int   g_hctr;                         // head grid-barrier counter
__device__ float g_eap[512];                     // easum partials (overwrite-only)
__device__ float g_eamean;
__device__ __align__(16) float g_c1[4];
__device__ float g_c2;
__device__ float g_Ms[20], g_Md[20];             // (5 x 4) score matrices: x @ M = s
// CSR-by-dst structures (real edges only; self loops handled analytically)
__device__ __align__(16) int g_cnt[Nn];          // zero at start (BSS / self-restored)
__device__ __align__(16) int g_off[Nn + 4];
__device__ __align__(16) unsigned short g_rank[Ee];  // within-segment rank per edge
__device__ __align__(16) unsigned g_sa[Ee];      // [fp16 a | uint16 src] per edge
__device__ int g_bpref[32];                      // mailboxes: 0 = empty, v = prefix+1

// ---------------- helpers ----------------
__device__ __forceinline__ float wredsum(float v) {
#pragma unroll
    for (int o = 16; o; o >>= 1) v += __shfl_xor_sync(0xffffffffu, v, o);
    return v;
}
__device__ __forceinline__ float lrelu(float x) { return x >= 0.f ? x : 0.2f * x; }
__device__ __forceinline__ float elu(float x)   { return x > 0.f ? x : expm1f(x); }
__device__ __forceinline__ int   sa_src(unsigned q) { return (int)(q & 0xFFFFu); }
__device__ __forceinline__ float sa_a(unsigned q) {
    return __half2float(__ushort_as_half((unsigned short)(q >> 16)));
}

// ---------------- kernels ----------------
// easum partials: overwrite-only, no pre-zeroing needed
__global__ void k_easum(const float* __restrict__ ea) {
    float s = 0.f;
    for (int i = blockIdx.x * blockDim.x + threadIdx.x; i < Ee; i += gridDim.x * blockDim.x)
        s += ea[i];
    s = wredsum(s);
    __shared__ float sm[8];
    int lane = threadIdx.x & 31, w = threadIdx.x >> 5;
    if (lane == 0) sm[w] = s;
    __syncthreads();
    if (threadIdx.x == 0) {
        float b = 0.f;
        for (int i = 0; i < (int)(blockDim.x >> 5); i++) b += sm[i];
        g_eap[blockIdx.x] = b;
    }
}

// consts: c1/c2/eamean (from partials) + score matrices Ms/Md (5x4)
__global__ void k_consts(const float* __restrict__ W1,
                         const float* __restrict__ as1, const float* __restrict__ ad1,
                         const float* __restrict__ We1, const float* __restrict__ ae1,
                         const float* __restrict__ We2, const float* __restrict__ ae2) {
    __shared__ float esm[4];
    int t = threadIdx.x;            // 128 threads; warp == head
    int lane = t & 31, h = t >> 5;
    float es = 0.f;
    for (int i = t; i < 512; i += 128) es += g_eap[i];
    es = wredsum(es);
    if (lane == 0) esm[h] = es;
    float p = We1[t] * ae1[t];
    p = wredsum(p);
    if (lane == 0) g_c1[h] = p;
    float asv = as1[t], adv = ad1[t];
#pragma unroll
    for (int k = 0; k < 5; k++) {
        float ms = wredsum(W1[k*128 + t] * asv);
        float md = wredsum(W1[k*128 + t] * adv);
        if (lane == 0) { g_Ms[k*4 + h] = ms; g_Md[k*4 + h] = md; }
    }
    if (t < 32) {
        float q = We2[t] * ae2[t];
        q = wredsum(q);
        if (t == 0) g_c2 = q;
    }
    __syncthreads();
    if (t == 0) g_eamean = (esm[0] + esm[1] + esm[2] + esm[3]) * (1.0f / Ee);
}

// emit edge_index_full: 2 edges/thread, int2 loads + float2 stores (8B-aligned dst)
__global__ void k_eif(const int* __restrict__ ei, float* __restrict__ out) {
    int p = blockIdx.x * blockDim.x + threadIdx.x;   // pair index
    int e = p * 2;
    if (e >= EF) return;
    float s0, s1, d0, d1;
    if (e < Ee) {        // Ee even: pair never straddles the boundary
        int2 sp = ((const int2*)ei)[p];
        int2 dp = *(const int2*)(ei + Ee + e);
        s0 = (float)sp.x; s1 = (float)sp.y;
        d0 = (float)dp.x; d1 = (float)dp.y;
    } else {
        s0 = d0 = (float)(e - Ee);
        s1 = d1 = (float)(e - Ee + 1);
    }
    *(float2*)(out + EI_OFF + e)      = make_float2(s0, s1);
    *(float2*)(out + EI_OFF + EF + e) = make_float2(d0, d1);
}

// histogram + rank capture: 4 edges/thread. atomicAdd's return value IS the
// edge's rank within its dst segment (stored u16; max degree << 65536 here).
__global__ void k_hist(const int* __restrict__ ei) {
    int q = blockIdx.x * blockDim.x + threadIdx.x;   // quad index
    if (q * 4 >= Ee) return;
    int4 d = *(const int4*)(ei + Ee + q * 4);
    ushort4 r;
    r.x = (unsigned short)atomicAdd(&g_cnt[d.x], 1);
    r.y = (unsigned short)atomicAdd(&g_cnt[d.y], 1);
    r.z = (unsigned short)atomicAdd(&g_cnt[d.z], 1);
    r.w = (unsigned short)atomicAdd(&g_cnt[d.w], 1);
    ((ushort4*)g_rank)[q] = r;
}

// decoupled chained scan: self-restoring (zeroes g_cnt, resets mailboxes,
// zeroes g_gsum/g_wsum/g_hctr).
__global__ void __launch_bounds__(1024) k_scan() {
    __shared__ int wsum[32];
    __shared__ int s_pref;
    const int M4 = Nn / 4;                 // 12500
    int b = blockIdx.x, t = threadIdx.x, lane = t & 31, w = t >> 5;
    if (b == 0) {
        if (t < 32) g_gsum[t] = 0.f;
        if (t == 32) g_wsum = 0.f;
        if (t == 33) g_hctr = 0;
    }
    int idx = b * 1024 + t;
    int4 v = (idx < M4) ? ((const int4*)g_cnt)[idx] : make_int4(0, 0, 0, 0);
    if (idx < M4) ((int4*)g_cnt)[idx] = make_int4(0, 0, 0, 0);   // restore for replay
    int tsum = v.x + v.y + v.z + v.w;
    int val = tsum;
#pragma unroll
    for (int o = 1; o < 32; o <<= 1) { int x = __shfl_up_sync(0xffffffffu, val, o); if (lane >= o) val += x; }
    if (lane == 31) wsum[w] = val;
    __syncthreads();
    if (w == 0) {
        int x = wsum[lane];
#pragma unroll
        for (int o = 1; o < 32; o <<= 1) { int y = __shfl_up_sync(0xffffffffu, x, o); if (lane >= o) x += y; }
        wsum[lane] = x;
    }
    __syncthreads();
    int btot = wsum[31];
    int excl = ((w > 0) ? wsum[w - 1] : 0) + val - tsum;   // exclusive within block
    if (t == 0) {
        int pref = 0;
        if (b > 0) {
            int m;
            while ((m = atomicAdd(&g_bpref[b], 0)) == 0) __nanosleep(64);
            pref = m - 1;
            atomicExch(&g_bpref[b], 0);                    // reset mailbox for replay
        }
        atomicExch(&g_bpref[b + 1], pref + btot + 1);
        s_pref = pref;
    }
    __syncthreads();
    int base = s_pref;
    if (idx < M4) {
        int4 o;
        o.x = base + excl; o.y = o.x + v.x; o.z = o.y + v.y; o.w = o.z + v.z;
        ((int4*)g_off)[idx] = o;
        if (idx == M4 - 1) g_off[Nn] = o.w + v.w;
    }
}

// scatter: ATOMIC-FREE. slot = off[dst] + rank. 4 edges/thread.
__global__ void k_scatter(const int* __restrict__ ei, const float* __restrict__ ea) {
    int q = blockIdx.x * blockDim.x + threadIdx.x;
    if (q * 4 >= Ee) return;
    int4 s4 = ((const int4*)ei)[q];
    int4 d4 = *(const int4*)(ei + Ee + q * 4);
    float4 a4 = ((const float4*)ea)[q];
    ushort4 r4 = ((const ushort4*)g_rank)[q];
    unsigned a0 = (unsigned)__half_as_ushort(__float2half_rn(a4.x));
    unsigned a1 = (unsigned)__half_as_ushort(__float2half_rn(a4.y));
    unsigned a2 = (unsigned)__half_as_ushort(__float2half_rn(a4.z));
    unsigned a3 = (unsigned)__half_as_ushort(__float2half_rn(a4.w));
    g_sa[g_off[d4.x] + r4.x] = (unsigned)s4.x | (a0 << 16);
    g_sa[g_off[d4.y] + r4.y] = (unsigned)s4.y | (a1 << 16);
    g_sa[g_off[d4.z] + r4.z] = (unsigned)s4.z | (a2 << 16);
    g_sa[g_off[d4.w] + r4.w] = (unsigned)s4.w | (a3 << 16);
}

// node prep: thread per node. ss1/sd1 = x @ Ms/Md (5x4). Packed node record.
__global__ void k_node1(const float* __restrict__ x) {
    __shared__ float Ms[20], Md[20];
    int t = threadIdx.x;
    if (t < 20) { Ms[t] = g_Ms[t]; Md[t] = g_Md[t]; }
    __syncthreads();
    int stride = gridDim.x * blockDim.x;
    for (int n = blockIdx.x * blockDim.x + t; n < Nn; n += stride) {
        float xk[5];
#pragma unroll
        for (int k = 0; k < 5; k++) xk[k] = x[n*5 + k];
        float ss[4] = {0,0,0,0}, sd[4] = {0,0,0,0};
#pragma unroll
        for (int k = 0; k < 5; k++)
#pragma unroll
            for (int h = 0; h < 4; h++) {
                ss[h] += xk[k] * Ms[k*4 + h];
                sd[h] += xk[k] * Md[k*4 + h];
            }
        g_rec[2*n] = make_float4(ss[0], ss[1], ss[2], ss[3]);
        __half2 p01 = __floats2half2_rn(xk[0], xk[1]);
        __half2 p23 = __floats2half2_rn(xk[2], xk[3]);
        __half2 p4z = __floats2half2_rn(xk[4], 0.f);
        uint4 u;
        u.x = *reinterpret_cast<unsigned*>(&p01);
        u.y = *reinterpret_cast<unsigned*>(&p23);
        u.z = *reinterpret_cast<unsigned*>(&p4z);
        u.w = 0u;
        ((uint4*)g_rec)[2*n + 1] = u;
        ((float4*)g_sdd1)[n*2] = make_float4(sd[0], sd[1], sd[2], sd[3]);
    }
}

// FUSED layer-1 aggregation + layer-2 projection: warp per node, LANE PER EDGE.
__global__ void __launch_bounds__(256) k_agg1f(
        const float* __restrict__ W1, const float* __restrict__ W2,
        const float* __restrict__ b1,
        const float* __restrict__ as2, const float* __restrict__ ad2) {
    __shared__ float W1s[640];
    __shared__ float W2s[128*32];
    __shared__ float hs[8][128];
    int t = threadIdx.x, lane = t & 31, w = t >> 5;
    for (int i = t; i < 640; i += 256) W1s[i] = W1[i];
    for (int i = t; i < 4096; i += 256) W2s[i] = W2[i];
    __syncthreads();
    int warp = (blockIdx.x * blockDim.x + t) >> 5;
    int nwarps = (gridDim.x * blockDim.x) >> 5;
    float4 cc = *(const float4*)g_c1;
    float eam = g_eamean;
    float4 bb = ((const float4*)b1)[lane];
    float asv = as2[lane], adv = ad2[lane];
    int hl = lane >> 3;                      // this lane's output head
    for (int d = warp; d < Nn; d += nwarps) {
        int beg = g_off[d], end = g_off[d+1];
        float4 sdv = ((const float4*)g_sdd1)[d*2];
        float den[4] = {0,0,0,0};
        float ax[4][5] = {{0,0,0,0,0},{0,0,0,0,0},{0,0,0,0,0},{0,0,0,0,0}};
        // self loop (lane 0): src = d, a = eamean
        if (lane == 0) {
            float4 ssv = g_rec[2*d];
            uint4 xp = ((const uint4*)g_rec)[2*d + 1];
            float2 x01 = __half22float2(*(__half2*)&xp.x);
            float2 x23 = __half22float2(*(__half2*)&xp.y);
            float2 x4_ = __half22float2(*(__half2*)&xp.z);
            float xk[5] = {x01.x, x01.y, x23.x, x23.y, x4_.x};
            float nh[4];
            nh[0] = __expf(lrelu(ssv.x + sdv.x + eam*cc.x));
            nh[1] = __expf(lrelu(ssv.y + sdv.y + eam*cc.y));
            nh[2] = __expf(lrelu(ssv.z + sdv.z + eam*cc.z));
            nh[3] = __expf(lrelu(ssv.w + sdv.w + eam*cc.w));
#pragma unroll
            for (int h = 0; h < 4; h++) {
                den[h] += nh[h];
#pragma unroll
                for (int k = 0; k < 5; k++) ax[h][k] += nh[h]*xk[k];
            }
        }
        // real edges: lane-striped (contiguous, coalesced metadata)
        for (int i = beg + lane; i < end; i += 32) {
            unsigned m = g_sa[i];
            int s = sa_src(m);
            float a = sa_a(m);
            float4 ssv = g_rec[2*s];
            uint4 xp = ((const uint4*)g_rec)[2*s + 1];
            float2 x01 = __half22float2(*(__half2*)&xp.x);
            float2 x23 = __half22float2(*(__half2*)&xp.y);
            float2 x4_ = __half22float2(*(__half2*)&xp.z);
            float xk[5] = {x01.x, x01.y, x23.x, x23.y, x4_.x};
            float nh[4];
            nh[0] = __expf(lrelu(ssv.x + sdv.x + a*cc.x));
            nh[1] = __expf(lrelu(ssv.y + sdv.y + a*cc.y));
            nh[2] = __expf(lrelu(ssv.z + sdv.z + a*cc.z));
            nh[3] = __expf(lrelu(ssv.w + sdv.w + a*cc.w));
#pragma unroll
            for (int h = 0; h < 4; h++) {
                den[h] += nh[h];
#pragma unroll
                for (int k = 0; k < 5; k++) ax[h][k] += nh[h]*xk[k];
            }
        }
#pragma unroll
        for (int h = 0; h < 4; h++) den[h] = wredsum(den[h]);
#pragma unroll
        for (int h = 0; h < 4; h++)
#pragma unroll
            for (int k = 0; k < 5; k++) ax[h][k] = wredsum(ax[h][k]);
        if (lane == 0)
            ((float4*)g_sdd1)[d*2 + 1] = make_float4(den[0], den[1], den[2], den[3]);
        float axh[5], denh;
        denh = (hl == 0) ? den[0] : (hl == 1) ? den[1] : (hl == 2) ? den[2] : den[3];
#pragma unroll
        for (int k = 0; k < 5; k++)
            axh[k] = (hl == 0) ? ax[0][k] : (hl == 1) ? ax[1][k] : (hl == 2) ? ax[2][k] : ax[3][k];
        float inv = 1.0f / (denh + 1e-16f);
        float hv[4];
#pragma unroll
        for (int j = 0; j < 4; j++) {
            int chn = lane*4 + j;
            float o = axh[0]*W1s[chn] + axh[1]*W1s[128+chn] + axh[2]*W1s[256+chn]
                    + axh[3]*W1s[384+chn] + axh[4]*W1s[512+chn];
            hv[j] = o * inv;
        }
        hs[w][lane*4+0] = elu(hv[0] + bb.x);
        hs[w][lane*4+1] = elu(hv[1] + bb.y);
        hs[w][lane*4+2] = elu(hv[2] + bb.z);
        hs[w][lane*4+3] = elu(hv[3] + bb.w);
        __syncwarp();
        float acc2 = 0.f;
#pragma unroll 16
        for (int j = 0; j < 128; j++)
            acc2 += hs[w][j] * W2s[j*32 + lane];
        g_h2h[d*32 + lane] = __float2half_rn(acc2);
        float ps = wredsum(acc2 * asv);
        float pd = wredsum(acc2 * adv);
        if (lane == 0) { g_ss2[d] = ps; g_sd2[d] = pd; }
        __syncwarp();
    }
}

// edge-parallel alpha1 writer: 2 edges/thread, coalesced float2 stores
__global__ void k_alphaE(const int* __restrict__ ei, const float* __restrict__ ea,
                         float* __restrict__ out) {
    int p = blockIdx.x * blockDim.x + threadIdx.x;
    int e = p * 2;
    if (e >= EF) return;
    int s0, d0, s1, d1; float a0, a1;
    if (e < Ee) {        // Ee even: pair never straddles
        int2 sp = ((const int2*)ei)[p];
        int2 dp = *(const int2*)(ei + Ee + e);
        float2 ap = ((const float2*)ea)[p];
        s0 = sp.x; s1 = sp.y; d0 = dp.x; d1 = dp.y; a0 = ap.x; a1 = ap.y;
    } else {
        s0 = d0 = e - Ee; s1 = d1 = e - Ee + 1;
        a0 = a1 = g_eamean;
    }
    float4 cc = *(const float4*)g_c1;
    float4 ssA = g_rec[2*s0];
    float4 sdA = ((const float4*)g_sdd1)[d0*2];
    float4 ddA = ((const float4*)g_sdd1)[d0*2 + 1];
    float4 ssB = g_rec[2*s1];
    float4 sdB = ((const float4*)g_sdd1)[d1*2];
    float4 ddB = ((const float4*)g_sdd1)[d1*2 + 1];
    float2* ao = (float2*)(out + A1_OFF + 4*e);
    ao[0] = make_float2(__expf(lrelu(ssA.x + sdA.x + a0*cc.x)) / (ddA.x + 1e-16f),
                        __expf(lrelu(ssA.y + sdA.y + a0*cc.y)) / (ddA.y + 1e-16f));
    ao[1] = make_float2(__expf(lrelu(ssA.z + sdA.z + a0*cc.z)) / (ddA.z + 1e-16f),
                        __expf(lrelu(ssA.w + sdA.w + a0*cc.w)) / (ddA.w + 1e-16f));
    ao[2] = make_float2(__expf(lrelu(ssB.x + sdB.x + a1*cc.x)) / (ddB.x + 1e-16f),
                        __expf(lrelu(ssB.y + sdB.y + a1*cc.y)) / (ddB.y + 1e-16f));
    ao[3] = make_float2(__expf(lrelu(ssB.z + sdB.z + a1*cc.z)) / (ddB.z + 1e-16f),
                        __expf(lrelu(ssB.w + sdB.w + a1*cc.w)) / (ddB.w + 1e-16f));
}

// layer-2 aggregation + node head: warp per node, 2 edges per warp-pass.
// Lane pl (=lane&15) owns channels (2pl, 2pl+1) via half2; groups 0/1 process
// alternating virtual items (item 0 = analytic self loop). Unrolled x2.
__global__ void __launch_bounds__(256) k_agg2(
        const float* __restrict__ b2, const float* __restrict__ Wa,
        const float* __restrict__ ba) {
    __shared__ float sacc[32];
    int t = threadIdx.x, lane = t & 31;
    int pl = lane & 15, grp = lane >> 4;
    if (t < 32) sacc[t] = 0.f;
    __syncthreads();
    int warp = (blockIdx.x * blockDim.x + t) >> 5;
    int nwarps = (gridDim.x * blockDim.x) >> 5;
    float c = g_c2, eam = g_eamean;
    float2 bl = ((const float2*)b2)[pl];
    float2 wl = ((const float2*)Wa)[pl];
    float bb = ba[0];
    float gacc0 = 0.f, gacc1 = 0.f;
    const __half2* h2p = (const __half2*)g_h2h;
    for (int d = warp; d < Nn; d += nwarps) {
        int beg = g_off[d], end = g_off[d+1];
        int L = end - beg + 1;                 // virtual items incl. self loop
        float sdv = g_sd2[d];
        float acc0 = 0.f, acc1 = 0.f, den = 0.f;
        int j = grp;
        if (grp == 0) {                         // item 0 = self loop
            float n = __expf(lrelu(g_ss2[d] + sdv + eam*c));
            float2 v = __half22float2(h2p[d*16 + pl]);
            den += n; acc0 += n*v.x; acc1 += n*v.y;
            j = 2;
        }
        for (; j + 2 < L; j += 4) {             // two items per group per pass
            unsigned m0 = g_sa[beg + j - 1];
            unsigned m1 = g_sa[beg + j + 1];
            int s0i = sa_src(m0), s1i = sa_src(m1);
            float n0 = __expf(lrelu(g_ss2[s0i] + sdv + sa_a(m0)*c));
            float n1 = __expf(lrelu(g_ss2[s1i] + sdv + sa_a(m1)*c));
            float2 v0 = __half22float2(h2p[s0i*16 + pl]);
            float2 v1 = __half22float2(h2p[s1i*16 + pl]);
            den += n0 + n1;
            acc0 += n0*v0.x + n1*v1.x;
            acc1 += n0*v0.y + n1*v1.y;
        }
        for (; j < L; j += 2) {
            unsigned m0 = g_sa[beg + j - 1];
            int s0i = sa_src(m0);
            float n0 = __expf(lrelu(g_ss2[s0i] + sdv + sa_a(m0)*c));
            float2 v0 = __half22float2(h2p[s0i*16 + pl]);
            den += n0; acc0 += n0*v0.x; acc1 += n0*v0.y;
        }
        // combine the two groups
        acc0 += __shfl_xor_sync(0xffffffffu, acc0, 16);
        acc1 += __shfl_xor_sync(0xffffffffu, acc1, 16);
        den  += __shfl_xor_sync(0xffffffffu, den, 16);
        float inv = 1.0f / (den + 1e-16f);
        float v0 = elu(acc0*inv + bl.x);
        float v1 = elu(acc1*inv + bl.y);
        float p = v0*wl.x + v1*wl.y;            // per-16-lane-group score sum
#pragma unroll
        for (int o = 8; o; o >>= 1) p += __shfl_xor_sync(0xffffffffu, p, o);
        if (lane == 0) g_scores[d] = p + bb;
        if (grp == 0) { gacc0 += v0; gacc1 += v1; }
    }
    if (grp == 0) {
        atomicAdd(&sacc[2*pl],   gacc0);
        atomicAdd(&sacc[2*pl+1], gacc1);
    }
    __syncthreads();
    if (t < 32) atomicAdd(&g_gsum[t], sacc[t]);
}

// fused softmax head: single kernel, spin grid barrier (<=148 blocks = 1 wave).
__global__ void k_headF(const float* __restrict__ cash, const int* __restrict__ stock_idx,
                        const float* __restrict__ Wc, const float* __restrict__ bc,
                        int ns, float* __restrict__ out) {
    __shared__ float sm[8];
    __shared__ float sInv;
    int t = threadIdx.x, lane = t & 31, w = t >> 5;
    int i = blockIdx.x * blockDim.x + t;
    float e = 0.f;
    if (i <= ns) {
        float v = (i == 0) ? cash[0] : g_scores[stock_idx[i-1]];
        e = __expf(v);
    }
    float s = wredsum(e);
    if (lane == 0) sm[w] = s;
    __syncthreads();
    if (t == 0) {
        float b = 0.f;
        for (int j = 0; j < (int)(blockDim.x >> 5); j++) b += sm[j];
        atomicAdd(&g_wsum, b);
        __threadfence();
        atomicAdd(&g_hctr, 1);
    }
    if (blockIdx.x == 0 && t < 32) {
        float p = wredsum(g_gsum[t] * (1.0f / Nn) * Wc[t]);
        if (t == 0) out[V_OFF] = p + bc[0];
    }
    if (t == 0) {
        while (atomicAdd(&g_hctr, 0) < (int)gridDim.x) __nanosleep(32);
        sInv = 1.0f / g_wsum;
    }
    __syncthreads();
    if (i <= ns) out[W_OFF + i] = e * sInv;
}

// ---------------- launch ----------------
extern "C" void kernel_launch(void* const* d_in, const int* in_sizes, int n_in,
                              void* d_out, int out_size) {
    const float* x    = (const float*)d_in[0];
    const float* ea   = (const float*)d_in[1];
    const float* W1   = (const float*)d_in[2];
    const float* as1  = (const float*)d_in[3];
    const float* ad1  = (const float*)d_in[4];
    const float* We1  = (const float*)d_in[5];
    const float* ae1  = (const float*)d_in[6];
    const float* b1   = (const float*)d_in[7];
    const float* W2   = (const float*)d_in[8];
    const float* as2  = (const float*)d_in[9];
    const float* ad2  = (const float*)d_in[10];
    const float* We2  = (const float*)d_in[11];
    const float* ae2  = (const float*)d_in[12];
    const float* b2   = (const float*)d_in[13];
    const float* Wa   = (const float*)d_in[14];
    const float* ba   = (const float*)d_in[15];
    const float* cash = (const float*)d_in[16];
    const float* Wc   = (const float*)d_in[17];
    const float* bc   = (const float*)d_in[18];
    const int*   ei   = (const int*)  d_in[19];
    const int*   sidx = (const int*)  d_in[20];
    float* out = (float*)d_out;
    int ns = in_sizes[20];

    // lazy one-time stream/event/occupancy setup (host-side objects only)
    static cudaStream_t sA = nullptr, sB = nullptr;
    static cudaEvent_t evFork, evNode1, evAgg1, evAlpha, evEnd;
    static int gridA1 = 0, gridA2 = 0;
    if (!sA) {
        cudaStreamCreateWithFlags(&sA, cudaStreamNonBlocking);
        cudaStreamCreateWithFlags(&sB, cudaStreamNonBlocking);
        cudaEventCreateWithFlags(&evFork,  cudaEventDisableTiming);
        cudaEventCreateWithFlags(&evNode1, cudaEventDisableTiming);
        cudaEventCreateWithFlags(&evAgg1,  cudaEventDisableTiming);
        cudaEventCreateWithFlags(&evAlpha, cudaEventDisableTiming);
        cudaEventCreateWithFlags(&evEnd,   cudaEventDisableTiming);
        int sms = 148, nb = 0;
        cudaDeviceGetAttribute(&sms, cudaDevAttrMultiProcessorCount, 0);
        cudaOccupancyMaxActiveBlocksPerMultiprocessor(&nb, k_agg1f, 256, 0);
        gridA1 = (nb > 0 ? nb : 4) * sms;
        cudaOccupancyMaxActiveBlocksPerMultiprocessor(&nb, k_agg2, 256, 0);
        gridA2 = (nb > 0 ? nb : 8) * sms;
        if (gridA2 > 6250) gridA2 = 6250;   // no more than one warp per node
        if (gridA1 > 6250) gridA1 = 6250;
    }

    // fork from the harness's (captured) stream
    cudaEventRecord(evFork, 0);
    cudaStreamWaitEvent(sA, evFork, 0);
    cudaStreamWaitEvent(sB, evFork, 0);

    // stream B: easum -> consts (+M matrices) -> node1 -> edge_index_full
    k_easum <<<512, 256, 0, sB>>>(ea);
    k_consts<<<1, 128, 0, sB>>>(W1, as1, ad1, We1, ae1, We2, ae2);
    k_node1 <<<196, 256, 0, sB>>>(x);
    cudaEventRecord(evNode1, sB);      // implies consts done too
    k_eif   <<<(EF/2 + 255) / 256, 256, 0, sB>>>(ei, out);

    // stream A: CSR build (rank-based, atomic-free scatter) -> agg -> head
    k_hist   <<<(Ee/4 + 255) / 256, 256, 0, sA>>>(ei);
    k_scan   <<<SCANB, 1024, 0, sA>>>();
    k_scatter<<<(Ee/4 + 255) / 256, 256, 0, sA>>>(ei, ea);
    cudaStreamWaitEvent(sA, evNode1, 0);                // records, sd1, consts
    k_agg1f  <<<gridA1, 256, 0, sA>>>(W1, W2, b1, as2, ad2);
    cudaEventRecord(evAgg1, sA);

    // stream B: alpha writer overlaps agg2 (disjoint data)
    cudaStreamWaitEvent(sB, evAgg1, 0);                 // denominators
    k_alphaE<<<(EF/2 + 255) / 256, 256, 0, sB>>>(ei, ea, out);
    cudaEventRecord(evAlpha, sB);

    k_agg2  <<<gridA2, 256, 0, sA>>>(b2, Wa, ba);
    k_headF <<<(ns + 256) / 256, 256, 0, sA>>>(cash, sidx, Wc, bc, ns, out);
    cudaEventRecord(evEnd, sA);

    // join both streams back into the harness stream
    cudaStreamWaitEvent(0, evEnd, 0);
    cudaStreamWaitEvent(0, evAlpha, 0);
}

// round 15
// speedup vs baseline: 2.8571x; 1.0203x over previous
#include <cuda_runtime.h>
#include <cuda_fp16.h>
#include <math.h>

// ---------------- problem constants ----------------
#define Nn    50000
#define Ee    1600000
#define EF    1650000          // E + N self loops
#define SCANB 13               // scan blocks: 13*1024 int4 = 53248 >= 12500

// output layout (float32, flattened in return order)
#define W_OFF  0               // weights [25001]
#define V_OFF  25001           // value   [1]
#define EI_OFF 25002           // edge_index_full [2, EF]
#define A1_OFF (25002 + 2*EF)  // alpha1 [EF, 4]  (8B-aligned only!)

// ---------------- device scratch ----------------
// node record: rec[2n] = ss1 (fp32 x4), rec[2n+1] = x (fp16 x5, packed, padded)
__device__ __align__(16) float4 g_rec [Nn*2];
__device__ __align__(16) float  g_sdd1[Nn*8];    // [sd1(4) | den1(4)] per node
__device__ __align__(16) __half g_h2h [Nn*32];   // layer2 features, fp16 (32 ch)
__device__ float g_ss2[Nn], g_sd2[Nn];
__device__ float g_scores[Nn];
__device__ float g_gsum[32];
__device__ float g_wsum;                         // softmax denominator
__device__ int   g_hctr;                         // head grid-barrier counter
__device__ float g_eap[512];                     // easum partials (overwrite-only)
__device__ float g_eamean;
__device__ __align__(16) float g_c1[4];
__device__ float g_c2;
__device__ float g_Ms[20], g_Md[20];             // (5 x 4) score matrices: x @ M = s
// CSR-by-dst structures (real edges only; self loops handled analytically)
__device__ __align__(16) int g_cnt[Nn];          // zero at start (BSS / self-restored)
__device__ __align__(16) int g_off[Nn + 4];
__device__ __align__(16) unsigned short g_rank[Ee];  // within-segment rank per edge
__device__ __align__(16) unsigned g_sa[Ee];      // [fp16 a | uint16 src] per edge
__device__ int g_bpref[32];                      // mailboxes: 0 = empty, v = prefix+1

// ---------------- helpers ----------------
__device__ __forceinline__ float wredsum(float v) {
#pragma unroll
    for (int o = 16; o; o >>= 1) v += __shfl_xor_sync(0xffffffffu, v, o);
    return v;
}
__device__ __forceinline__ float lrelu(float x) { return x >= 0.f ? x : 0.2f * x; }
__device__ __forceinline__ float elu(float x)   { return x > 0.f ? x : expm1f(x); }
__device__ __forceinline__ int   sa_src(unsigned q) { return (int)(q & 0xFFFFu); }
__device__ __forceinline__ float sa_a(unsigned q) {
    return __half2float(__ushort_as_half((unsigned short)(q >> 16)));
}

// ---------------- kernels ----------------
// easum partials: overwrite-only, no pre-zeroing needed
__global__ void k_easum(const float* __restrict__ ea) {
    float s = 0.f;
    for (int i = blockIdx.x * blockDim.x + threadIdx.x; i < Ee; i += gridDim.x * blockDim.x)
        s += ea[i];
    s = wredsum(s);
    __shared__ float sm[8];
    int lane = threadIdx.x & 31, w = threadIdx.x >> 5;
    if (lane == 0) sm[w] = s;
    __syncthreads();
    if (threadIdx.x == 0) {
        float b = 0.f;
        for (int i = 0; i < (int)(blockDim.x >> 5); i++) b += sm[i];
        g_eap[blockIdx.x] = b;
    }
}

// consts: c1/c2/eamean (from partials) + score matrices Ms/Md (5x4)
__global__ void k_consts(const float* __restrict__ W1,
                         const float* __restrict__ as1, const float* __restrict__ ad1,
                         const float* __restrict__ We1, const float* __restrict__ ae1,
                         const float* __restrict__ We2, const float* __restrict__ ae2) {
    __shared__ float esm[4];
    int t = threadIdx.x;            // 128 threads; warp == head
    int lane = t & 31, h = t >> 5;
    float es = 0.f;
    for (int i = t; i < 512; i += 128) es += g_eap[i];
    es = wredsum(es);
    if (lane == 0) esm[h] = es;
    float p = We1[t] * ae1[t];
    p = wredsum(p);
    if (lane == 0) g_c1[h] = p;
    float asv = as1[t], adv = ad1[t];
#pragma unroll
    for (int k = 0; k < 5; k++) {
        float ms = wredsum(W1[k*128 + t] * asv);
        float md = wredsum(W1[k*128 + t] * adv);
        if (lane == 0) { g_Ms[k*4 + h] = ms; g_Md[k*4 + h] = md; }
    }
    if (t < 32) {
        float q = We2[t] * ae2[t];
        q = wredsum(q);
        if (t == 0) g_c2 = q;
    }
    __syncthreads();
    if (t == 0) g_eamean = (esm[0] + esm[1] + esm[2] + esm[3]) * (1.0f / Ee);
}

// emit edge_index_full: 2 edges/thread, int2 loads + float2 stores (8B-aligned dst)
__global__ void k_eif(const int* __restrict__ ei, float* __restrict__ out) {
    int p = blockIdx.x * blockDim.x + threadIdx.x;   // pair index
    int e = p * 2;
    if (e >= EF) return;
    float s0, s1, d0, d1;
    if (e < Ee) {        // Ee even: pair never straddles the boundary
        int2 sp = ((const int2*)ei)[p];
        int2 dp = *(const int2*)(ei + Ee + e);
        s0 = (float)sp.x; s1 = (float)sp.y;
        d0 = (float)dp.x; d1 = (float)dp.y;
    } else {
        s0 = d0 = (float)(e - Ee);
        s1 = d1 = (float)(e - Ee + 1);
    }
    *(float2*)(out + EI_OFF + e)      = make_float2(s0, s1);
    *(float2*)(out + EI_OFF + EF + e) = make_float2(d0, d1);
}

// histogram + rank capture: 4 edges/thread.
__global__ void k_hist(const int* __restrict__ ei) {
    int q = blockIdx.x * blockDim.x + threadIdx.x;   // quad index
    if (q * 4 >= Ee) return;
    int4 d = *(const int4*)(ei + Ee + q * 4);
    ushort4 r;
    r.x = (unsigned short)atomicAdd(&g_cnt[d.x], 1);
    r.y = (unsigned short)atomicAdd(&g_cnt[d.y], 1);
    r.z = (unsigned short)atomicAdd(&g_cnt[d.z], 1);
    r.w = (unsigned short)atomicAdd(&g_cnt[d.w], 1);
    ((ushort4*)g_rank)[q] = r;
}

// decoupled chained scan: self-restoring.
__global__ void __launch_bounds__(1024) k_scan() {
    __shared__ int wsum[32];
    __shared__ int s_pref;
    const int M4 = Nn / 4;                 // 12500
    int b = blockIdx.x, t = threadIdx.x, lane = t & 31, w = t >> 5;
    if (b == 0) {
        if (t < 32) g_gsum[t] = 0.f;
        if (t == 32) g_wsum = 0.f;
        if (t == 33) g_hctr = 0;
    }
    int idx = b * 1024 + t;
    int4 v = (idx < M4) ? ((const int4*)g_cnt)[idx] : make_int4(0, 0, 0, 0);
    if (idx < M4) ((int4*)g_cnt)[idx] = make_int4(0, 0, 0, 0);   // restore for replay
    int tsum = v.x + v.y + v.z + v.w;
    int val = tsum;
#pragma unroll
    for (int o = 1; o < 32; o <<= 1) { int x = __shfl_up_sync(0xffffffffu, val, o); if (lane >= o) val += x; }
    if (lane == 31) wsum[w] = val;
    __syncthreads();
    if (w == 0) {
        int x = wsum[lane];
#pragma unroll
        for (int o = 1; o < 32; o <<= 1) { int y = __shfl_up_sync(0xffffffffu, x, o); if (lane >= o) x += y; }
        wsum[lane] = x;
    }
    __syncthreads();
    int btot = wsum[31];
    int excl = ((w > 0) ? wsum[w - 1] : 0) + val - tsum;   // exclusive within block
    if (t == 0) {
        int pref = 0;
        if (b > 0) {
            int m;
            while ((m = atomicAdd(&g_bpref[b], 0)) == 0) __nanosleep(64);
            pref = m - 1;
            atomicExch(&g_bpref[b], 0);                    // reset mailbox for replay
        }
        atomicExch(&g_bpref[b + 1], pref + btot + 1);
        s_pref = pref;
    }
    __syncthreads();
    int base = s_pref;
    if (idx < M4) {
        int4 o;
        o.x = base + excl; o.y = o.x + v.x; o.z = o.y + v.y; o.w = o.z + v.z;
        ((int4*)g_off)[idx] = o;
        if (idx == M4 - 1) g_off[Nn] = o.w + v.w;
    }
}

// scatter: ATOMIC-FREE. slot = off[dst] + rank. 4 edges/thread.
__global__ void k_scatter(const int* __restrict__ ei, const float* __restrict__ ea) {
    int q = blockIdx.x * blockDim.x + threadIdx.x;
    if (q * 4 >= Ee) return;
    int4 s4 = ((const int4*)ei)[q];
    int4 d4 = *(const int4*)(ei + Ee + q * 4);
    float4 a4 = ((const float4*)ea)[q];
    ushort4 r4 = ((const ushort4*)g_rank)[q];
    unsigned a0 = (unsigned)__half_as_ushort(__float2half_rn(a4.x));
    unsigned a1 = (unsigned)__half_as_ushort(__float2half_rn(a4.y));
    unsigned a2 = (unsigned)__half_as_ushort(__float2half_rn(a4.z));
    unsigned a3 = (unsigned)__half_as_ushort(__float2half_rn(a4.w));
    g_sa[g_off[d4.x] + r4.x] = (unsigned)s4.x | (a0 << 16);
    g_sa[g_off[d4.y] + r4.y] = (unsigned)s4.y | (a1 << 16);
    g_sa[g_off[d4.z] + r4.z] = (unsigned)s4.z | (a2 << 16);
    g_sa[g_off[d4.w] + r4.w] = (unsigned)s4.w | (a3 << 16);
}

// node prep: thread per node. ss1/sd1 = x @ Ms/Md (5x4). Packed node record.
__global__ void k_node1(const float* __restrict__ x) {
    __shared__ float Ms[20], Md[20];
    int t = threadIdx.x;
    if (t < 20) { Ms[t] = g_Ms[t]; Md[t] = g_Md[t]; }
    __syncthreads();
    int stride = gridDim.x * blockDim.x;
    for (int n = blockIdx.x * blockDim.x + t; n < Nn; n += stride) {
        float xk[5];
#pragma unroll
        for (int k = 0; k < 5; k++) xk[k] = x[n*5 + k];
        float ss[4] = {0,0,0,0}, sd[4] = {0,0,0,0};
#pragma unroll
        for (int k = 0; k < 5; k++)
#pragma unroll
            for (int h = 0; h < 4; h++) {
                ss[h] += xk[k] * Ms[k*4 + h];
                sd[h] += xk[k] * Md[k*4 + h];
            }
        g_rec[2*n] = make_float4(ss[0], ss[1], ss[2], ss[3]);
        __half2 p01 = __floats2half2_rn(xk[0], xk[1]);
        __half2 p23 = __floats2half2_rn(xk[2], xk[3]);
        __half2 p4z = __floats2half2_rn(xk[4], 0.f);
        uint4 u;
        u.x = *reinterpret_cast<unsigned*>(&p01);
        u.y = *reinterpret_cast<unsigned*>(&p23);
        u.z = *reinterpret_cast<unsigned*>(&p4z);
        u.w = 0u;
        ((uint4*)g_rec)[2*n + 1] = u;
        ((float4*)g_sdd1)[n*2] = make_float4(sd[0], sd[1], sd[2], sd[3]);
    }
}

// FUSED layer-1 aggregation + layer-2 projection: warp per node.
// Mainloop: 8 lanes per head (lane = 8h+pl); the 4 head-groups walk the SAME
// 8 edges per pass (record loads broadcast). Each lane computes 1 exp/edge and
// 6 partials -> reduction is a 3-stage butterfly within 8 lanes (36 instrs vs
// 240), and after it each lane already holds its own head's ax/den.
// Epilogue: W2 transposed+padded in smem -> LDS.128 loop (32 iters).
__global__ void __launch_bounds__(256) k_agg1f(
        const float* __restrict__ W1, const float* __restrict__ W2,
        const float* __restrict__ b1,
        const float* __restrict__ as2, const float* __restrict__ ad2) {
    __shared__ float W1s[640];
    __shared__ float W2T[32][132];           // [ch][j], pad 132: conflict-free LDS.128
    __shared__ __align__(16) float hs[8][128];
    int t = threadIdx.x, lane = t & 31, w = t >> 5;
    for (int i = t; i < 640; i += 256) W1s[i] = W1[i];
    for (int i = t; i < 4096; i += 256) W2T[i & 31][i >> 5] = W2[i];
    __syncthreads();
    int warp = (blockIdx.x * blockDim.x + t) >> 5;
    int nwarps = (gridDim.x * blockDim.x) >> 5;
    int h = lane >> 3, pl = lane & 7;
    float4 cc4 = *(const float4*)g_c1;
    float chc = (h == 0) ? cc4.x : (h == 1) ? cc4.y : (h == 2) ? cc4.z : cc4.w;
    float eam = g_eamean;
    float4 bb = ((const float4*)b1)[lane];
    float asv = as2[lane], adv = ad2[lane];
    for (int d = warp; d < Nn; d += nwarps) {
        int beg = g_off[d], end = g_off[d+1];
        float sdh = g_sdd1[d*8 + h];
        float den = 0.f;
        float ax[5] = {0.f, 0.f, 0.f, 0.f, 0.f};
        // self loop: pl==0 lane of each group, own head only
        if (pl == 0) {
            float4 ssv = g_rec[2*d];
            float ssh = (h == 0) ? ssv.x : (h == 1) ? ssv.y : (h == 2) ? ssv.z : ssv.w;
            uint4 xp = ((const uint4*)g_rec)[2*d + 1];
            float2 x01 = __half22float2(*(__half2*)&xp.x);
            float2 x23 = __half22float2(*(__half2*)&xp.y);
            float2 x4_ = __half22float2(*(__half2*)&xp.z);
            float n = __expf(lrelu(ssh + sdh + eam*chc));
            den += n;
            ax[0] += n*x01.x; ax[1] += n*x01.y; ax[2] += n*x23.x;
            ax[3] += n*x23.y; ax[4] += n*x4_.x;
        }
        // real edges: 8 per warp-pass, unroll x2 for MLP
        int i = beg + pl;
        for (; i + 8 < end; i += 16) {
            unsigned m0 = g_sa[i], m1 = g_sa[i + 8];
            int s0 = sa_src(m0), s1 = sa_src(m1);
            float4 sv0 = g_rec[2*s0];
            float4 sv1 = g_rec[2*s1];
            uint4 xp0 = ((const uint4*)g_rec)[2*s0 + 1];
            uint4 xp1 = ((const uint4*)g_rec)[2*s1 + 1];
            float sh0 = (h == 0) ? sv0.x : (h == 1) ? sv0.y : (h == 2) ? sv0.z : sv0.w;
            float sh1 = (h == 0) ? sv1.x : (h == 1) ? sv1.y : (h == 2) ? sv1.z : sv1.w;
            float n0 = __expf(lrelu(sh0 + sdh + sa_a(m0)*chc));
            float n1 = __expf(lrelu(sh1 + sdh + sa_a(m1)*chc));
            float2 a01 = __half22float2(*(__half2*)&xp0.x);
            float2 a23 = __half22float2(*(__half2*)&xp0.y);
            float2 a4_ = __half22float2(*(__half2*)&xp0.z);
            float2 b01 = __half22float2(*(__half2*)&xp1.x);
            float2 b23 = __half22float2(*(__half2*)&xp1.y);
            float2 b4_ = __half22float2(*(__half2*)&xp1.z);
            den += n0 + n1;
            ax[0] += n0*a01.x + n1*b01.x;
            ax[1] += n0*a01.y + n1*b01.y;
            ax[2] += n0*a23.x + n1*b23.x;
            ax[3] += n0*a23.y + n1*b23.y;
            ax[4] += n0*a4_.x + n1*b4_.x;
        }
        if (i < end) {
            unsigned m0 = g_sa[i];
            int s0 = sa_src(m0);
            float4 sv0 = g_rec[2*s0];
            uint4 xp0 = ((const uint4*)g_rec)[2*s0 + 1];
            float sh0 = (h == 0) ? sv0.x : (h == 1) ? sv0.y : (h == 2) ? sv0.z : sv0.w;
            float n0 = __expf(lrelu(sh0 + sdh + sa_a(m0)*chc));
            float2 a01 = __half22float2(*(__half2*)&xp0.x);
            float2 a23 = __half22float2(*(__half2*)&xp0.y);
            float2 a4_ = __half22float2(*(__half2*)&xp0.z);
            den += n0;
            ax[0] += n0*a01.x; ax[1] += n0*a01.y; ax[2] += n0*a23.x;
            ax[3] += n0*a23.y; ax[4] += n0*a4_.x;
        }
        // reduce within 8-lane head group (3-stage butterfly)
#pragma unroll
        for (int o = 4; o; o >>= 1) {
            den += __shfl_xor_sync(0xffffffffu, den, o);
#pragma unroll
            for (int k = 0; k < 5; k++) ax[k] += __shfl_xor_sync(0xffffffffu, ax[k], o);
        }
        float d0 = __shfl_sync(0xffffffffu, den, 0);
        float d1 = __shfl_sync(0xffffffffu, den, 8);
        float d2 = __shfl_sync(0xffffffffu, den, 16);
        float d3 = __shfl_sync(0xffffffffu, den, 24);
        if (lane == 0)
            ((float4*)g_sdd1)[d*2 + 1] = make_float4(d0, d1, d2, d3);
        float inv = 1.0f / (den + 1e-16f);     // this lane's head den
        // o1 channels [4*lane .. 4*lane+3] = ax @ W1 (this lane's head), elu + b1
        float hv[4];
#pragma unroll
        for (int j = 0; j < 4; j++) {
            int chn = lane*4 + j;
            float o = ax[0]*W1s[chn] + ax[1]*W1s[128+chn] + ax[2]*W1s[256+chn]
                    + ax[3]*W1s[384+chn] + ax[4]*W1s[512+chn];
            hv[j] = o * inv;
        }
        ((float4*)hs[w])[lane] = make_float4(elu(hv[0] + bb.x), elu(hv[1] + bb.y),
                                             elu(hv[2] + bb.z), elu(hv[3] + bb.w));
        __syncwarp();
        float acc2 = 0.f;
        const float4* hs4 = (const float4*)hs[w];
#pragma unroll 8
        for (int j4 = 0; j4 < 32; j4++) {
            float4 hv4 = hs4[j4];                       // broadcast
            float4 wv = *(const float4*)&W2T[lane][j4*4];
            acc2 += hv4.x*wv.x + hv4.y*wv.y + hv4.z*wv.z + hv4.w*wv.w;
        }
        g_h2h[d*32 + lane] = __float2half_rn(acc2);
        float ps = wredsum(acc2 * asv);
        float pd = wredsum(acc2 * adv);
        if (lane == 0) { g_ss2[d] = ps; g_sd2[d] = pd; }
        __syncwarp();
    }
}

// edge-parallel alpha1 writer: 2 edges/thread, coalesced float2 stores
__global__ void k_alphaE(const int* __restrict__ ei, const float* __restrict__ ea,
                         float* __restrict__ out) {
    int p = blockIdx.x * blockDim.x + threadIdx.x;
    int e = p * 2;
    if (e >= EF) return;
    int s0, d0, s1, d1; float a0, a1;
    if (e < Ee) {        // Ee even: pair never straddles
        int2 sp = ((const int2*)ei)[p];
        int2 dp = *(const int2*)(ei + Ee + e);
        float2 ap = ((const float2*)ea)[p];
        s0 = sp.x; s1 = sp.y; d0 = dp.x; d1 = dp.y; a0 = ap.x; a1 = ap.y;
    } else {
        s0 = d0 = e - Ee; s1 = d1 = e - Ee + 1;
        a0 = a1 = g_eamean;
    }
    float4 cc = *(const float4*)g_c1;
    float4 ssA = g_rec[2*s0];
    float4 sdA = ((const float4*)g_sdd1)[d0*2];
    float4 ddA = ((const float4*)g_sdd1)[d0*2 + 1];
    float4 ssB = g_rec[2*s1];
    float4 sdB = ((const float4*)g_sdd1)[d1*2];
    float4 ddB = ((const float4*)g_sdd1)[d1*2 + 1];
    float2* ao = (float2*)(out + A1_OFF + 4*e);
    ao[0] = make_float2(__expf(lrelu(ssA.x + sdA.x + a0*cc.x)) / (ddA.x + 1e-16f),
                        __expf(lrelu(ssA.y + sdA.y + a0*cc.y)) / (ddA.y + 1e-16f));
    ao[1] = make_float2(__expf(lrelu(ssA.z + sdA.z + a0*cc.z)) / (ddA.z + 1e-16f),
                        __expf(lrelu(ssA.w + sdA.w + a0*cc.w)) / (ddA.w + 1e-16f));
    ao[2] = make_float2(__expf(lrelu(ssB.x + sdB.x + a1*cc.x)) / (ddB.x + 1e-16f),
                        __expf(lrelu(ssB.y + sdB.y + a1*cc.y)) / (ddB.y + 1e-16f));
    ao[3] = make_float2(__expf(lrelu(ssB.z + sdB.z + a1*cc.z)) / (ddB.z + 1e-16f),
                        __expf(lrelu(ssB.w + sdB.w + a1*cc.w)) / (ddB.w + 1e-16f));
}

// layer-2 aggregation + node head: warp per node, 2 edges per warp-pass (half2).
__global__ void __launch_bounds__(256) k_agg2(
        const float* __restrict__ b2, const float* __restrict__ Wa,
        const float* __restrict__ ba) {
    __shared__ float sacc[32];
    int t = threadIdx.x, lane = t & 31;
    int pl = lane & 15, grp = lane >> 4;
    if (t < 32) sacc[t] = 0.f;
    __syncthreads();
    int warp = (blockIdx.x * blockDim.x + t) >> 5;
    int nwarps = (gridDim.x * blockDim.x) >> 5;
    float c = g_c2, eam = g_eamean;
    float2 bl = ((const float2*)b2)[pl];
    float2 wl = ((const float2*)Wa)[pl];
    float bb = ba[0];
    float gacc0 = 0.f, gacc1 = 0.f;
    const __half2* h2p = (const __half2*)g_h2h;
    for (int d = warp; d < Nn; d += nwarps) {
        int beg = g_off[d], end = g_off[d+1];
        int L = end - beg + 1;                 // virtual items incl. self loop
        float sdv = g_sd2[d];
        float acc0 = 0.f, acc1 = 0.f, den = 0.f;
        int j = grp;
        if (grp == 0) {                         // item 0 = self loop
            float n = __expf(lrelu(g_ss2[d] + sdv + eam*c));
            float2 v = __half22float2(h2p[d*16 + pl]);
            den += n; acc0 += n*v.x; acc1 += n*v.y;
            j = 2;
        }
        for (; j + 2 < L; j += 4) {             // two items per group per pass
            unsigned m0 = g_sa[beg + j - 1];
            unsigned m1 = g_sa[beg + j + 1];
            int s0i = sa_src(m0), s1i = sa_src(m1);
            float n0 = __expf(lrelu(g_ss2[s0i] + sdv + sa_a(m0)*c));
            float n1 = __expf(lrelu(g_ss2[s1i] + sdv + sa_a(m1)*c));
            float2 v0 = __half22float2(h2p[s0i*16 + pl]);
            float2 v1 = __half22float2(h2p[s1i*16 + pl]);
            den += n0 + n1;
            acc0 += n0*v0.x + n1*v1.x;
            acc1 += n0*v0.y + n1*v1.y;
        }
        for (; j < L; j += 2) {
            unsigned m0 = g_sa[beg + j - 1];
            int s0i = sa_src(m0);
            float n0 = __expf(lrelu(g_ss2[s0i] + sdv + sa_a(m0)*c));
            float2 v0 = __half22float2(h2p[s0i*16 + pl]);
            den += n0; acc0 += n0*v0.x; acc1 += n0*v0.y;
        }
        acc0 += __shfl_xor_sync(0xffffffffu, acc0, 16);
        acc1 += __shfl_xor_sync(0xffffffffu, acc1, 16);
        den  += __shfl_xor_sync(0xffffffffu, den, 16);
        float inv = 1.0f / (den + 1e-16f);
        float v0 = elu(acc0*inv + bl.x);
        float v1 = elu(acc1*inv + bl.y);
        float p = v0*wl.x + v1*wl.y;
#pragma unroll
        for (int o = 8; o; o >>= 1) p += __shfl_xor_sync(0xffffffffu, p, o);
        if (lane == 0) g_scores[d] = p + bb;
        if (grp == 0) { gacc0 += v0; gacc1 += v1; }
    }
    if (grp == 0) {
        atomicAdd(&sacc[2*pl],   gacc0);
        atomicAdd(&sacc[2*pl+1], gacc1);
    }
    __syncthreads();
    if (t < 32) atomicAdd(&g_gsum[t], sacc[t]);
}

// fused softmax head: single kernel, spin grid barrier (<=148 blocks = 1 wave).
__global__ void k_headF(const float* __restrict__ cash, const int* __restrict__ stock_idx,
                        const float* __restrict__ Wc, const float* __restrict__ bc,
                        int ns, float* __restrict__ out) {
    __shared__ float sm[8];
    __shared__ float sInv;
    int t = threadIdx.x, lane = t & 31, w = t >> 5;
    int i = blockIdx.x * blockDim.x + t;
    float e = 0.f;
    if (i <= ns) {
        float v = (i == 0) ? cash[0] : g_scores[stock_idx[i-1]];
        e = __expf(v);
    }
    float s = wredsum(e);
    if (lane == 0) sm[w] = s;
    __syncthreads();
    if (t == 0) {
        float b = 0.f;
        for (int j = 0; j < (int)(blockDim.x >> 5); j++) b += sm[j];
        atomicAdd(&g_wsum, b);
        __threadfence();
        atomicAdd(&g_hctr, 1);
    }
    if (blockIdx.x == 0 && t < 32) {
        float p = wredsum(g_gsum[t] * (1.0f / Nn) * Wc[t]);
        if (t == 0) out[V_OFF] = p + bc[0];
    }
    if (t == 0) {
        while (atomicAdd(&g_hctr, 0) < (int)gridDim.x) __nanosleep(32);
        sInv = 1.0f / g_wsum;
    }
    __syncthreads();
    if (i <= ns) out[W_OFF + i] = e * sInv;
}

// ---------------- launch ----------------
extern "C" void kernel_launch(void* const* d_in, const int* in_sizes, int n_in,
                              void* d_out, int out_size) {
    const float* x    = (const float*)d_in[0];
    const float* ea   = (const float*)d_in[1];
    const float* W1   = (const float*)d_in[2];
    const float* as1  = (const float*)d_in[3];
    const float* ad1  = (const float*)d_in[4];
    const float* We1  = (const float*)d_in[5];
    const float* ae1  = (const float*)d_in[6];
    const float* b1   = (const float*)d_in[7];
    const float* W2   = (const float*)d_in[8];
    const float* as2  = (const float*)d_in[9];
    const float* ad2  = (const float*)d_in[10];
    const float* We2  = (const float*)d_in[11];
    const float* ae2  = (const float*)d_in[12];
    const float* b2   = (const float*)d_in[13];
    const float* Wa   = (const float*)d_in[14];
    const float* ba   = (const float*)d_in[15];
    const float* cash = (const float*)d_in[16];
    const float* Wc   = (const float*)d_in[17];
    const float* bc   = (const float*)d_in[18];
    const int*   ei   = (const int*)  d_in[19];
    const int*   sidx = (const int*)  d_in[20];
    float* out = (float*)d_out;
    int ns = in_sizes[20];

    // lazy one-time stream/event/occupancy setup (host-side objects only)
    static cudaStream_t sA = nullptr, sB = nullptr;
    static cudaEvent_t evFork, evNode1, evAgg1, evAlpha, evEnd;
    static int gridA1 = 0, gridA2 = 0;
    if (!sA) {
        cudaStreamCreateWithFlags(&sA, cudaStreamNonBlocking);
        cudaStreamCreateWithFlags(&sB, cudaStreamNonBlocking);
        cudaEventCreateWithFlags(&evFork,  cudaEventDisableTiming);
        cudaEventCreateWithFlags(&evNode1, cudaEventDisableTiming);
        cudaEventCreateWithFlags(&evAgg1,  cudaEventDisableTiming);
        cudaEventCreateWithFlags(&evAlpha, cudaEventDisableTiming);
        cudaEventCreateWithFlags(&evEnd,   cudaEventDisableTiming);
        int sms = 148, nb = 0;
        cudaDeviceGetAttribute(&sms, cudaDevAttrMultiProcessorCount, 0);
        cudaOccupancyMaxActiveBlocksPerMultiprocessor(&nb, k_agg1f, 256, 0);
        gridA1 = (nb > 0 ? nb : 4) * sms;
        cudaOccupancyMaxActiveBlocksPerMultiprocessor(&nb, k_agg2, 256, 0);
        gridA2 = (nb > 0 ? nb : 8) * sms;
        if (gridA2 > 6250) gridA2 = 6250;   // no more than one warp per node
        if (gridA1 > 6250) gridA1 = 6250;
    }

    // fork from the harness's (captured) stream
    cudaEventRecord(evFork, 0);
    cudaStreamWaitEvent(sA, evFork, 0);
    cudaStreamWaitEvent(sB, evFork, 0);

    // stream B: easum -> consts (+M matrices) -> node1 -> edge_index_full
    k_easum <<<512, 256, 0, sB>>>(ea);
    k_consts<<<1, 128, 0, sB>>>(W1, as1, ad1, We1, ae1, We2, ae2);
    k_node1 <<<196, 256, 0, sB>>>(x);
    cudaEventRecord(evNode1, sB);      // implies consts done too
    k_eif   <<<(EF/2 + 255) / 256, 256, 0, sB>>>(ei, out);

    // stream A: CSR build (rank-based, atomic-free scatter) -> agg -> head
    k_hist   <<<(Ee/4 + 255) / 256, 256, 0, sA>>>(ei);
    k_scan   <<<SCANB, 1024, 0, sA>>>();
    k_scatter<<<(Ee/4 + 255) / 256, 256, 0, sA>>>(ei, ea);
    cudaStreamWaitEvent(sA, evNode1, 0);                // records, sd1, consts
    k_agg1f  <<<gridA1, 256, 0, sA>>>(W1, W2, b1, as2, ad2);
    cudaEventRecord(evAgg1, sA);

    // stream B: alpha writer overlaps agg2 (disjoint data)
    cudaStreamWaitEvent(sB, evAgg1, 0);                 // denominators
    k_alphaE<<<(EF/2 + 255) / 256, 256, 0, sB>>>(ei, ea, out);
    cudaEventRecord(evAlpha, sB);

    k_agg2  <<<gridA2, 256, 0, sA>>>(b2, Wa, ba);
    k_headF <<<(ns + 256) / 256, 256, 0, sA>>>(cash, sidx, Wc, bc, ns, out);
    cudaEventRecord(evEnd, sA);

    // join both streams back into the harness stream
    cudaStreamWaitEvent(0, evEnd, 0);
    cudaStreamWaitEvent(0, evAlpha, 0);
}